// round 4
// baseline (speedup 1.0000x reference)
#include <cuda_runtime.h>
#include <math.h>

#define TOK    8192
#define DMODEL 512
#define SQ     2048
#define NHEADS 8
#define HDIM   64
#define WIN    5

// ---------------------------------------------------------------------------
// Device scratch
// ---------------------------------------------------------------------------
__device__ float g_h1[(size_t)TOK * 1024];
__device__ float g_xm[(size_t)TOK * DMODEL];
__device__ float g_q [(size_t)TOK * DMODEL];
__device__ float g_k [(size_t)TOK * DMODEL];
__device__ float g_v [(size_t)TOK * DMODEL];
__device__ float g_o [(size_t)TOK * DMODEL];

// ---------------------------------------------------------------------------
// tf32 helpers
// ---------------------------------------------------------------------------
__device__ __forceinline__ float f2tf32(float x) {
    unsigned u;
    asm("cvt.rna.tf32.f32 %0, %1;" : "=r"(u) : "f"(x));
    return __uint_as_float(u);
}

__device__ __forceinline__ void mma_tf32(
    float& d0, float& d1, float& d2, float& d3,
    unsigned a0, unsigned a1, unsigned a2, unsigned a3,
    unsigned b0, unsigned b1)
{
    asm volatile(
        "mma.sync.aligned.m16n8k8.row.col.f32.tf32.tf32.f32 "
        "{%0,%1,%2,%3},{%4,%5,%6,%7},{%8,%9},{%0,%1,%2,%3};\n"
        : "+f"(d0), "+f"(d1), "+f"(d2), "+f"(d3)
        : "r"(a0), "r"(a1), "r"(a2), "r"(a3), "r"(b0), "r"(b1));
}

// ---------------------------------------------------------------------------
// TF32 GEMM v3: C[M,N] = act(A @ B + bias)
// BM=64, BN=128, BK=16; 128 threads = 4 warps (2x2), warp tile 32x64.
// Register-staged double buffering. ~3 blocks/SM for latency hiding.
// ---------------------------------------------------------------------------
#define APAD 20
#define BPAD 136

template<int RELU>
__global__ __launch_bounds__(128) void gemm_tf32(
    const float* __restrict__ A, const float* __restrict__ B,
    const float* __restrict__ bias, float* __restrict__ C,
    int M, int N, int K)
{
    __shared__ float As[2][64][APAD];    // [buf][m][k] tf32 bits
    __shared__ float Bs[2][16][BPAD];    // [buf][k][n]

    const int tid  = threadIdx.x;
    const int warp = tid >> 5;
    const int lane = tid & 31;
    const int g    = lane >> 2;
    const int tg   = lane & 3;
    const int wm   = warp >> 1;          // 0..1
    const int wn   = warp & 1;           // 0..1
    const int m0   = blockIdx.y * 64;
    const int n0   = blockIdx.x * 128;

    const int ar = tid >> 2;             // 0..31 (A rows, +32 for t=1)
    const int ac = (tid & 3) << 2;
    const int br = tid >> 5;             // 0..3  (B rows, +4 per t)
    const int bc = (tid & 31) << 2;

    float acc[2][8][4];
#pragma unroll
    for (int mi = 0; mi < 2; mi++)
#pragma unroll
        for (int nj = 0; nj < 8; nj++)
#pragma unroll
            for (int r = 0; r < 4; r++) acc[mi][nj][r] = 0.f;

    float4 ra[2], rb[4];

#pragma unroll
    for (int t = 0; t < 2; t++)
        ra[t] = *(const float4*)(A + (size_t)(m0 + ar + t * 32) * K + ac);
#pragma unroll
    for (int t = 0; t < 4; t++)
        rb[t] = *(const float4*)(B + (size_t)(br + t * 4) * N + n0 + bc);

#pragma unroll
    for (int t = 0; t < 2; t++) {
        float4 v = ra[t];
        v.x = f2tf32(v.x); v.y = f2tf32(v.y); v.z = f2tf32(v.z); v.w = f2tf32(v.w);
        *(float4*)&As[0][ar + t * 32][ac] = v;
    }
#pragma unroll
    for (int t = 0; t < 4; t++) {
        float4 w = rb[t];
        w.x = f2tf32(w.x); w.y = f2tf32(w.y); w.z = f2tf32(w.z); w.w = f2tf32(w.w);
        *(float4*)&Bs[0][br + t * 4][bc] = w;
    }
    __syncthreads();

    const int nt = K >> 4;
    int buf = 0;

    for (int kt = 0; kt < nt; kt++) {
        const bool more = (kt + 1 < nt);
        if (more) {
            const int k0 = (kt + 1) << 4;
#pragma unroll
            for (int t = 0; t < 2; t++)
                ra[t] = *(const float4*)(A + (size_t)(m0 + ar + t * 32) * K + k0 + ac);
#pragma unroll
            for (int t = 0; t < 4; t++)
                rb[t] = *(const float4*)(B + (size_t)(k0 + br + t * 4) * N + n0 + bc);
        }

#pragma unroll
        for (int ks = 0; ks < 2; ks++) {
            const int kb = ks * 8;
            unsigned a[2][4];
#pragma unroll
            for (int mi = 0; mi < 2; mi++) {
                const int row = wm * 32 + mi * 16;
                a[mi][0] = __float_as_uint(As[buf][row + g    ][kb + tg    ]);
                a[mi][1] = __float_as_uint(As[buf][row + g + 8][kb + tg    ]);
                a[mi][2] = __float_as_uint(As[buf][row + g    ][kb + tg + 4]);
                a[mi][3] = __float_as_uint(As[buf][row + g + 8][kb + tg + 4]);
            }
            unsigned b[8][2];
#pragma unroll
            for (int nj = 0; nj < 8; nj++) {
                const int col = wn * 64 + nj * 8 + g;
                b[nj][0] = __float_as_uint(Bs[buf][kb + tg    ][col]);
                b[nj][1] = __float_as_uint(Bs[buf][kb + tg + 4][col]);
            }
#pragma unroll
            for (int mi = 0; mi < 2; mi++)
#pragma unroll
                for (int nj = 0; nj < 8; nj++)
                    mma_tf32(acc[mi][nj][0], acc[mi][nj][1],
                             acc[mi][nj][2], acc[mi][nj][3],
                             a[mi][0], a[mi][1], a[mi][2], a[mi][3],
                             b[nj][0], b[nj][1]);
        }

        if (more) {
            const int nb = buf ^ 1;
#pragma unroll
            for (int t = 0; t < 2; t++) {
                float4 v = ra[t];
                v.x = f2tf32(v.x); v.y = f2tf32(v.y); v.z = f2tf32(v.z); v.w = f2tf32(v.w);
                *(float4*)&As[nb][ar + t * 32][ac] = v;
            }
#pragma unroll
            for (int t = 0; t < 4; t++) {
                float4 w = rb[t];
                w.x = f2tf32(w.x); w.y = f2tf32(w.y); w.z = f2tf32(w.z); w.w = f2tf32(w.w);
                *(float4*)&Bs[nb][br + t * 4][bc] = w;
            }
            __syncthreads();
            buf = nb;
        }
    }

    // Epilogue
#pragma unroll
    for (int mi = 0; mi < 2; mi++) {
        const int row = m0 + wm * 32 + mi * 16 + g;
#pragma unroll
        for (int nj = 0; nj < 8; nj++) {
            const int col = n0 + wn * 64 + nj * 8 + tg * 2;
            float2 bv = *(const float2*)(bias + col);
            float2 c0, c1;
            c0.x = acc[mi][nj][0] + bv.x;
            c0.y = acc[mi][nj][1] + bv.y;
            c1.x = acc[mi][nj][2] + bv.x;
            c1.y = acc[mi][nj][3] + bv.y;
            if (RELU) {
                c0.x = fmaxf(c0.x, 0.f); c0.y = fmaxf(c0.y, 0.f);
                c1.x = fmaxf(c1.x, 0.f); c1.y = fmaxf(c1.y, 0.f);
            }
            *(float2*)(C + (size_t)row * N + col)       = c0;
            *(float2*)(C + (size_t)(row + 8) * N + col) = c1;
        }
    }
}

// ---------------------------------------------------------------------------
// TF32 MMA flash attention v3, inverse band mask.
// Block: 256 q-rows for one (b,h), 256 threads = 8 warps, warp tile 32x64.
// Q fragments fully register-resident; Q smem buffer reused for P.
// ---------------------------------------------------------------------------
#define QKP 68
#define VP  72
#define QTILE 256

__global__ __launch_bounds__(256) void attn_tf32(
    const float* __restrict__ Qg, const float* __restrict__ Kg,
    const float* __restrict__ Vg, float* __restrict__ Og)
{
    extern __shared__ float sm[];
    float* QP = sm;                       // [256][QKP]: Q staging, then P
    float* Ks = QP + QTILE * QKP;         // [64][QKP]
    float* Vs = Ks + 64 * QKP;            // [64][VP]

    const int tid  = threadIdx.x;
    const int warp = tid >> 5;
    const int lane = tid & 31;
    const int g    = lane >> 2;
    const int tg   = lane & 3;
    const int bh   = blockIdx.y;
    const int b    = bh >> 3;
    const int h    = bh & 7;
    const int q0   = blockIdx.x * QTILE;
    const int wrow = warp * 32;

    const float* Qb = Qg + (size_t)b * SQ * DMODEL + h * HDIM;
    const float* Kb = Kg + (size_t)b * SQ * DMODEL + h * HDIM;
    const float* Vb = Vg + (size_t)b * SQ * DMODEL + h * HDIM;

    // Stage Q tile (256x64), pre-scaled by 1/8, tf32
#pragma unroll
    for (int t = 0; t < 16; t++) {
        int idx = tid + t * 256;
        int r   = idx >> 4;
        int c4  = (idx & 15) << 2;
        float4 v = *(const float4*)(Qb + (size_t)(q0 + r) * DMODEL + c4);
        v.x = f2tf32(v.x * 0.125f); v.y = f2tf32(v.y * 0.125f);
        v.z = f2tf32(v.z * 0.125f); v.w = f2tf32(v.w * 0.125f);
        *(float4*)&QP[r * QKP + c4] = v;
    }
    __syncwarp();  // warp reads only its own 32 rows, which it staged itself? No —
                   // staging is block-strided. Need full barrier before frag loads.
    __syncthreads();

    // Q fragments fully in registers: 8 k-steps x 2 m-tiles x 4 regs
    unsigned qf[8][2][4];
#pragma unroll
    for (int ks = 0; ks < 8; ks++) {
        const int kb = ks * 8;
#pragma unroll
        for (int mi = 0; mi < 2; mi++) {
            const int row = wrow + mi * 16;
            qf[ks][mi][0] = __float_as_uint(QP[(row + g    ) * QKP + kb + tg    ]);
            qf[ks][mi][1] = __float_as_uint(QP[(row + g + 8) * QKP + kb + tg    ]);
            qf[ks][mi][2] = __float_as_uint(QP[(row + g    ) * QKP + kb + tg + 4]);
            qf[ks][mi][3] = __float_as_uint(QP[(row + g + 8) * QKP + kb + tg + 4]);
        }
    }

    float oacc[2][8][4];
#pragma unroll
    for (int mi = 0; mi < 2; mi++)
#pragma unroll
        for (int nj = 0; nj < 8; nj++)
#pragma unroll
            for (int r = 0; r < 4; r++) oacc[mi][nj][r] = 0.f;
    float mrow[2][2], lrow[2][2];
#pragma unroll
    for (int mi = 0; mi < 2; mi++) {
        mrow[mi][0] = mrow[mi][1] = -1e30f;
        lrow[mi][0] = lrow[mi][1] = 0.f;
    }

    for (int kt = 0; kt < SQ / 64; kt++) {
        const int k0 = kt * 64;
        __syncthreads();   // prev iteration's Ks/Vs consumers done (also orders qf reads)

        // Load K and V tiles (64x64 each): 1024 float4 each / 256 threads
#pragma unroll
        for (int t = 0; t < 4; t++) {
            int idx = tid + t * 256;
            int r   = idx >> 4;
            int c4  = (idx & 15) << 2;
            float4 kv = *(const float4*)(Kb + (size_t)(k0 + r) * DMODEL + c4);
            kv.x = f2tf32(kv.x); kv.y = f2tf32(kv.y);
            kv.z = f2tf32(kv.z); kv.w = f2tf32(kv.w);
            *(float4*)&Ks[r * QKP + c4] = kv;
            float4 vv = *(const float4*)(Vb + (size_t)(k0 + r) * DMODEL + c4);
            vv.x = f2tf32(vv.x); vv.y = f2tf32(vv.y);
            vv.z = f2tf32(vv.z); vv.w = f2tf32(vv.w);
            *(float4*)&Vs[r * VP + c4] = vv;
        }
        __syncthreads();

        // S = Q @ K^T (32x64 per warp)
        float sfrag[2][8][4];
#pragma unroll
        for (int mi = 0; mi < 2; mi++)
#pragma unroll
            for (int nj = 0; nj < 8; nj++)
#pragma unroll
                for (int r = 0; r < 4; r++) sfrag[mi][nj][r] = 0.f;

#pragma unroll
        for (int ks = 0; ks < 8; ks++) {
            const int kb = ks * 8;
            unsigned bq[8][2];
#pragma unroll
            for (int nj = 0; nj < 8; nj++) {
                const int key = nj * 8 + g;
                bq[nj][0] = __float_as_uint(Ks[key * QKP + kb + tg    ]);
                bq[nj][1] = __float_as_uint(Ks[key * QKP + kb + tg + 4]);
            }
#pragma unroll
            for (int mi = 0; mi < 2; mi++)
#pragma unroll
                for (int nj = 0; nj < 8; nj++)
                    mma_tf32(sfrag[mi][nj][0], sfrag[mi][nj][1],
                             sfrag[mi][nj][2], sfrag[mi][nj][3],
                             qf[ks][mi][0], qf[ks][mi][1],
                             qf[ks][mi][2], qf[ks][mi][3],
                             bq[nj][0], bq[nj][1]);
        }

        // Inverse-band mask (Q already scaled)
        const bool need_mask = (k0 <= q0 + QTILE - 1 + WIN) && (k0 + 63 >= q0 - WIN);
        if (need_mask) {
#pragma unroll
            for (int mi = 0; mi < 2; mi++) {
                const int qr0 = q0 + wrow + mi * 16 + g;
                const int qr1 = qr0 + 8;
#pragma unroll
                for (int nj = 0; nj < 8; nj++) {
                    const int kc0 = k0 + nj * 8 + tg * 2;
                    if ((unsigned)(qr0 - kc0     + WIN) <= 2 * WIN) sfrag[mi][nj][0] = -1e9f;
                    if ((unsigned)(qr0 - kc0 - 1 + WIN) <= 2 * WIN) sfrag[mi][nj][1] = -1e9f;
                    if ((unsigned)(qr1 - kc0     + WIN) <= 2 * WIN) sfrag[mi][nj][2] = -1e9f;
                    if ((unsigned)(qr1 - kc0 - 1 + WIN) <= 2 * WIN) sfrag[mi][nj][3] = -1e9f;
                }
            }
        }

        // Online softmax
#pragma unroll
        for (int mi = 0; mi < 2; mi++) {
            float tmax0 = -1e30f, tmax1 = -1e30f;
#pragma unroll
            for (int nj = 0; nj < 8; nj++) {
                tmax0 = fmaxf(tmax0, fmaxf(sfrag[mi][nj][0], sfrag[mi][nj][1]));
                tmax1 = fmaxf(tmax1, fmaxf(sfrag[mi][nj][2], sfrag[mi][nj][3]));
            }
#pragma unroll
            for (int off = 1; off <= 2; off <<= 1) {
                tmax0 = fmaxf(tmax0, __shfl_xor_sync(0xffffffffu, tmax0, off));
                tmax1 = fmaxf(tmax1, __shfl_xor_sync(0xffffffffu, tmax1, off));
            }
            const float mnew0 = fmaxf(mrow[mi][0], tmax0);
            const float mnew1 = fmaxf(mrow[mi][1], tmax1);
            const float alpha0 = __expf(mrow[mi][0] - mnew0);
            const float alpha1 = __expf(mrow[mi][1] - mnew1);

            float rs0 = 0.f, rs1 = 0.f;
            const int prow0 = (wrow + mi * 16 + g) * QKP;
            const int prow1 = (wrow + mi * 16 + g + 8) * QKP;
#pragma unroll
            for (int nj = 0; nj < 8; nj++) {
                const float p0 = __expf(sfrag[mi][nj][0] - mnew0);
                const float p1 = __expf(sfrag[mi][nj][1] - mnew0);
                const float p2 = __expf(sfrag[mi][nj][2] - mnew1);
                const float p3 = __expf(sfrag[mi][nj][3] - mnew1);
                rs0 += p0 + p1;
                rs1 += p2 + p3;
                const int kc = nj * 8 + tg * 2;
                QP[prow0 + kc    ] = f2tf32(p0);
                QP[prow0 + kc + 1] = f2tf32(p1);
                QP[prow1 + kc    ] = f2tf32(p2);
                QP[prow1 + kc + 1] = f2tf32(p3);
            }
#pragma unroll
            for (int off = 1; off <= 2; off <<= 1) {
                rs0 += __shfl_xor_sync(0xffffffffu, rs0, off);
                rs1 += __shfl_xor_sync(0xffffffffu, rs1, off);
            }
            lrow[mi][0] = lrow[mi][0] * alpha0 + rs0;
            lrow[mi][1] = lrow[mi][1] * alpha1 + rs1;
            mrow[mi][0] = mnew0;
            mrow[mi][1] = mnew1;
#pragma unroll
            for (int nj = 0; nj < 8; nj++) {
                oacc[mi][nj][0] *= alpha0; oacc[mi][nj][1] *= alpha0;
                oacc[mi][nj][2] *= alpha1; oacc[mi][nj][3] *= alpha1;
            }
        }
        __syncwarp();   // P rows are warp-private; warp-level sync suffices

        // O += P @ V
#pragma unroll
        for (int ks = 0; ks < 8; ks++) {
            const int kb = ks * 8;
            unsigned ap[2][4];
#pragma unroll
            for (int mi = 0; mi < 2; mi++) {
                const int row = wrow + mi * 16;
                ap[mi][0] = __float_as_uint(QP[(row + g    ) * QKP + kb + tg    ]);
                ap[mi][1] = __float_as_uint(QP[(row + g + 8) * QKP + kb + tg    ]);
                ap[mi][2] = __float_as_uint(QP[(row + g    ) * QKP + kb + tg + 4]);
                ap[mi][3] = __float_as_uint(QP[(row + g + 8) * QKP + kb + tg + 4]);
            }
            unsigned bv[8][2];
#pragma unroll
            for (int nj = 0; nj < 8; nj++) {
                const int col = nj * 8 + g;
                bv[nj][0] = __float_as_uint(Vs[(kb + tg    ) * VP + col]);
                bv[nj][1] = __float_as_uint(Vs[(kb + tg + 4) * VP + col]);
            }
#pragma unroll
            for (int mi = 0; mi < 2; mi++)
#pragma unroll
                for (int nj = 0; nj < 8; nj++)
                    mma_tf32(oacc[mi][nj][0], oacc[mi][nj][1],
                             oacc[mi][nj][2], oacc[mi][nj][3],
                             ap[mi][0], ap[mi][1], ap[mi][2], ap[mi][3],
                             bv[nj][0], bv[nj][1]);
        }
    }

    // Finalize and store
    float* Ob = Og + (size_t)b * SQ * DMODEL + h * HDIM;
#pragma unroll
    for (int mi = 0; mi < 2; mi++) {
        const float inv0 = 1.0f / lrow[mi][0];
        const float inv1 = 1.0f / lrow[mi][1];
        const int row0 = q0 + wrow + mi * 16 + g;
#pragma unroll
        for (int nj = 0; nj < 8; nj++) {
            const int col = nj * 8 + tg * 2;
            float2 c0, c1;
            c0.x = oacc[mi][nj][0] * inv0; c0.y = oacc[mi][nj][1] * inv0;
            c1.x = oacc[mi][nj][2] * inv1; c1.y = oacc[mi][nj][3] * inv1;
            *(float2*)(Ob + (size_t)row0 * DMODEL + col)       = c0;
            *(float2*)(Ob + (size_t)(row0 + 8) * DMODEL + col) = c1;
        }
    }
}

// ---------------------------------------------------------------------------
// Launch
// ---------------------------------------------------------------------------
extern "C" void kernel_launch(void* const* d_in, const int* in_sizes, int n_in,
                              void* d_out, int out_size)
{
    (void)in_sizes; (void)n_in; (void)out_size;

    const float* x  = (const float*)d_in[0];
    const float* W1 = (const float*)d_in[1];
    const float* b1 = (const float*)d_in[2];
    const float* W2 = (const float*)d_in[3];
    const float* b2 = (const float*)d_in[4];
    const float* Wq = (const float*)d_in[5];
    const float* bq = (const float*)d_in[6];
    const float* Wk = (const float*)d_in[7];
    const float* bk = (const float*)d_in[8];
    const float* Wv = (const float*)d_in[9];
    const float* bv = (const float*)d_in[10];
    const float* Wo = (const float*)d_in[11];
    const float* bo = (const float*)d_in[12];
    float* out = (float*)d_out;

    float *h1, *xm, *q, *k, *v, *o;
    cudaGetSymbolAddress((void**)&h1, g_h1);
    cudaGetSymbolAddress((void**)&xm, g_xm);
    cudaGetSymbolAddress((void**)&q,  g_q);
    cudaGetSymbolAddress((void**)&k,  g_k);
    cudaGetSymbolAddress((void**)&v,  g_v);
    cudaGetSymbolAddress((void**)&o,  g_o);

    const int attn_smem = (QTILE * QKP + 64 * QKP + 64 * VP) * (int)sizeof(float); // 105472
    cudaFuncSetAttribute(attn_tf32, cudaFuncAttributeMaxDynamicSharedMemorySize,
                         attn_smem);

    dim3 blk(128);

    gemm_tf32<1><<<dim3(1024 / 128, TOK / 64), blk>>>(x,  W1, b1, h1,  TOK, 1024,  DMODEL);
    gemm_tf32<0><<<dim3(DMODEL / 128, TOK / 64), blk>>>(h1, W2, b2, xm, TOK, DMODEL, 1024);
    gemm_tf32<0><<<dim3(DMODEL / 128, TOK / 64), blk>>>(xm, Wq, bq, q,  TOK, DMODEL, DMODEL);
    gemm_tf32<0><<<dim3(DMODEL / 128, TOK / 64), blk>>>(xm, Wk, bk, k,  TOK, DMODEL, DMODEL);
    gemm_tf32<0><<<dim3(DMODEL / 128, TOK / 64), blk>>>(xm, Wv, bv, v,  TOK, DMODEL, DMODEL);
    attn_tf32<<<dim3(SQ / QTILE, 4 * NHEADS), dim3(256), attn_smem>>>(q, k, v, o);
    gemm_tf32<0><<<dim3(DMODEL / 128, TOK / 64), blk>>>(o,  Wo, bo, out, TOK, DMODEL, DMODEL);
}

// round 7
// speedup vs baseline: 1.0724x; 1.0724x over previous
#include <cuda_runtime.h>
#include <cstdint>
#include <math.h>

#define TOK    8192
#define DMODEL 512
#define SQ     2048
#define NHEADS 8
#define HDIM   64
#define WIN    5

// ---------------------------------------------------------------------------
// Device scratch (all intermediates stored tf32-rounded)
// ---------------------------------------------------------------------------
__device__ float g_xr[(size_t)TOK * DMODEL];   // tf32-rounded x
__device__ float g_h1[(size_t)TOK * 1024];
__device__ float g_xm[(size_t)TOK * DMODEL];
__device__ float g_q [(size_t)TOK * DMODEL];
__device__ float g_k [(size_t)TOK * DMODEL];
__device__ float g_v [(size_t)TOK * DMODEL];
__device__ float g_o [(size_t)TOK * DMODEL];
// transposed (tf32-rounded) weights, [N][K] layout
__device__ float g_w1t[(size_t)1024 * 512];
__device__ float g_w2t[(size_t)512 * 1024];
__device__ float g_wqt[(size_t)512 * 512];
__device__ float g_wkt[(size_t)512 * 512];
__device__ float g_wvt[(size_t)512 * 512];
__device__ float g_wot[(size_t)512 * 512];

// ---------------------------------------------------------------------------
// helpers
// ---------------------------------------------------------------------------
__device__ __forceinline__ float f2tf32(float x) {
    unsigned u;
    asm("cvt.rna.tf32.f32 %0, %1;" : "=r"(u) : "f"(x));
    return __uint_as_float(u);
}

__device__ __forceinline__ uint32_t smem_u32(const void* p) {
    uint32_t a;
    asm("{ .reg .u64 t; cvta.to.shared.u64 t, %1; cvt.u32.u64 %0, t; }"
        : "=r"(a) : "l"(p));
    return a;
}

#define CP_ASYNC16(dst_u32, src_ptr) \
    asm volatile("cp.async.cg.shared.global [%0], [%1], 16;" \
                 :: "r"(dst_u32), "l"(src_ptr) : "memory")
#define CP_COMMIT() asm volatile("cp.async.commit_group;" ::: "memory")
#define CP_WAIT(n)  asm volatile("cp.async.wait_group %0;" :: "n"(n) : "memory")

__device__ __forceinline__ void mma_tf32(
    float& d0, float& d1, float& d2, float& d3,
    unsigned a0, unsigned a1, unsigned a2, unsigned a3,
    unsigned b0, unsigned b1)
{
    asm volatile(
        "mma.sync.aligned.m16n8k8.row.col.f32.tf32.tf32.f32 "
        "{%0,%1,%2,%3},{%4,%5,%6,%7},{%8,%9},{%0,%1,%2,%3};\n"
        : "+f"(d0), "+f"(d1), "+f"(d2), "+f"(d3)
        : "r"(a0), "r"(a1), "r"(a2), "r"(a3), "r"(b0), "r"(b1));
}

// ---------------------------------------------------------------------------
// Elementwise tf32 pre-round: dst[i] = tf32(src[i])
// ---------------------------------------------------------------------------
__global__ __launch_bounds__(256) void preround_tf32(
    const float* __restrict__ src, float* __restrict__ dst)
{
    const size_t i = (size_t)blockIdx.x * 256 + threadIdx.x;
    float4 v = ((const float4*)src)[i];
    v.x = f2tf32(v.x); v.y = f2tf32(v.y);
    v.z = f2tf32(v.z); v.w = f2tf32(v.w);
    ((float4*)dst)[i] = v;
}

// ---------------------------------------------------------------------------
// Weight transpose + tf32 round: dst[n][k] = tf32(src[k][n])
// ---------------------------------------------------------------------------
__global__ __launch_bounds__(256) void transpose_tf32(
    const float* __restrict__ src, float* __restrict__ dst, int K, int N)
{
    __shared__ float t[32][33];
    const int k0 = blockIdx.y * 32;
    const int n0 = blockIdx.x * 32;
    const int tx = threadIdx.x, ty = threadIdx.y;
#pragma unroll
    for (int i = 0; i < 4; i++)
        t[ty + i * 8][tx] = src[(size_t)(k0 + ty + i * 8) * N + n0 + tx];
    __syncthreads();
#pragma unroll
    for (int i = 0; i < 4; i++)
        dst[(size_t)(n0 + ty + i * 8) * K + k0 + tx] = f2tf32(t[tx][ty + i * 8]);
}

// ---------------------------------------------------------------------------
// TF32 GEMM v4: C[M,N] = act(A[M,K] @ Bt[N,K]^T + bias)
// BM=128, BN=128, BK=16; 128 threads = 4 warps (2x2), warp tile 64x64.
// cp.async double buffering; A and Bt already tf32-rounded (raw copies).
// RELU: apply relu. RO: round output to tf32 (for intermediates).
// ---------------------------------------------------------------------------
#define APAD 20
#define BPAD 136

template<int RELU, int RO>
__global__ __launch_bounds__(128) void gemm_tf32(
    const float* __restrict__ A, const float* __restrict__ Bt,
    const float* __restrict__ bias, float* __restrict__ C,
    int M, int N, int K)
{
    __shared__ float As[2][128][APAD];   // [buf][m][k]
    __shared__ float Bs[2][16][BPAD];    // [buf][k][n]  (n = Bt row)

    const int tid  = threadIdx.x;
    const int warp = tid >> 5;
    const int lane = tid & 31;
    const int g    = lane >> 2;
    const int tg   = lane & 3;
    const int wm   = warp >> 1;
    const int wn   = warp & 1;
    const int m0   = blockIdx.y * 128;
    const int n0   = blockIdx.x * 128;

    // load coords: A tile 128x16 (512 float4, 4/thread), B tile 16x128 from
    // Bt rows n0..n0+127 cols k0..k0+15 -> stored transposed as Bs[k][n]?
    // NOTE: Bt is [N][K]; we need Bs[k][n]. cp.async can't transpose, so load
    // Bt rows directly into Bs as [n][k]? mma needs b-frag by (key col n, k).
    // Instead store Bs as [n 128][k 16]: BsT[128][BPAD2]. Simpler: keep
    // fragment reads b[nj] = Bs_n[col][kb+tg]. Use layout Bs[n][k] with pad.
    const int ar = tid >> 2;             // 0..31 (+32*t)
    const int ac = (tid & 3) << 2;
    const int br = tid >> 2;             // 0..31 (+32*t), n-row of Bt
    const int bc = (tid & 3) << 2;       // 0..12, k-col

    float acc[4][8][4];
#pragma unroll
    for (int mi = 0; mi < 4; mi++)
#pragma unroll
        for (int nj = 0; nj < 8; nj++)
#pragma unroll
            for (int r = 0; r < 4; r++) acc[mi][nj][r] = 0.f;

    const uint32_t aBase = smem_u32(&As[0][0][0]);
    const uint32_t bBase = smem_u32(&Bs[0][0][0]);

    // Bs reinterpreted as [buf][128][APAD] (n-major, k minor) — same footprint?
    // [16][136] = 2176 floats vs [128][20] = 2560. Use the A-style layout for B:
    // we alias Bs memory as Bn[buf][128][17]: 128*17=2176 = exactly [16][136]. 
    // Bn stride 17 floats = 68B: not 16B multiple -> cp.async dst must be 16B
    // aligned; 68B stride breaks alignment for odd rows. Use stride 20 requires
    // 2560 > 2176. Redefine Bs properly below instead.

    // --- actual B layout: Bn[buf][128][BNP], BNP=20 (16B-aligned stride 80B) ---
    // implemented via separate shared array:
    __shared__ float Bn[2][128][20];
    const uint32_t bnBase = smem_u32(&Bn[0][0][0]);
    (void)bBase; (void)Bs;

    const int nt = K >> 4;

    // prologue: issue tile 0
    {
#pragma unroll
        for (int t = 0; t < 4; t++) {
            const int r = ar + t * 32;
            CP_ASYNC16(aBase + (uint32_t)((r * APAD + ac) * 4),
                       A + (size_t)(m0 + r) * K + ac);
            CP_ASYNC16(bnBase + (uint32_t)((r * 20 + bc) * 4),
                       Bt + (size_t)(n0 + r) * K + bc);
        }
        CP_COMMIT();
    }

    int buf = 0;
    for (int kt = 0; kt < nt; kt++) {
        if (kt + 1 < nt) {
            const int k0 = (kt + 1) << 4;
            const int nb = buf ^ 1;
            const uint32_t aOff = aBase + (uint32_t)(nb * 128 * APAD * 4);
            const uint32_t bOff = bnBase + (uint32_t)(nb * 128 * 20 * 4);
#pragma unroll
            for (int t = 0; t < 4; t++) {
                const int r = ar + t * 32;
                CP_ASYNC16(aOff + (uint32_t)((r * APAD + ac) * 4),
                           A + (size_t)(m0 + r) * K + k0 + ac);
                CP_ASYNC16(bOff + (uint32_t)((r * 20 + bc) * 4),
                           Bt + (size_t)(n0 + r) * K + k0 + bc);
            }
            CP_COMMIT();
            CP_WAIT(1);
        } else {
            CP_WAIT(0);
        }
        __syncthreads();

#pragma unroll
        for (int ks = 0; ks < 2; ks++) {
            const int kb = ks * 8;
            unsigned a[4][4];
#pragma unroll
            for (int mi = 0; mi < 4; mi++) {
                const int row = wm * 64 + mi * 16;
                a[mi][0] = __float_as_uint(As[buf][row + g    ][kb + tg    ]);
                a[mi][1] = __float_as_uint(As[buf][row + g + 8][kb + tg    ]);
                a[mi][2] = __float_as_uint(As[buf][row + g    ][kb + tg + 4]);
                a[mi][3] = __float_as_uint(As[buf][row + g + 8][kb + tg + 4]);
            }
            unsigned b[8][2];
#pragma unroll
            for (int nj = 0; nj < 8; nj++) {
                const int col = wn * 64 + nj * 8 + g;
                b[nj][0] = __float_as_uint(Bn[buf][col][kb + tg    ]);
                b[nj][1] = __float_as_uint(Bn[buf][col][kb + tg + 4]);
            }
#pragma unroll
            for (int mi = 0; mi < 4; mi++)
#pragma unroll
                for (int nj = 0; nj < 8; nj++)
                    mma_tf32(acc[mi][nj][0], acc[mi][nj][1],
                             acc[mi][nj][2], acc[mi][nj][3],
                             a[mi][0], a[mi][1], a[mi][2], a[mi][3],
                             b[nj][0], b[nj][1]);
        }
        __syncthreads();
        buf ^= 1;
    }

    // Epilogue
#pragma unroll
    for (int mi = 0; mi < 4; mi++) {
        const int row = m0 + wm * 64 + mi * 16 + g;
#pragma unroll
        for (int nj = 0; nj < 8; nj++) {
            const int col = n0 + wn * 64 + nj * 8 + tg * 2;
            float2 bv = *(const float2*)(bias + col);
            float2 c0, c1;
            c0.x = acc[mi][nj][0] + bv.x;
            c0.y = acc[mi][nj][1] + bv.y;
            c1.x = acc[mi][nj][2] + bv.x;
            c1.y = acc[mi][nj][3] + bv.y;
            if (RELU) {
                c0.x = fmaxf(c0.x, 0.f); c0.y = fmaxf(c0.y, 0.f);
                c1.x = fmaxf(c1.x, 0.f); c1.y = fmaxf(c1.y, 0.f);
            }
            if (RO) {
                c0.x = f2tf32(c0.x); c0.y = f2tf32(c0.y);
                c1.x = f2tf32(c1.x); c1.y = f2tf32(c1.y);
            }
            *(float2*)(C + (size_t)row * N + col)       = c0;
            *(float2*)(C + (size_t)(row + 8) * N + col) = c1;
        }
    }
}

// ---------------------------------------------------------------------------
// TF32 MMA flash attention (QTILE=256), inverse band mask.
// Inputs q,k,v are already tf32-rounded -> no cvt on load paths.
// Output o written tf32-rounded (consumed by final GEMM).
// ---------------------------------------------------------------------------
#define QKP 68
#define VP  72
#define QTILE 256

__global__ __launch_bounds__(256) void attn_tf32(
    const float* __restrict__ Qg, const float* __restrict__ Kg,
    const float* __restrict__ Vg, float* __restrict__ Og)
{
    extern __shared__ float sm[];
    float* QP = sm;                       // [256][QKP]: Q staging, then P
    float* Ks = QP + QTILE * QKP;         // [64][QKP]
    float* Vs = Ks + 64 * QKP;            // [64][VP]

    const int tid  = threadIdx.x;
    const int warp = tid >> 5;
    const int lane = tid & 31;
    const int g    = lane >> 2;
    const int tg   = lane & 3;
    const int bh   = blockIdx.y;
    const int b    = bh >> 3;
    const int h    = bh & 7;
    const int q0   = blockIdx.x * QTILE;
    const int wrow = warp * 32;

    const float* Qb = Qg + (size_t)b * SQ * DMODEL + h * HDIM;
    const float* Kb = Kg + (size_t)b * SQ * DMODEL + h * HDIM;
    const float* Vb = Vg + (size_t)b * SQ * DMODEL + h * HDIM;

    // Stage Q (pre-scaled by 1/8: exact on tf32 values)
#pragma unroll
    for (int t = 0; t < 16; t++) {
        int idx = tid + t * 256;
        int r   = idx >> 4;
        int c4  = (idx & 15) << 2;
        float4 v = *(const float4*)(Qb + (size_t)(q0 + r) * DMODEL + c4);
        v.x *= 0.125f; v.y *= 0.125f; v.z *= 0.125f; v.w *= 0.125f;
        *(float4*)&QP[r * QKP + c4] = v;
    }
    __syncthreads();

    unsigned qf[8][2][4];
#pragma unroll
    for (int ks = 0; ks < 8; ks++) {
        const int kb = ks * 8;
#pragma unroll
        for (int mi = 0; mi < 2; mi++) {
            const int row = wrow + mi * 16;
            qf[ks][mi][0] = __float_as_uint(QP[(row + g    ) * QKP + kb + tg    ]);
            qf[ks][mi][1] = __float_as_uint(QP[(row + g + 8) * QKP + kb + tg    ]);
            qf[ks][mi][2] = __float_as_uint(QP[(row + g    ) * QKP + kb + tg + 4]);
            qf[ks][mi][3] = __float_as_uint(QP[(row + g + 8) * QKP + kb + tg + 4]);
        }
    }

    float oacc[2][8][4];
#pragma unroll
    for (int mi = 0; mi < 2; mi++)
#pragma unroll
        for (int nj = 0; nj < 8; nj++)
#pragma unroll
            for (int r = 0; r < 4; r++) oacc[mi][nj][r] = 0.f;
    float mrow[2][2], lrow[2][2];
#pragma unroll
    for (int mi = 0; mi < 2; mi++) {
        mrow[mi][0] = mrow[mi][1] = -1e30f;
        lrow[mi][0] = lrow[mi][1] = 0.f;
    }

    for (int kt = 0; kt < SQ / 64; kt++) {
        const int k0 = kt * 64;
        __syncthreads();

        // K/V tiles: raw copies (already tf32)
#pragma unroll
        for (int t = 0; t < 4; t++) {
            int idx = tid + t * 256;
            int r   = idx >> 4;
            int c4  = (idx & 15) << 2;
            *(float4*)&Ks[r * QKP + c4] =
                *(const float4*)(Kb + (size_t)(k0 + r) * DMODEL + c4);
            *(float4*)&Vs[r * VP + c4] =
                *(const float4*)(Vb + (size_t)(k0 + r) * DMODEL + c4);
        }
        __syncthreads();

        float sfrag[2][8][4];
#pragma unroll
        for (int mi = 0; mi < 2; mi++)
#pragma unroll
            for (int nj = 0; nj < 8; nj++)
#pragma unroll
                for (int r = 0; r < 4; r++) sfrag[mi][nj][r] = 0.f;

#pragma unroll
        for (int ks = 0; ks < 8; ks++) {
            const int kb = ks * 8;
            unsigned bq[8][2];
#pragma unroll
            for (int nj = 0; nj < 8; nj++) {
                const int key = nj * 8 + g;
                bq[nj][0] = __float_as_uint(Ks[key * QKP + kb + tg    ]);
                bq[nj][1] = __float_as_uint(Ks[key * QKP + kb + tg + 4]);
            }
#pragma unroll
            for (int mi = 0; mi < 2; mi++)
#pragma unroll
                for (int nj = 0; nj < 8; nj++)
                    mma_tf32(sfrag[mi][nj][0], sfrag[mi][nj][1],
                             sfrag[mi][nj][2], sfrag[mi][nj][3],
                             qf[ks][mi][0], qf[ks][mi][1],
                             qf[ks][mi][2], qf[ks][mi][3],
                             bq[nj][0], bq[nj][1]);
        }

        const bool need_mask = (k0 <= q0 + QTILE - 1 + WIN) && (k0 + 63 >= q0 - WIN);
        if (need_mask) {
#pragma unroll
            for (int mi = 0; mi < 2; mi++) {
                const int qr0 = q0 + wrow + mi * 16 + g;
                const int qr1 = qr0 + 8;
#pragma unroll
                for (int nj = 0; nj < 8; nj++) {
                    const int kc0 = k0 + nj * 8 + tg * 2;
                    if ((unsigned)(qr0 - kc0     + WIN) <= 2 * WIN) sfrag[mi][nj][0] = -1e9f;
                    if ((unsigned)(qr0 - kc0 - 1 + WIN) <= 2 * WIN) sfrag[mi][nj][1] = -1e9f;
                    if ((unsigned)(qr1 - kc0     + WIN) <= 2 * WIN) sfrag[mi][nj][2] = -1e9f;
                    if ((unsigned)(qr1 - kc0 - 1 + WIN) <= 2 * WIN) sfrag[mi][nj][3] = -1e9f;
                }
            }
        }

#pragma unroll
        for (int mi = 0; mi < 2; mi++) {
            float tmax0 = -1e30f, tmax1 = -1e30f;
#pragma unroll
            for (int nj = 0; nj < 8; nj++) {
                tmax0 = fmaxf(tmax0, fmaxf(sfrag[mi][nj][0], sfrag[mi][nj][1]));
                tmax1 = fmaxf(tmax1, fmaxf(sfrag[mi][nj][2], sfrag[mi][nj][3]));
            }
#pragma unroll
            for (int off = 1; off <= 2; off <<= 1) {
                tmax0 = fmaxf(tmax0, __shfl_xor_sync(0xffffffffu, tmax0, off));
                tmax1 = fmaxf(tmax1, __shfl_xor_sync(0xffffffffu, tmax1, off));
            }
            const float mnew0 = fmaxf(mrow[mi][0], tmax0);
            const float mnew1 = fmaxf(mrow[mi][1], tmax1);
            const float alpha0 = __expf(mrow[mi][0] - mnew0);
            const float alpha1 = __expf(mrow[mi][1] - mnew1);

            float rs0 = 0.f, rs1 = 0.f;
            const int prow0 = (wrow + mi * 16 + g) * QKP;
            const int prow1 = (wrow + mi * 16 + g + 8) * QKP;
#pragma unroll
            for (int nj = 0; nj < 8; nj++) {
                const float p0 = __expf(sfrag[mi][nj][0] - mnew0);
                const float p1 = __expf(sfrag[mi][nj][1] - mnew0);
                const float p2 = __expf(sfrag[mi][nj][2] - mnew1);
                const float p3 = __expf(sfrag[mi][nj][3] - mnew1);
                rs0 += p0 + p1;
                rs1 += p2 + p3;
                const int kc = nj * 8 + tg * 2;
                QP[prow0 + kc    ] = f2tf32(p0);
                QP[prow0 + kc + 1] = f2tf32(p1);
                QP[prow1 + kc    ] = f2tf32(p2);
                QP[prow1 + kc + 1] = f2tf32(p3);
            }
#pragma unroll
            for (int off = 1; off <= 2; off <<= 1) {
                rs0 += __shfl_xor_sync(0xffffffffu, rs0, off);
                rs1 += __shfl_xor_sync(0xffffffffu, rs1, off);
            }
            lrow[mi][0] = lrow[mi][0] * alpha0 + rs0;
            lrow[mi][1] = lrow[mi][1] * alpha1 + rs1;
            mrow[mi][0] = mnew0;
            mrow[mi][1] = mnew1;
#pragma unroll
            for (int nj = 0; nj < 8; nj++) {
                oacc[mi][nj][0] *= alpha0; oacc[mi][nj][1] *= alpha0;
                oacc[mi][nj][2] *= alpha1; oacc[mi][nj][3] *= alpha1;
            }
        }
        __syncwarp();

#pragma unroll
        for (int ks = 0; ks < 8; ks++) {
            const int kb = ks * 8;
            unsigned ap[2][4];
#pragma unroll
            for (int mi = 0; mi < 2; mi++) {
                const int row = wrow + mi * 16;
                ap[mi][0] = __float_as_uint(QP[(row + g    ) * QKP + kb + tg    ]);
                ap[mi][1] = __float_as_uint(QP[(row + g + 8) * QKP + kb + tg    ]);
                ap[mi][2] = __float_as_uint(QP[(row + g    ) * QKP + kb + tg + 4]);
                ap[mi][3] = __float_as_uint(QP[(row + g + 8) * QKP + kb + tg + 4]);
            }
            unsigned bv[8][2];
#pragma unroll
            for (int nj = 0; nj < 8; nj++) {
                const int col = nj * 8 + g;
                bv[nj][0] = __float_as_uint(Vs[(kb + tg    ) * VP + col]);
                bv[nj][1] = __float_as_uint(Vs[(kb + tg + 4) * VP + col]);
            }
#pragma unroll
            for (int mi = 0; mi < 2; mi++)
#pragma unroll
                for (int nj = 0; nj < 8; nj++)
                    mma_tf32(oacc[mi][nj][0], oacc[mi][nj][1],
                             oacc[mi][nj][2], oacc[mi][nj][3],
                             ap[mi][0], ap[mi][1], ap[mi][2], ap[mi][3],
                             bv[nj][0], bv[nj][1]);
        }
    }

    // Finalize: write tf32-rounded (consumed as GEMM A operand)
    float* Ob = Og + (size_t)b * SQ * DMODEL + h * HDIM;
#pragma unroll
    for (int mi = 0; mi < 2; mi++) {
        const float inv0 = 1.0f / lrow[mi][0];
        const float inv1 = 1.0f / lrow[mi][1];
        const int row0 = q0 + wrow + mi * 16 + g;
#pragma unroll
        for (int nj = 0; nj < 8; nj++) {
            const int col = nj * 8 + tg * 2;
            float2 c0, c1;
            c0.x = f2tf32(oacc[mi][nj][0] * inv0);
            c0.y = f2tf32(oacc[mi][nj][1] * inv0);
            c1.x = f2tf32(oacc[mi][nj][2] * inv1);
            c1.y = f2tf32(oacc[mi][nj][3] * inv1);
            *(float2*)(Ob + (size_t)row0 * DMODEL + col)       = c0;
            *(float2*)(Ob + (size_t)(row0 + 8) * DMODEL + col) = c1;
        }
    }
}

// ---------------------------------------------------------------------------
// Launch
// ---------------------------------------------------------------------------
extern "C" void kernel_launch(void* const* d_in, const int* in_sizes, int n_in,
                              void* d_out, int out_size)
{
    (void)in_sizes; (void)n_in; (void)out_size;

    const float* x  = (const float*)d_in[0];
    const float* W1 = (const float*)d_in[1];
    const float* b1 = (const float*)d_in[2];
    const float* W2 = (const float*)d_in[3];
    const float* b2 = (const float*)d_in[4];
    const float* Wq = (const float*)d_in[5];
    const float* bq = (const float*)d_in[6];
    const float* Wk = (const float*)d_in[7];
    const float* bk = (const float*)d_in[8];
    const float* Wv = (const float*)d_in[9];
    const float* bv = (const float*)d_in[10];
    const float* Wo = (const float*)d_in[11];
    const float* bo = (const float*)d_in[12];
    float* out = (float*)d_out;

    float *xr, *h1, *xm, *q, *k, *v, *o;
    float *w1t, *w2t, *wqt, *wkt, *wvt, *wot;
    cudaGetSymbolAddress((void**)&xr, g_xr);
    cudaGetSymbolAddress((void**)&h1, g_h1);
    cudaGetSymbolAddress((void**)&xm, g_xm);
    cudaGetSymbolAddress((void**)&q,  g_q);
    cudaGetSymbolAddress((void**)&k,  g_k);
    cudaGetSymbolAddress((void**)&v,  g_v);
    cudaGetSymbolAddress((void**)&o,  g_o);
    cudaGetSymbolAddress((void**)&w1t, g_w1t);
    cudaGetSymbolAddress((void**)&w2t, g_w2t);
    cudaGetSymbolAddress((void**)&wqt, g_wqt);
    cudaGetSymbolAddress((void**)&wkt, g_wkt);
    cudaGetSymbolAddress((void**)&wvt, g_wvt);
    cudaGetSymbolAddress((void**)&wot, g_wot);

    const int attn_smem = (QTILE * QKP + 64 * QKP + 64 * VP) * (int)sizeof(float);
    cudaFuncSetAttribute(attn_tf32, cudaFuncAttributeMaxDynamicSharedMemorySize,
                         attn_smem);

    // Prep: round x, transpose+round weights
    preround_tf32<<<(TOK * DMODEL) / (256 * 4), 256>>>(x, xr);
    dim3 tb(32, 8);
    transpose_tf32<<<dim3(1024 / 32, 512 / 32), tb>>>(W1, w1t, 512, 1024);
    transpose_tf32<<<dim3(512 / 32, 1024 / 32), tb>>>(W2, w2t, 1024, 512);
    transpose_tf32<<<dim3(16, 16), tb>>>(Wq, wqt, 512, 512);
    transpose_tf32<<<dim3(16, 16), tb>>>(Wk, wkt, 512, 512);
    transpose_tf32<<<dim3(16, 16), tb>>>(Wv, wvt, 512, 512);
    transpose_tf32<<<dim3(16, 16), tb>>>(Wo, wot, 512, 512);

    dim3 blk(128);
    gemm_tf32<1, 1><<<dim3(1024 / 128, TOK / 128), blk>>>(xr, w1t, b1, h1,  TOK, 1024,  DMODEL);
    gemm_tf32<0, 1><<<dim3(DMODEL / 128, TOK / 128), blk>>>(h1, w2t, b2, xm, TOK, DMODEL, 1024);
    gemm_tf32<0, 1><<<dim3(DMODEL / 128, TOK / 128), blk>>>(xm, wqt, bq, q,  TOK, DMODEL, DMODEL);
    gemm_tf32<0, 1><<<dim3(DMODEL / 128, TOK / 128), blk>>>(xm, wkt, bk, k,  TOK, DMODEL, DMODEL);
    gemm_tf32<0, 1><<<dim3(DMODEL / 128, TOK / 128), blk>>>(xm, wvt, bv, v,  TOK, DMODEL, DMODEL);
    attn_tf32<<<dim3(SQ / QTILE, 4 * NHEADS), dim3(256), attn_smem>>>(q, k, v, o);
    gemm_tf32<0, 0><<<dim3(DMODEL / 128, TOK / 128), blk>>>(o,  wot, bo, out, TOK, DMODEL, DMODEL);
}

// round 8
// speedup vs baseline: 1.7672x; 1.6478x over previous
#include <cuda_runtime.h>
#include <cuda_fp16.h>
#include <cstdint>

#define TOK    8192
#define DMODEL 512
#define SQ     2048
#define NHEADS 8
#define HDIM   64
#define WIN    5

// ---------------------------------------------------------------------------
// Device scratch (half precision)
// ---------------------------------------------------------------------------
__device__ __half g_xh[(size_t)TOK * DMODEL];
__device__ __half g_h1[(size_t)TOK * 1024];
__device__ __half g_xm[(size_t)TOK * DMODEL];
__device__ __half g_q [(size_t)TOK * DMODEL];
__device__ __half g_k [(size_t)TOK * DMODEL];
__device__ __half g_vt[(size_t)4 * NHEADS * HDIM * SQ];  // [b*8+h][d][s]
__device__ __half g_o [(size_t)TOK * DMODEL];
// transposed weights, [N][K] half
__device__ __half g_w1t[(size_t)1024 * 512];
__device__ __half g_w2t[(size_t)512 * 1024];
__device__ __half g_wqt[(size_t)512 * 512];
__device__ __half g_wkt[(size_t)512 * 512];
__device__ __half g_wvt[(size_t)512 * 512];
__device__ __half g_wot[(size_t)512 * 512];

// ---------------------------------------------------------------------------
// helpers
// ---------------------------------------------------------------------------
__device__ __forceinline__ uint32_t smem_u32(const void* p) {
    uint32_t a;
    asm("{ .reg .u64 t; cvta.to.shared.u64 t, %1; cvt.u32.u64 %0, t; }"
        : "=r"(a) : "l"(p));
    return a;
}

#define CP_ASYNC16(dst_u32, src_ptr) \
    asm volatile("cp.async.cg.shared.global [%0], [%1], 16;" \
                 :: "r"(dst_u32), "l"(src_ptr) : "memory")
#define CP_COMMIT() asm volatile("cp.async.commit_group;" ::: "memory")
#define CP_WAIT(n)  asm volatile("cp.async.wait_group %0;" :: "n"(n) : "memory")

__device__ __forceinline__ void mma_f16(
    float& d0, float& d1, float& d2, float& d3,
    unsigned a0, unsigned a1, unsigned a2, unsigned a3,
    unsigned b0, unsigned b1)
{
    asm volatile(
        "mma.sync.aligned.m16n8k16.row.col.f32.f16.f16.f32 "
        "{%0,%1,%2,%3},{%4,%5,%6,%7},{%8,%9},{%0,%1,%2,%3};\n"
        : "+f"(d0), "+f"(d1), "+f"(d2), "+f"(d3)
        : "r"(a0), "r"(a1), "r"(a2), "r"(a3), "r"(b0), "r"(b1));
}

// ---------------------------------------------------------------------------
// fp32 -> half elementwise
// ---------------------------------------------------------------------------
__global__ __launch_bounds__(256) void to_half(
    const float* __restrict__ src, __half* __restrict__ dst)
{
    const size_t i = ((size_t)blockIdx.x * 256 + threadIdx.x) * 4;
    float4 v = *(const float4*)(src + i);
    __half2* d = (__half2*)(dst + i);
    d[0] = __floats2half2_rn(v.x, v.y);
    d[1] = __floats2half2_rn(v.z, v.w);
}

// ---------------------------------------------------------------------------
// Weight transpose to half: dst[n][k] = h(src[k][n])
// ---------------------------------------------------------------------------
__global__ __launch_bounds__(256) void transpose_h(
    const float* __restrict__ src, __half* __restrict__ dst, int K, int N)
{
    __shared__ float t[32][33];
    const int k0 = blockIdx.y * 32;
    const int n0 = blockIdx.x * 32;
    const int tx = threadIdx.x, ty = threadIdx.y;
#pragma unroll
    for (int i = 0; i < 4; i++)
        t[ty + i * 8][tx] = src[(size_t)(k0 + ty + i * 8) * N + n0 + tx];
    __syncthreads();
#pragma unroll
    for (int i = 0; i < 4; i++)
        dst[(size_t)(n0 + ty + i * 8) * K + k0 + tx] =
            __float2half_rn(t[tx][ty + i * 8]);
}

struct P4 { const float* src[4]; __half* dst[4]; };

__global__ __launch_bounds__(256) void transpose4_h(P4 p)
{
    __shared__ float t[32][33];
    const float* src = p.src[blockIdx.z];
    __half* dst = p.dst[blockIdx.z];
    const int k0 = blockIdx.y * 32;
    const int n0 = blockIdx.x * 32;
    const int tx = threadIdx.x, ty = threadIdx.y;
#pragma unroll
    for (int i = 0; i < 4; i++)
        t[ty + i * 8][tx] = src[(size_t)(k0 + ty + i * 8) * 512 + n0 + tx];
    __syncthreads();
#pragma unroll
    for (int i = 0; i < 4; i++)
        dst[(size_t)(n0 + ty + i * 8) * 512 + k0 + tx] =
            __float2half_rn(t[tx][ty + i * 8]);
}

// ---------------------------------------------------------------------------
// FP16 GEMM: C[M,N] = act(A[M,K] @ Bt[N,K]^T + bias)
// BM=128, BN=128, BK=32; 128 threads = 4 warps (2x2), warp tile 64x64.
// cp.async double buffering. OMODE: 0=float out, 1=half out, 2=half V^T out.
// ---------------------------------------------------------------------------
#define AP 40   // halves per smem row (32 + 8 pad); stride 80B

template<int RELU, int OMODE>
__global__ __launch_bounds__(128) void gemm_f16(
    const __half* __restrict__ A, const __half* __restrict__ Bt,
    const float* __restrict__ bias, void* __restrict__ Cv,
    int M, int N, int K)
{
    __shared__ __half As[2][128][AP];
    __shared__ __half Bs[2][128][AP];   // [n][k]

    const int tid  = threadIdx.x;
    const int warp = tid >> 5;
    const int lane = tid & 31;
    const int g    = lane >> 2;
    const int tg   = lane & 3;
    const int wm   = warp >> 1;
    const int wn   = warp & 1;
    const int m0   = blockIdx.y * 128;
    const int n0   = blockIdx.x * 128;

    const uint32_t aBase = smem_u32(&As[0][0][0]);
    const uint32_t bBase = smem_u32(&Bs[0][0][0]);
    const uint32_t bufStride = 128 * AP * 2;   // bytes per buffer

    float acc[4][8][4];
#pragma unroll
    for (int mi = 0; mi < 4; mi++)
#pragma unroll
        for (int nj = 0; nj < 8; nj++)
#pragma unroll
            for (int r = 0; r < 4; r++) acc[mi][nj][r] = 0.f;

    // tile loads: 128 rows x 32 halves = 4 x 16B chunks/row; 4 chunk-loads/thread
    // prologue: tile 0
#pragma unroll
    for (int t = 0; t < 4; t++) {
        const int idx = tid + t * 128;
        const int r = idx >> 2, ch = idx & 3;
        CP_ASYNC16(aBase + (uint32_t)(r * AP * 2 + ch * 16),
                   A + (size_t)(m0 + r) * K + ch * 8);
        CP_ASYNC16(bBase + (uint32_t)(r * AP * 2 + ch * 16),
                   Bt + (size_t)(n0 + r) * K + ch * 8);
    }
    CP_COMMIT();

    const int nt = K >> 5;
    int buf = 0;
    for (int kt = 0; kt < nt; kt++) {
        if (kt + 1 < nt) {
            const int k0 = (kt + 1) << 5;
            const uint32_t aOff = aBase + (buf ^ 1) * bufStride;
            const uint32_t bOff = bBase + (buf ^ 1) * bufStride;
#pragma unroll
            for (int t = 0; t < 4; t++) {
                const int idx = tid + t * 128;
                const int r = idx >> 2, ch = idx & 3;
                CP_ASYNC16(aOff + (uint32_t)(r * AP * 2 + ch * 16),
                           A + (size_t)(m0 + r) * K + k0 + ch * 8);
                CP_ASYNC16(bOff + (uint32_t)(r * AP * 2 + ch * 16),
                           Bt + (size_t)(n0 + r) * K + k0 + ch * 8);
            }
            CP_COMMIT();
            CP_WAIT(1);
        } else {
            CP_WAIT(0);
        }
        __syncthreads();

#pragma unroll
        for (int ks = 0; ks < 2; ks++) {
            const int kb = ks * 16;
            unsigned a[4][4];
#pragma unroll
            for (int mi = 0; mi < 4; mi++) {
                const int row = wm * 64 + mi * 16;
                a[mi][0] = *(const uint32_t*)&As[buf][row + g    ][kb + 2 * tg    ];
                a[mi][1] = *(const uint32_t*)&As[buf][row + g + 8][kb + 2 * tg    ];
                a[mi][2] = *(const uint32_t*)&As[buf][row + g    ][kb + 2 * tg + 8];
                a[mi][3] = *(const uint32_t*)&As[buf][row + g + 8][kb + 2 * tg + 8];
            }
            unsigned b[8][2];
#pragma unroll
            for (int nj = 0; nj < 8; nj++) {
                const int col = wn * 64 + nj * 8 + g;
                b[nj][0] = *(const uint32_t*)&Bs[buf][col][kb + 2 * tg    ];
                b[nj][1] = *(const uint32_t*)&Bs[buf][col][kb + 2 * tg + 8];
            }
#pragma unroll
            for (int mi = 0; mi < 4; mi++)
#pragma unroll
                for (int nj = 0; nj < 8; nj++)
                    mma_f16(acc[mi][nj][0], acc[mi][nj][1],
                            acc[mi][nj][2], acc[mi][nj][3],
                            a[mi][0], a[mi][1], a[mi][2], a[mi][3],
                            b[nj][0], b[nj][1]);
        }
        __syncthreads();
        buf ^= 1;
    }

    // Epilogue
#pragma unroll
    for (int mi = 0; mi < 4; mi++) {
        const int row = m0 + wm * 64 + mi * 16 + g;
#pragma unroll
        for (int nj = 0; nj < 8; nj++) {
            const int col = n0 + wn * 64 + nj * 8 + tg * 2;
            float2 bv = *(const float2*)(bias + col);
            float c0x = acc[mi][nj][0] + bv.x;
            float c0y = acc[mi][nj][1] + bv.y;
            float c1x = acc[mi][nj][2] + bv.x;
            float c1y = acc[mi][nj][3] + bv.y;
            if (RELU) {
                c0x = fmaxf(c0x, 0.f); c0y = fmaxf(c0y, 0.f);
                c1x = fmaxf(c1x, 0.f); c1y = fmaxf(c1y, 0.f);
            }
            if (OMODE == 0) {
                float* C = (float*)Cv;
                float2 u; u.x = c0x; u.y = c0y;
                float2 w; w.x = c1x; w.y = c1y;
                *(float2*)(C + (size_t)row * N + col)       = u;
                *(float2*)(C + (size_t)(row + 8) * N + col) = w;
            } else if (OMODE == 1) {
                __half* C = (__half*)Cv;
                *(__half2*)(C + (size_t)row * N + col)       = __floats2half2_rn(c0x, c0y);
                *(__half2*)(C + (size_t)(row + 8) * N + col) = __floats2half2_rn(c1x, c1y);
            } else {
                // V^T: vt[(b*8+h)][dd][s],  b = row>>11, s = row&2047,
                //      h = col>>6, dd = col&63
                __half* C = (__half*)Cv;
                const int b = row >> 11, s = row & 2047;
                const int h = col >> 6, dd = col & 63;
                const size_t base = (((size_t)(b * 8 + h) * 64 + dd) << 11);
                C[base + s]               = __float2half_rn(c0x);
                C[base + 2048 + s]        = __float2half_rn(c0y);   // dd+1 same h
                C[base + s + 8]           = __float2half_rn(c1x);
                C[base + 2048 + s + 8]    = __float2half_rn(c1y);
            }
        }
    }
}

// ---------------------------------------------------------------------------
// FP16 MMA flash attention (QTILE=256), inverse band mask.
// m16n8k16; hd=64 -> 4 k-steps. V read pre-transposed from vt.
// ---------------------------------------------------------------------------
#define QP_STRIDE 72   // halves (64 + 8 pad), 144B row
#define QTILE 256

__global__ __launch_bounds__(256) void attn_f16(
    const __half* __restrict__ Qg, const __half* __restrict__ Kg,
    const __half* __restrict__ Vt, __half* __restrict__ Og)
{
    extern __shared__ __half smh[];
    __half (*QP)[QP_STRIDE] = (__half(*)[QP_STRIDE])smh;                 // [256][72]
    __half (*Ks)[QP_STRIDE] = (__half(*)[QP_STRIDE])(smh + QTILE * QP_STRIDE); // [64][72]
    __half (*Vs)[QP_STRIDE] = (__half(*)[QP_STRIDE])(smh + (QTILE + 64) * QP_STRIDE); // [64][72]

    const int tid  = threadIdx.x;
    const int warp = tid >> 5;
    const int lane = tid & 31;
    const int g    = lane >> 2;
    const int tg   = lane & 3;
    const int bh   = blockIdx.y;
    const int b    = bh >> 3;
    const int h    = bh & 7;
    const int q0   = blockIdx.x * QTILE;
    const int wrow = warp * 32;

    const __half* Qb  = Qg + (size_t)b * SQ * DMODEL + h * HDIM;
    const __half* Kb  = Kg + (size_t)b * SQ * DMODEL + h * HDIM;
    const __half* Vtb = Vt + (size_t)bh * HDIM * SQ;

    // Stage Q (scaled by 1/8, exact in fp16)
    const __half2 sc = __float2half2_rn(0.125f);
#pragma unroll
    for (int t = 0; t < 8; t++) {
        const int idx = tid + t * 256;
        const int r = idx >> 3, c = (idx & 7) * 8;
        uint4 v = *(const uint4*)(Qb + (size_t)(q0 + r) * DMODEL + c);
        __half2* pv = (__half2*)&v;
#pragma unroll
        for (int j = 0; j < 4; j++) pv[j] = __hmul2(pv[j], sc);
        *(uint4*)&QP[r][c] = v;
    }
    __syncthreads();

    // Q fragments fully in registers: 4 k-steps x 2 m-tiles x 4 regs
    unsigned qf[4][2][4];
#pragma unroll
    for (int ks = 0; ks < 4; ks++) {
        const int kb = ks * 16;
#pragma unroll
        for (int mi = 0; mi < 2; mi++) {
            const int row = wrow + mi * 16;
            qf[ks][mi][0] = *(const uint32_t*)&QP[row + g    ][kb + 2 * tg    ];
            qf[ks][mi][1] = *(const uint32_t*)&QP[row + g + 8][kb + 2 * tg    ];
            qf[ks][mi][2] = *(const uint32_t*)&QP[row + g    ][kb + 2 * tg + 8];
            qf[ks][mi][3] = *(const uint32_t*)&QP[row + g + 8][kb + 2 * tg + 8];
        }
    }

    float oacc[2][8][4];
#pragma unroll
    for (int mi = 0; mi < 2; mi++)
#pragma unroll
        for (int nj = 0; nj < 8; nj++)
#pragma unroll
            for (int r = 0; r < 4; r++) oacc[mi][nj][r] = 0.f;
    float mrow[2][2], lrow[2][2];
#pragma unroll
    for (int mi = 0; mi < 2; mi++) {
        mrow[mi][0] = mrow[mi][1] = -1e30f;
        lrow[mi][0] = lrow[mi][1] = 0.f;
    }

    for (int kt = 0; kt < SQ / 64; kt++) {
        const int k0 = kt * 64;
        __syncthreads();

        // Stage K [key][d] and V^T [d][key] tiles, 2 uint4 per thread each
#pragma unroll
        for (int t = 0; t < 2; t++) {
            const int idx = tid + t * 256;
            const int r = idx >> 3, c = (idx & 7) * 8;
            *(uint4*)&Ks[r][c] = *(const uint4*)(Kb + (size_t)(k0 + r) * DMODEL + c);
            *(uint4*)&Vs[r][c] = *(const uint4*)(Vtb + (size_t)r * SQ + k0 + c);
        }
        __syncthreads();

        // S = Q @ K^T (32x64 per warp)
        float sfrag[2][8][4];
#pragma unroll
        for (int mi = 0; mi < 2; mi++)
#pragma unroll
            for (int nj = 0; nj < 8; nj++)
#pragma unroll
                for (int r = 0; r < 4; r++) sfrag[mi][nj][r] = 0.f;

#pragma unroll
        for (int ks = 0; ks < 4; ks++) {
            const int kb = ks * 16;
            unsigned bq[8][2];
#pragma unroll
            for (int nj = 0; nj < 8; nj++) {
                const int key = nj * 8 + g;
                bq[nj][0] = *(const uint32_t*)&Ks[key][kb + 2 * tg    ];
                bq[nj][1] = *(const uint32_t*)&Ks[key][kb + 2 * tg + 8];
            }
#pragma unroll
            for (int mi = 0; mi < 2; mi++)
#pragma unroll
                for (int nj = 0; nj < 8; nj++)
                    mma_f16(sfrag[mi][nj][0], sfrag[mi][nj][1],
                            sfrag[mi][nj][2], sfrag[mi][nj][3],
                            qf[ks][mi][0], qf[ks][mi][1],
                            qf[ks][mi][2], qf[ks][mi][3],
                            bq[nj][0], bq[nj][1]);
        }

        // Inverse-band mask
        const bool need_mask = (k0 <= q0 + QTILE - 1 + WIN) && (k0 + 63 >= q0 - WIN);
        if (need_mask) {
#pragma unroll
            for (int mi = 0; mi < 2; mi++) {
                const int qr0 = q0 + wrow + mi * 16 + g;
                const int qr1 = qr0 + 8;
#pragma unroll
                for (int nj = 0; nj < 8; nj++) {
                    const int kc0 = k0 + nj * 8 + tg * 2;
                    if ((unsigned)(qr0 - kc0     + WIN) <= 2 * WIN) sfrag[mi][nj][0] = -1e9f;
                    if ((unsigned)(qr0 - kc0 - 1 + WIN) <= 2 * WIN) sfrag[mi][nj][1] = -1e9f;
                    if ((unsigned)(qr1 - kc0     + WIN) <= 2 * WIN) sfrag[mi][nj][2] = -1e9f;
                    if ((unsigned)(qr1 - kc0 - 1 + WIN) <= 2 * WIN) sfrag[mi][nj][3] = -1e9f;
                }
            }
        }

        // Online softmax
#pragma unroll
        for (int mi = 0; mi < 2; mi++) {
            float tmax0 = -1e30f, tmax1 = -1e30f;
#pragma unroll
            for (int nj = 0; nj < 8; nj++) {
                tmax0 = fmaxf(tmax0, fmaxf(sfrag[mi][nj][0], sfrag[mi][nj][1]));
                tmax1 = fmaxf(tmax1, fmaxf(sfrag[mi][nj][2], sfrag[mi][nj][3]));
            }
#pragma unroll
            for (int off = 1; off <= 2; off <<= 1) {
                tmax0 = fmaxf(tmax0, __shfl_xor_sync(0xffffffffu, tmax0, off));
                tmax1 = fmaxf(tmax1, __shfl_xor_sync(0xffffffffu, tmax1, off));
            }
            const float mnew0 = fmaxf(mrow[mi][0], tmax0);
            const float mnew1 = fmaxf(mrow[mi][1], tmax1);
            const float alpha0 = __expf(mrow[mi][0] - mnew0);
            const float alpha1 = __expf(mrow[mi][1] - mnew1);

            float rs0 = 0.f, rs1 = 0.f;
            const int r0 = wrow + mi * 16 + g;
            const int r1 = r0 + 8;
#pragma unroll
            for (int nj = 0; nj < 8; nj++) {
                const float p0 = __expf(sfrag[mi][nj][0] - mnew0);
                const float p1 = __expf(sfrag[mi][nj][1] - mnew0);
                const float p2 = __expf(sfrag[mi][nj][2] - mnew1);
                const float p3 = __expf(sfrag[mi][nj][3] - mnew1);
                rs0 += p0 + p1;
                rs1 += p2 + p3;
                const int kc = nj * 8 + tg * 2;
                *(__half2*)&QP[r0][kc] = __floats2half2_rn(p0, p1);
                *(__half2*)&QP[r1][kc] = __floats2half2_rn(p2, p3);
            }
#pragma unroll
            for (int off = 1; off <= 2; off <<= 1) {
                rs0 += __shfl_xor_sync(0xffffffffu, rs0, off);
                rs1 += __shfl_xor_sync(0xffffffffu, rs1, off);
            }
            lrow[mi][0] = lrow[mi][0] * alpha0 + rs0;
            lrow[mi][1] = lrow[mi][1] * alpha1 + rs1;
            mrow[mi][0] = mnew0;
            mrow[mi][1] = mnew1;
#pragma unroll
            for (int nj = 0; nj < 8; nj++) {
                oacc[mi][nj][0] *= alpha0; oacc[mi][nj][1] *= alpha0;
                oacc[mi][nj][2] *= alpha1; oacc[mi][nj][3] *= alpha1;
            }
        }
        __syncwarp();   // P rows are warp-private

        // O += P @ V  (A = P [q][key], B = V [key][d] via Vs = V^T [d][key])
#pragma unroll
        for (int ks = 0; ks < 4; ks++) {
            const int kb = ks * 16;
            unsigned ap[2][4];
#pragma unroll
            for (int mi = 0; mi < 2; mi++) {
                const int row = wrow + mi * 16;
                ap[mi][0] = *(const uint32_t*)&QP[row + g    ][kb + 2 * tg    ];
                ap[mi][1] = *(const uint32_t*)&QP[row + g + 8][kb + 2 * tg    ];
                ap[mi][2] = *(const uint32_t*)&QP[row + g    ][kb + 2 * tg + 8];
                ap[mi][3] = *(const uint32_t*)&QP[row + g + 8][kb + 2 * tg + 8];
            }
            unsigned bv[8][2];
#pragma unroll
            for (int nj = 0; nj < 8; nj++) {
                const int col = nj * 8 + g;   // d index
                bv[nj][0] = *(const uint32_t*)&Vs[col][kb + 2 * tg    ];
                bv[nj][1] = *(const uint32_t*)&Vs[col][kb + 2 * tg + 8];
            }
#pragma unroll
            for (int mi = 0; mi < 2; mi++)
#pragma unroll
                for (int nj = 0; nj < 8; nj++)
                    mma_f16(oacc[mi][nj][0], oacc[mi][nj][1],
                            oacc[mi][nj][2], oacc[mi][nj][3],
                            ap[mi][0], ap[mi][1], ap[mi][2], ap[mi][3],
                            bv[nj][0], bv[nj][1]);
        }
    }

    // Finalize: write half (consumed by final GEMM)
    __half* Ob = Og + (size_t)b * SQ * DMODEL + h * HDIM;
#pragma unroll
    for (int mi = 0; mi < 2; mi++) {
        const float inv0 = 1.0f / lrow[mi][0];
        const float inv1 = 1.0f / lrow[mi][1];
        const int row0 = q0 + wrow + mi * 16 + g;
#pragma unroll
        for (int nj = 0; nj < 8; nj++) {
            const int col = nj * 8 + tg * 2;
            *(__half2*)(Ob + (size_t)row0 * DMODEL + col) =
                __floats2half2_rn(oacc[mi][nj][0] * inv0, oacc[mi][nj][1] * inv0);
            *(__half2*)(Ob + (size_t)(row0 + 8) * DMODEL + col) =
                __floats2half2_rn(oacc[mi][nj][2] * inv1, oacc[mi][nj][3] * inv1);
        }
    }
}

// ---------------------------------------------------------------------------
// Launch
// ---------------------------------------------------------------------------
extern "C" void kernel_launch(void* const* d_in, const int* in_sizes, int n_in,
                              void* d_out, int out_size)
{
    (void)in_sizes; (void)n_in; (void)out_size;

    const float* x  = (const float*)d_in[0];
    const float* W1 = (const float*)d_in[1];
    const float* b1 = (const float*)d_in[2];
    const float* W2 = (const float*)d_in[3];
    const float* b2 = (const float*)d_in[4];
    const float* Wq = (const float*)d_in[5];
    const float* bq = (const float*)d_in[6];
    const float* Wk = (const float*)d_in[7];
    const float* bk = (const float*)d_in[8];
    const float* Wv = (const float*)d_in[9];
    const float* bv = (const float*)d_in[10];
    const float* Wo = (const float*)d_in[11];
    const float* bo = (const float*)d_in[12];
    float* out = (float*)d_out;

    __half *xh, *h1, *xm, *q, *k, *vt, *o;
    __half *w1t, *w2t, *wqt, *wkt, *wvt, *wot;
    cudaGetSymbolAddress((void**)&xh, g_xh);
    cudaGetSymbolAddress((void**)&h1, g_h1);
    cudaGetSymbolAddress((void**)&xm, g_xm);
    cudaGetSymbolAddress((void**)&q,  g_q);
    cudaGetSymbolAddress((void**)&k,  g_k);
    cudaGetSymbolAddress((void**)&vt, g_vt);
    cudaGetSymbolAddress((void**)&o,  g_o);
    cudaGetSymbolAddress((void**)&w1t, g_w1t);
    cudaGetSymbolAddress((void**)&w2t, g_w2t);
    cudaGetSymbolAddress((void**)&wqt, g_wqt);
    cudaGetSymbolAddress((void**)&wkt, g_wkt);
    cudaGetSymbolAddress((void**)&wvt, g_wvt);
    cudaGetSymbolAddress((void**)&wot, g_wot);

    const int attn_smem = (QTILE + 64 + 64) * QP_STRIDE * (int)sizeof(__half); // 55296
    cudaFuncSetAttribute(attn_f16, cudaFuncAttributeMaxDynamicSharedMemorySize,
                         attn_smem);

    // Prep
    to_half<<<(TOK * DMODEL) / (256 * 4), 256>>>(x, xh);
    dim3 tb(32, 8);
    transpose_h<<<dim3(1024 / 32, 512 / 32), tb>>>(W1, w1t, 512, 1024);
    transpose_h<<<dim3(512 / 32, 1024 / 32), tb>>>(W2, w2t, 1024, 512);
    P4 p4;
    p4.src[0] = Wq; p4.src[1] = Wk; p4.src[2] = Wv; p4.src[3] = Wo;
    p4.dst[0] = wqt; p4.dst[1] = wkt; p4.dst[2] = wvt; p4.dst[3] = wot;
    transpose4_h<<<dim3(16, 16, 4), tb>>>(p4);

    dim3 blk(128);
    gemm_f16<1, 1><<<dim3(1024 / 128, TOK / 128), blk>>>(xh, w1t, b1, h1,  TOK, 1024,  DMODEL);
    gemm_f16<0, 1><<<dim3(DMODEL / 128, TOK / 128), blk>>>(h1, w2t, b2, xm, TOK, DMODEL, 1024);
    gemm_f16<0, 1><<<dim3(DMODEL / 128, TOK / 128), blk>>>(xm, wqt, bq, q,  TOK, DMODEL, DMODEL);
    gemm_f16<0, 1><<<dim3(DMODEL / 128, TOK / 128), blk>>>(xm, wkt, bk, k,  TOK, DMODEL, DMODEL);
    gemm_f16<0, 2><<<dim3(DMODEL / 128, TOK / 128), blk>>>(xm, wvt, bv, vt, TOK, DMODEL, DMODEL);
    attn_f16<<<dim3(SQ / QTILE, 4 * NHEADS), dim3(256), attn_smem>>>(q, k, vt, o);
    gemm_f16<0, 0><<<dim3(DMODEL / 128, TOK / 128), blk>>>(o,  wot, bo, out, TOK, DMODEL, DMODEL);
}

// round 9
// speedup vs baseline: 1.9062x; 1.0787x over previous
#include <cuda_runtime.h>
#include <cuda_fp16.h>
#include <cstdint>

#define TOK    8192
#define DMODEL 512
#define SQ     2048
#define NHEADS 8
#define HDIM   64
#define WIN    5

// ---------------------------------------------------------------------------
// Device scratch (half precision). Weights kept in [K][N] layout (no transpose).
// ---------------------------------------------------------------------------
__device__ __half g_xh[(size_t)TOK * DMODEL];
__device__ __half g_h1[(size_t)TOK * 1024];
__device__ __half g_xm[(size_t)TOK * DMODEL];
__device__ __half g_q [(size_t)TOK * DMODEL];
__device__ __half g_k [(size_t)TOK * DMODEL];
__device__ __half g_vt[(size_t)4 * NHEADS * HDIM * SQ];  // [b*8+h][d][s]
__device__ __half g_o [(size_t)TOK * DMODEL];
__device__ __half g_w1h[(size_t)512 * 1024];
__device__ __half g_w2h[(size_t)1024 * 512];
__device__ __half g_wqh[(size_t)512 * 512];
__device__ __half g_wkh[(size_t)512 * 512];
__device__ __half g_wvh[(size_t)512 * 512];
__device__ __half g_woh[(size_t)512 * 512];

// ---------------------------------------------------------------------------
// helpers
// ---------------------------------------------------------------------------
__device__ __forceinline__ uint32_t smem_u32(const void* p) {
    uint32_t a;
    asm("{ .reg .u64 t; cvta.to.shared.u64 t, %1; cvt.u32.u64 %0, t; }"
        : "=r"(a) : "l"(p));
    return a;
}

#define CP_ASYNC16(dst_u32, src_ptr) \
    asm volatile("cp.async.cg.shared.global [%0], [%1], 16;" \
                 :: "r"(dst_u32), "l"(src_ptr) : "memory")
#define CP_COMMIT() asm volatile("cp.async.commit_group;" ::: "memory")
#define CP_WAIT(n)  asm volatile("cp.async.wait_group %0;" :: "n"(n) : "memory")

__device__ __forceinline__ void mma_f16(
    float& d0, float& d1, float& d2, float& d3,
    unsigned a0, unsigned a1, unsigned a2, unsigned a3,
    unsigned b0, unsigned b1)
{
    asm volatile(
        "mma.sync.aligned.m16n8k16.row.col.f32.f16.f16.f32 "
        "{%0,%1,%2,%3},{%4,%5,%6,%7},{%8,%9},{%0,%1,%2,%3};\n"
        : "+f"(d0), "+f"(d1), "+f"(d2), "+f"(d3)
        : "r"(a0), "r"(a1), "r"(a2), "r"(a3), "r"(b0), "r"(b1));
}

__device__ __forceinline__ void ldm_x4(
    unsigned& r0, unsigned& r1, unsigned& r2, unsigned& r3, uint32_t addr)
{
    asm volatile("ldmatrix.sync.aligned.m8n8.x4.shared.b16 {%0,%1,%2,%3}, [%4];"
        : "=r"(r0), "=r"(r1), "=r"(r2), "=r"(r3) : "r"(addr));
}

__device__ __forceinline__ void ldm_x4_t(
    unsigned& r0, unsigned& r1, unsigned& r2, unsigned& r3, uint32_t addr)
{
    asm volatile("ldmatrix.sync.aligned.m8n8.x4.trans.shared.b16 {%0,%1,%2,%3}, [%4];"
        : "=r"(r0), "=r"(r1), "=r"(r2), "=r"(r3) : "r"(addr));
}

// ---------------------------------------------------------------------------
// fp32 -> half elementwise (x), and batched weight conversion
// ---------------------------------------------------------------------------
__global__ __launch_bounds__(256) void to_half(
    const float* __restrict__ src, __half* __restrict__ dst)
{
    const size_t i = ((size_t)blockIdx.x * 256 + threadIdx.x) * 4;
    float4 v = *(const float4*)(src + i);
    __half2* d = (__half2*)(dst + i);
    d[0] = __floats2half2_rn(v.x, v.y);
    d[1] = __floats2half2_rn(v.z, v.w);
}

struct C6 { const float* s[6]; __half* d[6]; int nblk[6]; };

__global__ __launch_bounds__(256) void conv6(C6 p)
{
    const int z = blockIdx.z;
    if (blockIdx.x >= p.nblk[z]) return;
    const size_t i = ((size_t)blockIdx.x * 256 + threadIdx.x) * 4;
    float4 v = *(const float4*)(p.s[z] + i);
    __half2* d = (__half2*)(p.d[z] + i);
    d[0] = __floats2half2_rn(v.x, v.y);
    d[1] = __floats2half2_rn(v.z, v.w);
}

// ---------------------------------------------------------------------------
// FP16 GEMM: C[M,N] = act(A[M,K] @ W[K,N] + bias)
// BM=128, BN=128, BK=32; 128 threads = 4 warps (2x2), warp tile 64x64.
// A-frags: ldmatrix; B-frags: ldmatrix.trans from [k][n] tile.
// OMODE: 0 = float out, 1 = half out.
// ---------------------------------------------------------------------------
#define AP  40    // A smem row stride in halves (32 + 8)
#define BPH 136   // B smem row stride in halves (128 + 8)

template<int RELU, int OMODE>
__global__ __launch_bounds__(128) void gemm_f16(
    const __half* __restrict__ A, const __half* __restrict__ W,
    const float* __restrict__ bias, void* __restrict__ Cv,
    int M, int N, int K)
{
    __shared__ __half As[2][128][AP];   // [m][k]
    __shared__ __half Bs[2][32][BPH];   // [k][n]

    const int tid  = threadIdx.x;
    const int warp = tid >> 5;
    const int lane = tid & 31;
    const int g    = lane >> 2;
    const int tg   = lane & 3;
    const int wm   = warp >> 1;
    const int wn   = warp & 1;
    const int m0   = blockIdx.y * 128;
    const int n0   = blockIdx.x * 128;

    const uint32_t aBase = smem_u32(&As[0][0][0]);
    const uint32_t bBase = smem_u32(&Bs[0][0][0]);
    const uint32_t aStride = 128 * AP * 2;
    const uint32_t bStride = 32 * BPH * 2;

    float acc[4][8][4];
#pragma unroll
    for (int mi = 0; mi < 4; mi++)
#pragma unroll
        for (int nj = 0; nj < 8; nj++)
#pragma unroll
            for (int r = 0; r < 4; r++) acc[mi][nj][r] = 0.f;

    // prologue: tile 0.  A: 128 rows x 4 chunks; B: 32 rows x 16 chunks.
#pragma unroll
    for (int t = 0; t < 4; t++) {
        const int ia = tid + t * 128;
        const int ra = ia >> 2, ca = ia & 3;
        CP_ASYNC16(aBase + (uint32_t)(ra * AP * 2 + ca * 16),
                   A + (size_t)(m0 + ra) * K + ca * 8);
        const int rb = ia >> 4, cb = ia & 15;
        CP_ASYNC16(bBase + (uint32_t)(rb * BPH * 2 + cb * 16),
                   W + (size_t)rb * N + n0 + cb * 8);
    }
    CP_COMMIT();

    const int nt = K >> 5;
    int buf = 0;
    for (int kt = 0; kt < nt; kt++) {
        if (kt + 1 < nt) {
            const int k0 = (kt + 1) << 5;
            const uint32_t aOff = aBase + (buf ^ 1) * aStride;
            const uint32_t bOff = bBase + (buf ^ 1) * bStride;
#pragma unroll
            for (int t = 0; t < 4; t++) {
                const int ia = tid + t * 128;
                const int ra = ia >> 2, ca = ia & 3;
                CP_ASYNC16(aOff + (uint32_t)(ra * AP * 2 + ca * 16),
                           A + (size_t)(m0 + ra) * K + k0 + ca * 8);
                const int rb = ia >> 4, cb = ia & 15;
                CP_ASYNC16(bOff + (uint32_t)(rb * BPH * 2 + cb * 16),
                           W + (size_t)(k0 + rb) * N + n0 + cb * 8);
            }
            CP_COMMIT();
            CP_WAIT(1);
        } else {
            CP_WAIT(0);
        }
        __syncthreads();

        const uint32_t aB = aBase + buf * aStride;
        const uint32_t bB = bBase + buf * bStride;
        const int lrow = lane & 15;          // ldmatrix row-within-16
        const int lcol = (lane >> 4) << 3;   // 0 or 8

#pragma unroll
        for (int ks = 0; ks < 2; ks++) {
            const int kb = ks * 16;
            unsigned a[4][4];
#pragma unroll
            for (int mi = 0; mi < 4; mi++) {
                const int row0 = wm * 64 + mi * 16;
                ldm_x4(a[mi][0], a[mi][1], a[mi][2], a[mi][3],
                       aB + (uint32_t)(((row0 + lrow) * AP + kb + lcol) * 2));
            }
            unsigned b[8][2];
#pragma unroll
            for (int njp = 0; njp < 4; njp++) {
                const int col0 = wn * 64 + njp * 16;
                ldm_x4_t(b[2 * njp][0], b[2 * njp][1],
                         b[2 * njp + 1][0], b[2 * njp + 1][1],
                         bB + (uint32_t)(((kb + lrow) * BPH + col0 + lcol) * 2));
            }
#pragma unroll
            for (int mi = 0; mi < 4; mi++)
#pragma unroll
                for (int nj = 0; nj < 8; nj++)
                    mma_f16(acc[mi][nj][0], acc[mi][nj][1],
                            acc[mi][nj][2], acc[mi][nj][3],
                            a[mi][0], a[mi][1], a[mi][2], a[mi][3],
                            b[nj][0], b[nj][1]);
        }
        __syncthreads();
        buf ^= 1;
    }

    // Epilogue
#pragma unroll
    for (int mi = 0; mi < 4; mi++) {
        const int row = m0 + wm * 64 + mi * 16 + g;
#pragma unroll
        for (int nj = 0; nj < 8; nj++) {
            const int col = n0 + wn * 64 + nj * 8 + tg * 2;
            float2 bv = *(const float2*)(bias + col);
            float c0x = acc[mi][nj][0] + bv.x;
            float c0y = acc[mi][nj][1] + bv.y;
            float c1x = acc[mi][nj][2] + bv.x;
            float c1y = acc[mi][nj][3] + bv.y;
            if (RELU) {
                c0x = fmaxf(c0x, 0.f); c0y = fmaxf(c0y, 0.f);
                c1x = fmaxf(c1x, 0.f); c1y = fmaxf(c1y, 0.f);
            }
            if (OMODE == 0) {
                float* C = (float*)Cv;
                float2 u; u.x = c0x; u.y = c0y;
                float2 w; w.x = c1x; w.y = c1y;
                *(float2*)(C + (size_t)row * N + col)       = u;
                *(float2*)(C + (size_t)(row + 8) * N + col) = w;
            } else {
                __half* C = (__half*)Cv;
                *(__half2*)(C + (size_t)row * N + col)       = __floats2half2_rn(c0x, c0y);
                *(__half2*)(C + (size_t)(row + 8) * N + col) = __floats2half2_rn(c1x, c1y);
            }
        }
    }
}

// ---------------------------------------------------------------------------
// Fused QKV GEMM: one launch over N=1536 (3 x 512 regions).
// region 0 -> q (half), 1 -> k (half), 2 -> v transposed into vt.
// ---------------------------------------------------------------------------
struct QKVp {
    const __half* w[3];
    const float*  b[3];
    __half* q; __half* k; __half* vt;
};

__global__ __launch_bounds__(128) void gemm_qkv(
    const __half* __restrict__ A, QKVp p, int M, int K)
{
    __shared__ __half As[2][128][AP];
    __shared__ __half Bs[2][32][BPH];

    const int tid  = threadIdx.x;
    const int warp = tid >> 5;
    const int lane = tid & 31;
    const int g    = lane >> 2;
    const int tg   = lane & 3;
    const int wm   = warp >> 1;
    const int wn   = warp & 1;
    const int m0   = blockIdx.y * 128;
    const int n0g  = blockIdx.x * 128;        // global col 0..1535
    const int reg  = n0g >> 9;
    const int n0   = n0g & 511;               // col within region
    const __half* W = p.w[reg];
    const float* bias = p.b[reg];

    const uint32_t aBase = smem_u32(&As[0][0][0]);
    const uint32_t bBase = smem_u32(&Bs[0][0][0]);
    const uint32_t aStride = 128 * AP * 2;
    const uint32_t bStride = 32 * BPH * 2;

    float acc[4][8][4];
#pragma unroll
    for (int mi = 0; mi < 4; mi++)
#pragma unroll
        for (int nj = 0; nj < 8; nj++)
#pragma unroll
            for (int r = 0; r < 4; r++) acc[mi][nj][r] = 0.f;

#pragma unroll
    for (int t = 0; t < 4; t++) {
        const int ia = tid + t * 128;
        const int ra = ia >> 2, ca = ia & 3;
        CP_ASYNC16(aBase + (uint32_t)(ra * AP * 2 + ca * 16),
                   A + (size_t)(m0 + ra) * K + ca * 8);
        const int rb = ia >> 4, cb = ia & 15;
        CP_ASYNC16(bBase + (uint32_t)(rb * BPH * 2 + cb * 16),
                   W + (size_t)rb * 512 + n0 + cb * 8);
    }
    CP_COMMIT();

    const int nt = K >> 5;
    int buf = 0;
    for (int kt = 0; kt < nt; kt++) {
        if (kt + 1 < nt) {
            const int k0 = (kt + 1) << 5;
            const uint32_t aOff = aBase + (buf ^ 1) * aStride;
            const uint32_t bOff = bBase + (buf ^ 1) * bStride;
#pragma unroll
            for (int t = 0; t < 4; t++) {
                const int ia = tid + t * 128;
                const int ra = ia >> 2, ca = ia & 3;
                CP_ASYNC16(aOff + (uint32_t)(ra * AP * 2 + ca * 16),
                           A + (size_t)(m0 + ra) * K + k0 + ca * 8);
                const int rb = ia >> 4, cb = ia & 15;
                CP_ASYNC16(bOff + (uint32_t)(rb * BPH * 2 + cb * 16),
                           W + (size_t)(k0 + rb) * 512 + n0 + cb * 8);
            }
            CP_COMMIT();
            CP_WAIT(1);
        } else {
            CP_WAIT(0);
        }
        __syncthreads();

        const uint32_t aB = aBase + buf * aStride;
        const uint32_t bB = bBase + buf * bStride;
        const int lrow = lane & 15;
        const int lcol = (lane >> 4) << 3;

#pragma unroll
        for (int ks = 0; ks < 2; ks++) {
            const int kb = ks * 16;
            unsigned a[4][4];
#pragma unroll
            for (int mi = 0; mi < 4; mi++) {
                const int row0 = wm * 64 + mi * 16;
                ldm_x4(a[mi][0], a[mi][1], a[mi][2], a[mi][3],
                       aB + (uint32_t)(((row0 + lrow) * AP + kb + lcol) * 2));
            }
            unsigned b[8][2];
#pragma unroll
            for (int njp = 0; njp < 4; njp++) {
                const int col0 = wn * 64 + njp * 16;
                ldm_x4_t(b[2 * njp][0], b[2 * njp][1],
                         b[2 * njp + 1][0], b[2 * njp + 1][1],
                         bB + (uint32_t)(((kb + lrow) * BPH + col0 + lcol) * 2));
            }
#pragma unroll
            for (int mi = 0; mi < 4; mi++)
#pragma unroll
                for (int nj = 0; nj < 8; nj++)
                    mma_f16(acc[mi][nj][0], acc[mi][nj][1],
                            acc[mi][nj][2], acc[mi][nj][3],
                            a[mi][0], a[mi][1], a[mi][2], a[mi][3],
                            b[nj][0], b[nj][1]);
        }
        __syncthreads();
        buf ^= 1;
    }

    // Epilogue with region dispatch
#pragma unroll
    for (int mi = 0; mi < 4; mi++) {
        const int row = m0 + wm * 64 + mi * 16 + g;
#pragma unroll
        for (int nj = 0; nj < 8; nj++) {
            const int coln = n0 + wn * 64 + nj * 8 + tg * 2;
            float2 bv = *(const float2*)(bias + coln);
            const float c0x = acc[mi][nj][0] + bv.x;
            const float c0y = acc[mi][nj][1] + bv.y;
            const float c1x = acc[mi][nj][2] + bv.x;
            const float c1y = acc[mi][nj][3] + bv.y;
            if (reg == 2) {
                // V^T: vt[(b*8+h)][dd][s]
                __half* C = p.vt;
                const int b = row >> 11, s = row & 2047;
                const int h = coln >> 6, dd = coln & 63;
                const size_t base = (((size_t)(b * 8 + h) * 64 + dd) << 11);
                C[base + s]            = __float2half_rn(c0x);
                C[base + 2048 + s]     = __float2half_rn(c0y);
                C[base + s + 8]        = __float2half_rn(c1x);
                C[base + 2048 + s + 8] = __float2half_rn(c1y);
            } else {
                __half* C = (reg == 0) ? p.q : p.k;
                *(__half2*)(C + (size_t)row * DMODEL + coln)       = __floats2half2_rn(c0x, c0y);
                *(__half2*)(C + (size_t)(row + 8) * DMODEL + coln) = __floats2half2_rn(c1x, c1y);
            }
        }
    }
}

// ---------------------------------------------------------------------------
// FP16 MMA flash attention (QTILE=256), inverse band mask, ldmatrix operands.
// ---------------------------------------------------------------------------
#define QP_STRIDE 72
#define QTILE 256

__global__ __launch_bounds__(256) void attn_f16(
    const __half* __restrict__ Qg, const __half* __restrict__ Kg,
    const __half* __restrict__ Vt, __half* __restrict__ Og)
{
    extern __shared__ __half smh[];
    __half (*QP)[QP_STRIDE] = (__half(*)[QP_STRIDE])smh;
    __half (*Ks)[QP_STRIDE] = (__half(*)[QP_STRIDE])(smh + QTILE * QP_STRIDE);
    __half (*Vs)[QP_STRIDE] = (__half(*)[QP_STRIDE])(smh + (QTILE + 64) * QP_STRIDE);

    const int tid  = threadIdx.x;
    const int warp = tid >> 5;
    const int lane = tid & 31;
    const int g    = lane >> 2;
    const int tg   = lane & 3;
    const int bh   = blockIdx.y;
    const int b    = bh >> 3;
    const int h    = bh & 7;
    const int q0   = blockIdx.x * QTILE;
    const int wrow = warp * 32;

    const uint32_t qpB = smem_u32(&QP[0][0]);
    const uint32_t ksB = smem_u32(&Ks[0][0]);
    const uint32_t vsB = smem_u32(&Vs[0][0]);
    const int lr16 = lane & 15;
    const int lc16 = (lane >> 4) << 3;
    const int lr8  = (lane & 7) + ((lane >> 4) << 3);
    const int lc8  = ((lane >> 3) & 1) << 3;

    const __half* Qb  = Qg + (size_t)b * SQ * DMODEL + h * HDIM;
    const __half* Kb  = Kg + (size_t)b * SQ * DMODEL + h * HDIM;
    const __half* Vtb = Vt + (size_t)bh * HDIM * SQ;

    // Stage Q (scaled by 1/8)
    const __half2 sc = __float2half2_rn(0.125f);
#pragma unroll
    for (int t = 0; t < 8; t++) {
        const int idx = tid + t * 256;
        const int r = idx >> 3, c = (idx & 7) * 8;
        uint4 v = *(const uint4*)(Qb + (size_t)(q0 + r) * DMODEL + c);
        __half2* pv = (__half2*)&v;
#pragma unroll
        for (int j = 0; j < 4; j++) pv[j] = __hmul2(pv[j], sc);
        *(uint4*)&QP[r][c] = v;
    }
    __syncthreads();

    // Q fragments via ldmatrix: 4 k-steps x 2 m-tiles
    unsigned qf[4][2][4];
#pragma unroll
    for (int ks = 0; ks < 4; ks++) {
        const int kb = ks * 16;
#pragma unroll
        for (int mi = 0; mi < 2; mi++) {
            const int row0 = wrow + mi * 16;
            ldm_x4(qf[ks][mi][0], qf[ks][mi][1], qf[ks][mi][2], qf[ks][mi][3],
                   qpB + (uint32_t)(((row0 + lr16) * QP_STRIDE + kb + lc16) * 2));
        }
    }

    float oacc[2][8][4];
#pragma unroll
    for (int mi = 0; mi < 2; mi++)
#pragma unroll
        for (int nj = 0; nj < 8; nj++)
#pragma unroll
            for (int r = 0; r < 4; r++) oacc[mi][nj][r] = 0.f;
    float mrow[2][2], lrow[2][2];
#pragma unroll
    for (int mi = 0; mi < 2; mi++) {
        mrow[mi][0] = mrow[mi][1] = -1e30f;
        lrow[mi][0] = lrow[mi][1] = 0.f;
    }

    for (int kt = 0; kt < SQ / 64; kt++) {
        const int k0 = kt * 64;
        __syncthreads();

#pragma unroll
        for (int t = 0; t < 2; t++) {
            const int idx = tid + t * 256;
            const int r = idx >> 3, c = (idx & 7) * 8;
            *(uint4*)&Ks[r][c] = *(const uint4*)(Kb + (size_t)(k0 + r) * DMODEL + c);
            *(uint4*)&Vs[r][c] = *(const uint4*)(Vtb + (size_t)r * SQ + k0 + c);
        }
        __syncthreads();

        // S = Q @ K^T
        float sfrag[2][8][4];
#pragma unroll
        for (int mi = 0; mi < 2; mi++)
#pragma unroll
            for (int nj = 0; nj < 8; nj++)
#pragma unroll
                for (int r = 0; r < 4; r++) sfrag[mi][nj][r] = 0.f;

#pragma unroll
        for (int ks = 0; ks < 4; ks++) {
            const int kb = ks * 16;
            unsigned bq[8][2];
#pragma unroll
            for (int njp = 0; njp < 4; njp++) {
                ldm_x4(bq[2 * njp][0], bq[2 * njp][1],
                       bq[2 * njp + 1][0], bq[2 * njp + 1][1],
                       ksB + (uint32_t)(((njp * 16 + lr8) * QP_STRIDE + kb + lc8) * 2));
            }
#pragma unroll
            for (int mi = 0; mi < 2; mi++)
#pragma unroll
                for (int nj = 0; nj < 8; nj++)
                    mma_f16(sfrag[mi][nj][0], sfrag[mi][nj][1],
                            sfrag[mi][nj][2], sfrag[mi][nj][3],
                            qf[ks][mi][0], qf[ks][mi][1],
                            qf[ks][mi][2], qf[ks][mi][3],
                            bq[nj][0], bq[nj][1]);
        }

        // Inverse-band mask
        const bool need_mask = (k0 <= q0 + QTILE - 1 + WIN) && (k0 + 63 >= q0 - WIN);
        if (need_mask) {
#pragma unroll
            for (int mi = 0; mi < 2; mi++) {
                const int qr0 = q0 + wrow + mi * 16 + g;
                const int qr1 = qr0 + 8;
#pragma unroll
                for (int nj = 0; nj < 8; nj++) {
                    const int kc0 = k0 + nj * 8 + tg * 2;
                    if ((unsigned)(qr0 - kc0     + WIN) <= 2 * WIN) sfrag[mi][nj][0] = -1e9f;
                    if ((unsigned)(qr0 - kc0 - 1 + WIN) <= 2 * WIN) sfrag[mi][nj][1] = -1e9f;
                    if ((unsigned)(qr1 - kc0     + WIN) <= 2 * WIN) sfrag[mi][nj][2] = -1e9f;
                    if ((unsigned)(qr1 - kc0 - 1 + WIN) <= 2 * WIN) sfrag[mi][nj][3] = -1e9f;
                }
            }
        }

        // Online softmax
#pragma unroll
        for (int mi = 0; mi < 2; mi++) {
            float tmax0 = -1e30f, tmax1 = -1e30f;
#pragma unroll
            for (int nj = 0; nj < 8; nj++) {
                tmax0 = fmaxf(tmax0, fmaxf(sfrag[mi][nj][0], sfrag[mi][nj][1]));
                tmax1 = fmaxf(tmax1, fmaxf(sfrag[mi][nj][2], sfrag[mi][nj][3]));
            }
#pragma unroll
            for (int off = 1; off <= 2; off <<= 1) {
                tmax0 = fmaxf(tmax0, __shfl_xor_sync(0xffffffffu, tmax0, off));
                tmax1 = fmaxf(tmax1, __shfl_xor_sync(0xffffffffu, tmax1, off));
            }
            const float mnew0 = fmaxf(mrow[mi][0], tmax0);
            const float mnew1 = fmaxf(mrow[mi][1], tmax1);
            const float alpha0 = __expf(mrow[mi][0] - mnew0);
            const float alpha1 = __expf(mrow[mi][1] - mnew1);

            float rs0 = 0.f, rs1 = 0.f;
            const int r0 = wrow + mi * 16 + g;
            const int r1 = r0 + 8;
#pragma unroll
            for (int nj = 0; nj < 8; nj++) {
                const float p0 = __expf(sfrag[mi][nj][0] - mnew0);
                const float p1 = __expf(sfrag[mi][nj][1] - mnew0);
                const float p2 = __expf(sfrag[mi][nj][2] - mnew1);
                const float p3 = __expf(sfrag[mi][nj][3] - mnew1);
                rs0 += p0 + p1;
                rs1 += p2 + p3;
                const int kc = nj * 8 + tg * 2;
                *(__half2*)&QP[r0][kc] = __floats2half2_rn(p0, p1);
                *(__half2*)&QP[r1][kc] = __floats2half2_rn(p2, p3);
            }
#pragma unroll
            for (int off = 1; off <= 2; off <<= 1) {
                rs0 += __shfl_xor_sync(0xffffffffu, rs0, off);
                rs1 += __shfl_xor_sync(0xffffffffu, rs1, off);
            }
            lrow[mi][0] = lrow[mi][0] * alpha0 + rs0;
            lrow[mi][1] = lrow[mi][1] * alpha1 + rs1;
            mrow[mi][0] = mnew0;
            mrow[mi][1] = mnew1;
#pragma unroll
            for (int nj = 0; nj < 8; nj++) {
                oacc[mi][nj][0] *= alpha0; oacc[mi][nj][1] *= alpha0;
                oacc[mi][nj][2] *= alpha1; oacc[mi][nj][3] *= alpha1;
            }
        }
        __syncwarp();

        // O += P @ V
#pragma unroll
        for (int ks = 0; ks < 4; ks++) {
            const int kb = ks * 16;
            unsigned ap[2][4];
#pragma unroll
            for (int mi = 0; mi < 2; mi++) {
                const int row0 = wrow + mi * 16;
                ldm_x4(ap[mi][0], ap[mi][1], ap[mi][2], ap[mi][3],
                       qpB + (uint32_t)(((row0 + lr16) * QP_STRIDE + kb + lc16) * 2));
            }
            unsigned bv[8][2];
#pragma unroll
            for (int njp = 0; njp < 4; njp++) {
                ldm_x4(bv[2 * njp][0], bv[2 * njp][1],
                       bv[2 * njp + 1][0], bv[2 * njp + 1][1],
                       vsB + (uint32_t)(((njp * 16 + lr8) * QP_STRIDE + kb + lc8) * 2));
            }
#pragma unroll
            for (int mi = 0; mi < 2; mi++)
#pragma unroll
                for (int nj = 0; nj < 8; nj++)
                    mma_f16(oacc[mi][nj][0], oacc[mi][nj][1],
                            oacc[mi][nj][2], oacc[mi][nj][3],
                            ap[mi][0], ap[mi][1], ap[mi][2], ap[mi][3],
                            bv[nj][0], bv[nj][1]);
        }
    }

    // Finalize: write half
    __half* Ob = Og + (size_t)b * SQ * DMODEL + h * HDIM;
#pragma unroll
    for (int mi = 0; mi < 2; mi++) {
        const float inv0 = 1.0f / lrow[mi][0];
        const float inv1 = 1.0f / lrow[mi][1];
        const int row0 = q0 + wrow + mi * 16 + g;
#pragma unroll
        for (int nj = 0; nj < 8; nj++) {
            const int col = nj * 8 + tg * 2;
            *(__half2*)(Ob + (size_t)row0 * DMODEL + col) =
                __floats2half2_rn(oacc[mi][nj][0] * inv0, oacc[mi][nj][1] * inv0);
            *(__half2*)(Ob + (size_t)(row0 + 8) * DMODEL + col) =
                __floats2half2_rn(oacc[mi][nj][2] * inv1, oacc[mi][nj][3] * inv1);
        }
    }
}

// ---------------------------------------------------------------------------
// Launch
// ---------------------------------------------------------------------------
extern "C" void kernel_launch(void* const* d_in, const int* in_sizes, int n_in,
                              void* d_out, int out_size)
{
    (void)in_sizes; (void)n_in; (void)out_size;

    const float* x  = (const float*)d_in[0];
    const float* W1 = (const float*)d_in[1];
    const float* b1 = (const float*)d_in[2];
    const float* W2 = (const float*)d_in[3];
    const float* b2 = (const float*)d_in[4];
    const float* Wq = (const float*)d_in[5];
    const float* bq = (const float*)d_in[6];
    const float* Wk = (const float*)d_in[7];
    const float* bk = (const float*)d_in[8];
    const float* Wv = (const float*)d_in[9];
    const float* bv = (const float*)d_in[10];
    const float* Wo = (const float*)d_in[11];
    const float* bo = (const float*)d_in[12];
    float* out = (float*)d_out;

    __half *xh, *h1, *xm, *q, *k, *vt, *o;
    __half *w1h, *w2h, *wqh, *wkh, *wvh, *woh;
    cudaGetSymbolAddress((void**)&xh, g_xh);
    cudaGetSymbolAddress((void**)&h1, g_h1);
    cudaGetSymbolAddress((void**)&xm, g_xm);
    cudaGetSymbolAddress((void**)&q,  g_q);
    cudaGetSymbolAddress((void**)&k,  g_k);
    cudaGetSymbolAddress((void**)&vt, g_vt);
    cudaGetSymbolAddress((void**)&o,  g_o);
    cudaGetSymbolAddress((void**)&w1h, g_w1h);
    cudaGetSymbolAddress((void**)&w2h, g_w2h);
    cudaGetSymbolAddress((void**)&wqh, g_wqh);
    cudaGetSymbolAddress((void**)&wkh, g_wkh);
    cudaGetSymbolAddress((void**)&wvh, g_wvh);
    cudaGetSymbolAddress((void**)&woh, g_woh);

    const int attn_smem = (QTILE + 64 + 64) * QP_STRIDE * (int)sizeof(__half);
    cudaFuncSetAttribute(attn_f16, cudaFuncAttributeMaxDynamicSharedMemorySize,
                         attn_smem);

    // Prep: x -> half; all weights -> half ([K][N] layout preserved)
    to_half<<<(TOK * DMODEL) / (256 * 4), 256>>>(x, xh);
    C6 c6;
    c6.s[0] = W1; c6.d[0] = w1h; c6.nblk[0] = (512 * 1024) / 1024;
    c6.s[1] = W2; c6.d[1] = w2h; c6.nblk[1] = (1024 * 512) / 1024;
    c6.s[2] = Wq; c6.d[2] = wqh; c6.nblk[2] = (512 * 512) / 1024;
    c6.s[3] = Wk; c6.d[3] = wkh; c6.nblk[3] = (512 * 512) / 1024;
    c6.s[4] = Wv; c6.d[4] = wvh; c6.nblk[4] = (512 * 512) / 1024;
    c6.s[5] = Wo; c6.d[5] = woh; c6.nblk[5] = (512 * 512) / 1024;
    conv6<<<dim3(512, 1, 6), 256>>>(c6);

    QKVp qp;
    qp.w[0] = wqh; qp.w[1] = wkh; qp.w[2] = wvh;
    qp.b[0] = bq;  qp.b[1] = bk;  qp.b[2] = bv;
    qp.q = q; qp.k = k; qp.vt = vt;

    dim3 blk(128);
    gemm_f16<1, 1><<<dim3(1024 / 128, TOK / 128), blk>>>(xh, w1h, b1, h1, TOK, 1024, DMODEL);
    gemm_f16<0, 1><<<dim3(DMODEL / 128, TOK / 128), blk>>>(h1, w2h, b2, xm, TOK, DMODEL, 1024);
    gemm_qkv<<<dim3(1536 / 128, TOK / 128), blk>>>(xm, qp, TOK, DMODEL);
    attn_f16<<<dim3(SQ / QTILE, 4 * NHEADS), dim3(256), attn_smem>>>(q, k, vt, o);
    gemm_f16<0, 0><<<dim3(DMODEL / 128, TOK / 128), blk>>>(o, woh, bo, out, TOK, DMODEL, DMODEL);
}

// round 10
// speedup vs baseline: 2.1923x; 1.1501x over previous
#include <cuda_runtime.h>
#include <cuda_fp16.h>
#include <cstdint>

#define TOK    8192
#define DMODEL 512
#define SQ     2048
#define NHEADS 8
#define HDIM   64
#define WIN    5

// ---------------------------------------------------------------------------
// Device scratch (half). Weights in [K][N] layout (no transpose needed).
// ---------------------------------------------------------------------------
__device__ __half g_xh[(size_t)TOK * DMODEL];
__device__ __half g_h1[(size_t)TOK * 1024];
__device__ __half g_xm[(size_t)TOK * DMODEL];
__device__ __half g_q [(size_t)TOK * DMODEL];
__device__ __half g_k [(size_t)TOK * DMODEL];
__device__ __half g_vt[(size_t)4 * NHEADS * HDIM * SQ];  // [b*8+h][d][s]
__device__ __half g_o [(size_t)TOK * DMODEL];
__device__ __half g_w1h[(size_t)512 * 1024];
__device__ __half g_w2h[(size_t)1024 * 512];
__device__ __half g_wqh[(size_t)512 * 512];
__device__ __half g_wkh[(size_t)512 * 512];
__device__ __half g_wvh[(size_t)512 * 512];
__device__ __half g_woh[(size_t)512 * 512];

// ---------------------------------------------------------------------------
// helpers
// ---------------------------------------------------------------------------
__device__ __forceinline__ uint32_t smem_u32(const void* p) {
    uint32_t a;
    asm("{ .reg .u64 t; cvta.to.shared.u64 t, %1; cvt.u32.u64 %0, t; }"
        : "=r"(a) : "l"(p));
    return a;
}

#define CP_ASYNC16(dst_u32, src_ptr) \
    asm volatile("cp.async.cg.shared.global [%0], [%1], 16;" \
                 :: "r"(dst_u32), "l"(src_ptr) : "memory")
#define CP_COMMIT() asm volatile("cp.async.commit_group;" ::: "memory")
#define CP_WAIT(n)  asm volatile("cp.async.wait_group %0;" :: "n"(n) : "memory")

__device__ __forceinline__ void mma_f16(
    float& d0, float& d1, float& d2, float& d3,
    unsigned a0, unsigned a1, unsigned a2, unsigned a3,
    unsigned b0, unsigned b1)
{
    asm volatile(
        "mma.sync.aligned.m16n8k16.row.col.f32.f16.f16.f32 "
        "{%0,%1,%2,%3},{%4,%5,%6,%7},{%8,%9},{%0,%1,%2,%3};\n"
        : "+f"(d0), "+f"(d1), "+f"(d2), "+f"(d3)
        : "r"(a0), "r"(a1), "r"(a2), "r"(a3), "r"(b0), "r"(b1));
}

__device__ __forceinline__ void ldm_x4(
    unsigned& r0, unsigned& r1, unsigned& r2, unsigned& r3, uint32_t addr)
{
    asm volatile("ldmatrix.sync.aligned.m8n8.x4.shared.b16 {%0,%1,%2,%3}, [%4];"
        : "=r"(r0), "=r"(r1), "=r"(r2), "=r"(r3) : "r"(addr));
}

__device__ __forceinline__ void ldm_x4_t(
    unsigned& r0, unsigned& r1, unsigned& r2, unsigned& r3, uint32_t addr)
{
    asm volatile("ldmatrix.sync.aligned.m8n8.x4.trans.shared.b16 {%0,%1,%2,%3}, [%4];"
        : "=r"(r0), "=r"(r1), "=r"(r2), "=r"(r3) : "r"(addr));
}

__device__ __forceinline__ unsigned h2u(__half2 h) {
    return *(unsigned*)&h;
}

// ---------------------------------------------------------------------------
// fp32 -> half conversions
// ---------------------------------------------------------------------------
__global__ __launch_bounds__(256) void to_half(
    const float* __restrict__ src, __half* __restrict__ dst)
{
    const size_t i = ((size_t)blockIdx.x * 256 + threadIdx.x) * 4;
    float4 v = *(const float4*)(src + i);
    __half2* d = (__half2*)(dst + i);
    d[0] = __floats2half2_rn(v.x, v.y);
    d[1] = __floats2half2_rn(v.z, v.w);
}

struct C6 { const float* s[6]; __half* d[6]; int nblk[6]; };

__global__ __launch_bounds__(256) void conv6(C6 p)
{
    const int z = blockIdx.z;
    if (blockIdx.x >= p.nblk[z]) return;
    const size_t i = ((size_t)blockIdx.x * 256 + threadIdx.x) * 4;
    float4 v = *(const float4*)(p.s[z] + i);
    __half2* d = (__half2*)(p.d[z] + i);
    d[0] = __floats2half2_rn(v.x, v.y);
    d[1] = __floats2half2_rn(v.z, v.w);
}

// ---------------------------------------------------------------------------
// FP16 GEMM: C[M,N] = act(A[M,K] @ W[K,N] + bias)
// BM=64, BN=128, BK=32; 128 threads = 4 warps (2x2), warp tile 32x64.
// ldmatrix feeds, cp.async double buffer. OMODE: 0=float out, 1=half out.
// ---------------------------------------------------------------------------
#define AP  40
#define BPH 136

template<int RELU, int OMODE>
__global__ __launch_bounds__(128) void gemm_f16(
    const __half* __restrict__ A, const __half* __restrict__ W,
    const float* __restrict__ bias, void* __restrict__ Cv,
    int M, int N, int K)
{
    __shared__ __half As[2][64][AP];    // [m][k]
    __shared__ __half Bs[2][32][BPH];   // [k][n]

    const int tid  = threadIdx.x;
    const int warp = tid >> 5;
    const int lane = tid & 31;
    const int g    = lane >> 2;
    const int tg   = lane & 3;
    const int wm   = warp >> 1;
    const int wn   = warp & 1;
    const int m0   = blockIdx.y * 64;
    const int n0   = blockIdx.x * 128;

    const uint32_t aBase = smem_u32(&As[0][0][0]);
    const uint32_t bBase = smem_u32(&Bs[0][0][0]);
    const uint32_t aStride = 64 * AP * 2;
    const uint32_t bStride = 32 * BPH * 2;

    float acc[2][8][4];
#pragma unroll
    for (int mi = 0; mi < 2; mi++)
#pragma unroll
        for (int nj = 0; nj < 8; nj++)
#pragma unroll
            for (int r = 0; r < 4; r++) acc[mi][nj][r] = 0.f;

    // prologue: A 64x4 chunks (2/thread), B 32x16 chunks (4/thread)
#pragma unroll
    for (int t = 0; t < 2; t++) {
        const int ia = tid + t * 128;
        const int ra = ia >> 2, ca = ia & 3;
        CP_ASYNC16(aBase + (uint32_t)(ra * AP * 2 + ca * 16),
                   A + (size_t)(m0 + ra) * K + ca * 8);
    }
#pragma unroll
    for (int t = 0; t < 4; t++) {
        const int ib = tid + t * 128;
        const int rb = ib >> 4, cb = ib & 15;
        CP_ASYNC16(bBase + (uint32_t)(rb * BPH * 2 + cb * 16),
                   W + (size_t)rb * N + n0 + cb * 8);
    }
    CP_COMMIT();

    const int nt = K >> 5;
    int buf = 0;
    for (int kt = 0; kt < nt; kt++) {
        if (kt + 1 < nt) {
            const int k0 = (kt + 1) << 5;
            const uint32_t aOff = aBase + (buf ^ 1) * aStride;
            const uint32_t bOff = bBase + (buf ^ 1) * bStride;
#pragma unroll
            for (int t = 0; t < 2; t++) {
                const int ia = tid + t * 128;
                const int ra = ia >> 2, ca = ia & 3;
                CP_ASYNC16(aOff + (uint32_t)(ra * AP * 2 + ca * 16),
                           A + (size_t)(m0 + ra) * K + k0 + ca * 8);
            }
#pragma unroll
            for (int t = 0; t < 4; t++) {
                const int ib = tid + t * 128;
                const int rb = ib >> 4, cb = ib & 15;
                CP_ASYNC16(bOff + (uint32_t)(rb * BPH * 2 + cb * 16),
                           W + (size_t)(k0 + rb) * N + n0 + cb * 8);
            }
            CP_COMMIT();
            CP_WAIT(1);
        } else {
            CP_WAIT(0);
        }
        __syncthreads();

        const uint32_t aB = aBase + buf * aStride;
        const uint32_t bB = bBase + buf * bStride;
        const int lrow = lane & 15;
        const int lcol = (lane >> 4) << 3;

#pragma unroll
        for (int ks = 0; ks < 2; ks++) {
            const int kb = ks * 16;
            unsigned a[2][4];
#pragma unroll
            for (int mi = 0; mi < 2; mi++) {
                const int row0 = wm * 32 + mi * 16;
                ldm_x4(a[mi][0], a[mi][1], a[mi][2], a[mi][3],
                       aB + (uint32_t)(((row0 + lrow) * AP + kb + lcol) * 2));
            }
            unsigned b[8][2];
#pragma unroll
            for (int njp = 0; njp < 4; njp++) {
                const int col0 = wn * 64 + njp * 16;
                ldm_x4_t(b[2 * njp][0], b[2 * njp][1],
                         b[2 * njp + 1][0], b[2 * njp + 1][1],
                         bB + (uint32_t)(((kb + lrow) * BPH + col0 + lcol) * 2));
            }
#pragma unroll
            for (int mi = 0; mi < 2; mi++)
#pragma unroll
                for (int nj = 0; nj < 8; nj++)
                    mma_f16(acc[mi][nj][0], acc[mi][nj][1],
                            acc[mi][nj][2], acc[mi][nj][3],
                            a[mi][0], a[mi][1], a[mi][2], a[mi][3],
                            b[nj][0], b[nj][1]);
        }
        __syncthreads();
        buf ^= 1;
    }

    // Epilogue
#pragma unroll
    for (int mi = 0; mi < 2; mi++) {
        const int row = m0 + wm * 32 + mi * 16 + g;
#pragma unroll
        for (int nj = 0; nj < 8; nj++) {
            const int col = n0 + wn * 64 + nj * 8 + tg * 2;
            float2 bv = *(const float2*)(bias + col);
            float c0x = acc[mi][nj][0] + bv.x;
            float c0y = acc[mi][nj][1] + bv.y;
            float c1x = acc[mi][nj][2] + bv.x;
            float c1y = acc[mi][nj][3] + bv.y;
            if (RELU) {
                c0x = fmaxf(c0x, 0.f); c0y = fmaxf(c0y, 0.f);
                c1x = fmaxf(c1x, 0.f); c1y = fmaxf(c1y, 0.f);
            }
            if (OMODE == 0) {
                float* C = (float*)Cv;
                float2 u; u.x = c0x; u.y = c0y;
                float2 w; w.x = c1x; w.y = c1y;
                *(float2*)(C + (size_t)row * N + col)       = u;
                *(float2*)(C + (size_t)(row + 8) * N + col) = w;
            } else {
                __half* C = (__half*)Cv;
                *(__half2*)(C + (size_t)row * N + col)       = __floats2half2_rn(c0x, c0y);
                *(__half2*)(C + (size_t)(row + 8) * N + col) = __floats2half2_rn(c1x, c1y);
            }
        }
    }
}

// ---------------------------------------------------------------------------
// Fused QKV GEMM (BM=64): N=1536, regions q/k/vt.
// ---------------------------------------------------------------------------
struct QKVp {
    const __half* w[3];
    const float*  b[3];
    __half* q; __half* k; __half* vt;
};

__global__ __launch_bounds__(128) void gemm_qkv(
    const __half* __restrict__ A, QKVp p, int M, int K)
{
    __shared__ __half As[2][64][AP];
    __shared__ __half Bs[2][32][BPH];

    const int tid  = threadIdx.x;
    const int warp = tid >> 5;
    const int lane = tid & 31;
    const int g    = lane >> 2;
    const int tg   = lane & 3;
    const int wm   = warp >> 1;
    const int wn   = warp & 1;
    const int m0   = blockIdx.y * 64;
    const int n0g  = blockIdx.x * 128;
    const int reg  = n0g >> 9;
    const int n0   = n0g & 511;
    const __half* W = p.w[reg];
    const float* bias = p.b[reg];

    const uint32_t aBase = smem_u32(&As[0][0][0]);
    const uint32_t bBase = smem_u32(&Bs[0][0][0]);
    const uint32_t aStride = 64 * AP * 2;
    const uint32_t bStride = 32 * BPH * 2;

    float acc[2][8][4];
#pragma unroll
    for (int mi = 0; mi < 2; mi++)
#pragma unroll
        for (int nj = 0; nj < 8; nj++)
#pragma unroll
            for (int r = 0; r < 4; r++) acc[mi][nj][r] = 0.f;

#pragma unroll
    for (int t = 0; t < 2; t++) {
        const int ia = tid + t * 128;
        const int ra = ia >> 2, ca = ia & 3;
        CP_ASYNC16(aBase + (uint32_t)(ra * AP * 2 + ca * 16),
                   A + (size_t)(m0 + ra) * K + ca * 8);
    }
#pragma unroll
    for (int t = 0; t < 4; t++) {
        const int ib = tid + t * 128;
        const int rb = ib >> 4, cb = ib & 15;
        CP_ASYNC16(bBase + (uint32_t)(rb * BPH * 2 + cb * 16),
                   W + (size_t)rb * 512 + n0 + cb * 8);
    }
    CP_COMMIT();

    const int nt = K >> 5;
    int buf = 0;
    for (int kt = 0; kt < nt; kt++) {
        if (kt + 1 < nt) {
            const int k0 = (kt + 1) << 5;
            const uint32_t aOff = aBase + (buf ^ 1) * aStride;
            const uint32_t bOff = bBase + (buf ^ 1) * bStride;
#pragma unroll
            for (int t = 0; t < 2; t++) {
                const int ia = tid + t * 128;
                const int ra = ia >> 2, ca = ia & 3;
                CP_ASYNC16(aOff + (uint32_t)(ra * AP * 2 + ca * 16),
                           A + (size_t)(m0 + ra) * K + k0 + ca * 8);
            }
#pragma unroll
            for (int t = 0; t < 4; t++) {
                const int ib = tid + t * 128;
                const int rb = ib >> 4, cb = ib & 15;
                CP_ASYNC16(bOff + (uint32_t)(rb * BPH * 2 + cb * 16),
                           W + (size_t)(k0 + rb) * 512 + n0 + cb * 8);
            }
            CP_COMMIT();
            CP_WAIT(1);
        } else {
            CP_WAIT(0);
        }
        __syncthreads();

        const uint32_t aB = aBase + buf * aStride;
        const uint32_t bB = bBase + buf * bStride;
        const int lrow = lane & 15;
        const int lcol = (lane >> 4) << 3;

#pragma unroll
        for (int ks = 0; ks < 2; ks++) {
            const int kb = ks * 16;
            unsigned a[2][4];
#pragma unroll
            for (int mi = 0; mi < 2; mi++) {
                const int row0 = wm * 32 + mi * 16;
                ldm_x4(a[mi][0], a[mi][1], a[mi][2], a[mi][3],
                       aB + (uint32_t)(((row0 + lrow) * AP + kb + lcol) * 2));
            }
            unsigned b[8][2];
#pragma unroll
            for (int njp = 0; njp < 4; njp++) {
                const int col0 = wn * 64 + njp * 16;
                ldm_x4_t(b[2 * njp][0], b[2 * njp][1],
                         b[2 * njp + 1][0], b[2 * njp + 1][1],
                         bB + (uint32_t)(((kb + lrow) * BPH + col0 + lcol) * 2));
            }
#pragma unroll
            for (int mi = 0; mi < 2; mi++)
#pragma unroll
                for (int nj = 0; nj < 8; nj++)
                    mma_f16(acc[mi][nj][0], acc[mi][nj][1],
                            acc[mi][nj][2], acc[mi][nj][3],
                            a[mi][0], a[mi][1], a[mi][2], a[mi][3],
                            b[nj][0], b[nj][1]);
        }
        __syncthreads();
        buf ^= 1;
    }

#pragma unroll
    for (int mi = 0; mi < 2; mi++) {
        const int row = m0 + wm * 32 + mi * 16 + g;
#pragma unroll
        for (int nj = 0; nj < 8; nj++) {
            const int coln = n0 + wn * 64 + nj * 8 + tg * 2;
            float2 bv = *(const float2*)(bias + coln);
            const float c0x = acc[mi][nj][0] + bv.x;
            const float c0y = acc[mi][nj][1] + bv.y;
            const float c1x = acc[mi][nj][2] + bv.x;
            const float c1y = acc[mi][nj][3] + bv.y;
            if (reg == 2) {
                __half* C = p.vt;
                const int b = row >> 11, s = row & 2047;
                const int h = coln >> 6, dd = coln & 63;
                const size_t base = (((size_t)(b * 8 + h) * 64 + dd) << 11);
                C[base + s]            = __float2half_rn(c0x);
                C[base + 2048 + s]     = __float2half_rn(c0y);
                C[base + s + 8]        = __float2half_rn(c1x);
                C[base + 2048 + s + 8] = __float2half_rn(c1y);
            } else {
                __half* C = (reg == 0) ? p.q : p.k;
                *(__half2*)(C + (size_t)row * DMODEL + coln)       = __floats2half2_rn(c0x, c0y);
                *(__half2*)(C + (size_t)(row + 8) * DMODEL + coln) = __floats2half2_rn(c1x, c1y);
            }
        }
    }
}

// ---------------------------------------------------------------------------
// FP16 flash attention: QTILE=256, register-resident P, cp.async K/V pipeline.
// ---------------------------------------------------------------------------
#define QP_STRIDE 72
#define QTILE 256
#define KVBUF (64 * QP_STRIDE)

__global__ __launch_bounds__(256) void attn_f16(
    const __half* __restrict__ Qg, const __half* __restrict__ Kg,
    const __half* __restrict__ Vt, __half* __restrict__ Og)
{
    extern __shared__ __half smh[];
    __half (*QP)[QP_STRIDE] = (__half(*)[QP_STRIDE])smh;              // [256][72]
    __half* KsBase = smh + QTILE * QP_STRIDE;                          // [2][64][72]
    __half* VsBase = KsBase + 2 * KVBUF;                               // [2][64][72]

    const int tid  = threadIdx.x;
    const int warp = tid >> 5;
    const int lane = tid & 31;
    const int g    = lane >> 2;
    const int tg   = lane & 3;
    const int bh   = blockIdx.y;
    const int b    = bh >> 3;
    const int h    = bh & 7;
    const int q0   = blockIdx.x * QTILE;
    const int wrow = warp * 32;

    const uint32_t qpB = smem_u32(&QP[0][0]);
    const uint32_t ksB = smem_u32(KsBase);
    const uint32_t vsB = smem_u32(VsBase);
    const int lr16 = lane & 15;
    const int lc16 = (lane >> 4) << 3;
    const int lr8  = (lane & 7) + ((lane >> 4) << 3);
    const int lc8  = ((lane >> 3) & 1) << 3;

    const __half* Qb  = Qg + (size_t)b * SQ * DMODEL + h * HDIM;
    const __half* Kb  = Kg + (size_t)b * SQ * DMODEL + h * HDIM;
    const __half* Vtb = Vt + (size_t)bh * HDIM * SQ;

    // Stage Q (scaled by 1/8)
    const __half2 sc = __float2half2_rn(0.125f);
#pragma unroll
    for (int t = 0; t < 8; t++) {
        const int idx = tid + t * 256;
        const int r = idx >> 3, c = (idx & 7) * 8;
        uint4 v = *(const uint4*)(Qb + (size_t)(q0 + r) * DMODEL + c);
        __half2* pv = (__half2*)&v;
#pragma unroll
        for (int j = 0; j < 4; j++) pv[j] = __hmul2(pv[j], sc);
        *(uint4*)&QP[r][c] = v;
    }

    // Prologue: issue K/V tile 0 (K: 512 chunks, V: 512 chunks; 4/thread)
#pragma unroll
    for (int t = 0; t < 2; t++) {
        const int idx = tid + t * 256;
        const int r = idx >> 3, c = (idx & 7) * 8;
        CP_ASYNC16(ksB + (uint32_t)((r * QP_STRIDE + c) * 2),
                   Kb + (size_t)r * DMODEL + c);
        CP_ASYNC16(vsB + (uint32_t)((r * QP_STRIDE + c) * 2),
                   Vtb + (size_t)r * SQ + c);
    }
    CP_COMMIT();
    __syncthreads();

    // Q fragments via ldmatrix
    unsigned qf[4][2][4];
#pragma unroll
    for (int ks = 0; ks < 4; ks++) {
        const int kb = ks * 16;
#pragma unroll
        for (int mi = 0; mi < 2; mi++) {
            const int row0 = wrow + mi * 16;
            ldm_x4(qf[ks][mi][0], qf[ks][mi][1], qf[ks][mi][2], qf[ks][mi][3],
                   qpB + (uint32_t)(((row0 + lr16) * QP_STRIDE + kb + lc16) * 2));
        }
    }

    float oacc[2][8][4];
#pragma unroll
    for (int mi = 0; mi < 2; mi++)
#pragma unroll
        for (int nj = 0; nj < 8; nj++)
#pragma unroll
            for (int r = 0; r < 4; r++) oacc[mi][nj][r] = 0.f;
    float mrow[2][2], lrow[2][2];
#pragma unroll
    for (int mi = 0; mi < 2; mi++) {
        mrow[mi][0] = mrow[mi][1] = -1e30f;
        lrow[mi][0] = lrow[mi][1] = 0.f;
    }

    const int NT = SQ / 64;
    for (int kt = 0; kt < NT; kt++) {
        const int k0 = kt * 64;
        const int buf = kt & 1;

        if (kt + 1 < NT) {
            const int kn = (kt + 1) * 64;
            const uint32_t kOff = ksB + (buf ^ 1) * KVBUF * 2;
            const uint32_t vOff = vsB + (buf ^ 1) * KVBUF * 2;
#pragma unroll
            for (int t = 0; t < 2; t++) {
                const int idx = tid + t * 256;
                const int r = idx >> 3, c = (idx & 7) * 8;
                CP_ASYNC16(kOff + (uint32_t)((r * QP_STRIDE + c) * 2),
                           Kb + (size_t)(kn + r) * DMODEL + c);
                CP_ASYNC16(vOff + (uint32_t)((r * QP_STRIDE + c) * 2),
                           Vtb + (size_t)r * SQ + kn + c);
            }
            CP_COMMIT();
            CP_WAIT(1);
        } else {
            CP_WAIT(0);
        }
        __syncthreads();

        const uint32_t kB = ksB + buf * KVBUF * 2;
        const uint32_t vB = vsB + buf * KVBUF * 2;

        // S = Q @ K^T
        float sfrag[2][8][4];
#pragma unroll
        for (int mi = 0; mi < 2; mi++)
#pragma unroll
            for (int nj = 0; nj < 8; nj++)
#pragma unroll
                for (int r = 0; r < 4; r++) sfrag[mi][nj][r] = 0.f;

#pragma unroll
        for (int ks = 0; ks < 4; ks++) {
            const int kb = ks * 16;
            unsigned bq[8][2];
#pragma unroll
            for (int njp = 0; njp < 4; njp++) {
                ldm_x4(bq[2 * njp][0], bq[2 * njp][1],
                       bq[2 * njp + 1][0], bq[2 * njp + 1][1],
                       kB + (uint32_t)(((njp * 16 + lr8) * QP_STRIDE + kb + lc8) * 2));
            }
#pragma unroll
            for (int mi = 0; mi < 2; mi++)
#pragma unroll
                for (int nj = 0; nj < 8; nj++)
                    mma_f16(sfrag[mi][nj][0], sfrag[mi][nj][1],
                            sfrag[mi][nj][2], sfrag[mi][nj][3],
                            qf[ks][mi][0], qf[ks][mi][1],
                            qf[ks][mi][2], qf[ks][mi][3],
                            bq[nj][0], bq[nj][1]);
        }

        // Inverse-band mask
        const bool need_mask = (k0 <= q0 + QTILE - 1 + WIN) && (k0 + 63 >= q0 - WIN);
        if (need_mask) {
#pragma unroll
            for (int mi = 0; mi < 2; mi++) {
                const int qr0 = q0 + wrow + mi * 16 + g;
                const int qr1 = qr0 + 8;
#pragma unroll
                for (int nj = 0; nj < 8; nj++) {
                    const int kc0 = k0 + nj * 8 + tg * 2;
                    if ((unsigned)(qr0 - kc0     + WIN) <= 2 * WIN) sfrag[mi][nj][0] = -1e9f;
                    if ((unsigned)(qr0 - kc0 - 1 + WIN) <= 2 * WIN) sfrag[mi][nj][1] = -1e9f;
                    if ((unsigned)(qr1 - kc0     + WIN) <= 2 * WIN) sfrag[mi][nj][2] = -1e9f;
                    if ((unsigned)(qr1 - kc0 - 1 + WIN) <= 2 * WIN) sfrag[mi][nj][3] = -1e9f;
                }
            }
        }

        // Online softmax; P packed directly into A-fragments (register-resident)
        unsigned pf[2][8][2];
#pragma unroll
        for (int mi = 0; mi < 2; mi++) {
            float tmax0 = -1e30f, tmax1 = -1e30f;
#pragma unroll
            for (int nj = 0; nj < 8; nj++) {
                tmax0 = fmaxf(tmax0, fmaxf(sfrag[mi][nj][0], sfrag[mi][nj][1]));
                tmax1 = fmaxf(tmax1, fmaxf(sfrag[mi][nj][2], sfrag[mi][nj][3]));
            }
#pragma unroll
            for (int off = 1; off <= 2; off <<= 1) {
                tmax0 = fmaxf(tmax0, __shfl_xor_sync(0xffffffffu, tmax0, off));
                tmax1 = fmaxf(tmax1, __shfl_xor_sync(0xffffffffu, tmax1, off));
            }
            const float mnew0 = fmaxf(mrow[mi][0], tmax0);
            const float mnew1 = fmaxf(mrow[mi][1], tmax1);
            const float alpha0 = __expf(mrow[mi][0] - mnew0);
            const float alpha1 = __expf(mrow[mi][1] - mnew1);

            float rs0 = 0.f, rs1 = 0.f;
#pragma unroll
            for (int nj = 0; nj < 8; nj++) {
                const float p0 = __expf(sfrag[mi][nj][0] - mnew0);
                const float p1 = __expf(sfrag[mi][nj][1] - mnew0);
                const float p2 = __expf(sfrag[mi][nj][2] - mnew1);
                const float p3 = __expf(sfrag[mi][nj][3] - mnew1);
                rs0 += p0 + p1;
                rs1 += p2 + p3;
                pf[mi][nj][0] = h2u(__floats2half2_rn(p0, p1));  // row g
                pf[mi][nj][1] = h2u(__floats2half2_rn(p2, p3));  // row g+8
            }
#pragma unroll
            for (int off = 1; off <= 2; off <<= 1) {
                rs0 += __shfl_xor_sync(0xffffffffu, rs0, off);
                rs1 += __shfl_xor_sync(0xffffffffu, rs1, off);
            }
            lrow[mi][0] = lrow[mi][0] * alpha0 + rs0;
            lrow[mi][1] = lrow[mi][1] * alpha1 + rs1;
            mrow[mi][0] = mnew0;
            mrow[mi][1] = mnew1;
#pragma unroll
            for (int nj = 0; nj < 8; nj++) {
                oacc[mi][nj][0] *= alpha0; oacc[mi][nj][1] *= alpha0;
                oacc[mi][nj][2] *= alpha1; oacc[mi][nj][3] *= alpha1;
            }
        }

        // O += P @ V   (A-fragments straight from pf; B via ldmatrix on V^T)
#pragma unroll
        for (int ks = 0; ks < 4; ks++) {
            const int kb = ks * 16;
            unsigned bv[8][2];
#pragma unroll
            for (int njp = 0; njp < 4; njp++) {
                ldm_x4(bv[2 * njp][0], bv[2 * njp][1],
                       bv[2 * njp + 1][0], bv[2 * njp + 1][1],
                       vB + (uint32_t)(((njp * 16 + lr8) * QP_STRIDE + kb + lc8) * 2));
            }
#pragma unroll
            for (int mi = 0; mi < 2; mi++) {
                const unsigned a0 = pf[mi][2 * ks][0];
                const unsigned a1 = pf[mi][2 * ks][1];
                const unsigned a2 = pf[mi][2 * ks + 1][0];
                const unsigned a3 = pf[mi][2 * ks + 1][1];
#pragma unroll
                for (int nj = 0; nj < 8; nj++)
                    mma_f16(oacc[mi][nj][0], oacc[mi][nj][1],
                            oacc[mi][nj][2], oacc[mi][nj][3],
                            a0, a1, a2, a3, bv[nj][0], bv[nj][1]);
            }
        }
        __syncthreads();   // all reads of buf done before next issue overwrites
    }

    // Finalize: write half
    __half* Ob = Og + (size_t)b * SQ * DMODEL + h * HDIM;
#pragma unroll
    for (int mi = 0; mi < 2; mi++) {
        const float inv0 = 1.0f / lrow[mi][0];
        const float inv1 = 1.0f / lrow[mi][1];
        const int row0 = q0 + wrow + mi * 16 + g;
#pragma unroll
        for (int nj = 0; nj < 8; nj++) {
            const int col = nj * 8 + tg * 2;
            *(__half2*)(Ob + (size_t)row0 * DMODEL + col) =
                __floats2half2_rn(oacc[mi][nj][0] * inv0, oacc[mi][nj][1] * inv0);
            *(__half2*)(Ob + (size_t)(row0 + 8) * DMODEL + col) =
                __floats2half2_rn(oacc[mi][nj][2] * inv1, oacc[mi][nj][3] * inv1);
        }
    }
}

// ---------------------------------------------------------------------------
// Launch
// ---------------------------------------------------------------------------
extern "C" void kernel_launch(void* const* d_in, const int* in_sizes, int n_in,
                              void* d_out, int out_size)
{
    (void)in_sizes; (void)n_in; (void)out_size;

    const float* x  = (const float*)d_in[0];
    const float* W1 = (const float*)d_in[1];
    const float* b1 = (const float*)d_in[2];
    const float* W2 = (const float*)d_in[3];
    const float* b2 = (const float*)d_in[4];
    const float* Wq = (const float*)d_in[5];
    const float* bq = (const float*)d_in[6];
    const float* Wk = (const float*)d_in[7];
    const float* bk = (const float*)d_in[8];
    const float* Wv = (const float*)d_in[9];
    const float* bv = (const float*)d_in[10];
    const float* Wo = (const float*)d_in[11];
    const float* bo = (const float*)d_in[12];
    float* out = (float*)d_out;

    __half *xh, *h1, *xm, *q, *k, *vt, *o;
    __half *w1h, *w2h, *wqh, *wkh, *wvh, *woh;
    cudaGetSymbolAddress((void**)&xh, g_xh);
    cudaGetSymbolAddress((void**)&h1, g_h1);
    cudaGetSymbolAddress((void**)&xm, g_xm);
    cudaGetSymbolAddress((void**)&q,  g_q);
    cudaGetSymbolAddress((void**)&k,  g_k);
    cudaGetSymbolAddress((void**)&vt, g_vt);
    cudaGetSymbolAddress((void**)&o,  g_o);
    cudaGetSymbolAddress((void**)&w1h, g_w1h);
    cudaGetSymbolAddress((void**)&w2h, g_w2h);
    cudaGetSymbolAddress((void**)&wqh, g_wqh);
    cudaGetSymbolAddress((void**)&wkh, g_wkh);
    cudaGetSymbolAddress((void**)&wvh, g_wvh);
    cudaGetSymbolAddress((void**)&woh, g_woh);

    const int attn_smem = (QTILE * QP_STRIDE + 4 * KVBUF) * (int)sizeof(__half); // 73728
    cudaFuncSetAttribute(attn_f16, cudaFuncAttributeMaxDynamicSharedMemorySize,
                         attn_smem);

    // Prep
    to_half<<<(TOK * DMODEL) / (256 * 4), 256>>>(x, xh);
    C6 c6;
    c6.s[0] = W1; c6.d[0] = w1h; c6.nblk[0] = (512 * 1024) / 1024;
    c6.s[1] = W2; c6.d[1] = w2h; c6.nblk[1] = (1024 * 512) / 1024;
    c6.s[2] = Wq; c6.d[2] = wqh; c6.nblk[2] = (512 * 512) / 1024;
    c6.s[3] = Wk; c6.d[3] = wkh; c6.nblk[3] = (512 * 512) / 1024;
    c6.s[4] = Wv; c6.d[4] = wvh; c6.nblk[4] = (512 * 512) / 1024;
    c6.s[5] = Wo; c6.d[5] = woh; c6.nblk[5] = (512 * 512) / 1024;
    conv6<<<dim3(512, 1, 6), 256>>>(c6);

    QKVp qp;
    qp.w[0] = wqh; qp.w[1] = wkh; qp.w[2] = wvh;
    qp.b[0] = bq;  qp.b[1] = bk;  qp.b[2] = bv;
    qp.q = q; qp.k = k; qp.vt = vt;

    dim3 blk(128);
    gemm_f16<1, 1><<<dim3(1024 / 128, TOK / 64), blk>>>(xh, w1h, b1, h1, TOK, 1024, DMODEL);
    gemm_f16<0, 1><<<dim3(DMODEL / 128, TOK / 64), blk>>>(h1, w2h, b2, xm, TOK, DMODEL, 1024);
    gemm_qkv<<<dim3(1536 / 128, TOK / 64), blk>>>(xm, qp, TOK, DMODEL);
    attn_f16<<<dim3(SQ / QTILE, 4 * NHEADS), dim3(256), attn_smem>>>(q, k, vt, o);
    gemm_f16<0, 0><<<dim3(DMODEL / 128, TOK / 64), blk>>>(o, woh, bo, out, TOK, DMODEL, DMODEL);
}

// round 11
// speedup vs baseline: 2.2197x; 1.0125x over previous
#include <cuda_runtime.h>
#include <cuda_fp16.h>
#include <cstdint>

#define TOK    8192
#define DMODEL 512
#define SQ     2048
#define NHEADS 8
#define HDIM   64
#define WIN    5

// ---------------------------------------------------------------------------
// Device scratch (half). Weights in [K][N] layout.
// ---------------------------------------------------------------------------
__device__ __half g_xh[(size_t)TOK * DMODEL];
__device__ __half g_h1[(size_t)TOK * 1024];
__device__ __half g_xm[(size_t)TOK * DMODEL];
__device__ __half g_q [(size_t)TOK * DMODEL];
__device__ __half g_k [(size_t)TOK * DMODEL];
__device__ __half g_vt[(size_t)4 * NHEADS * HDIM * SQ];  // [b*8+h][d][s]
__device__ __half g_o [(size_t)TOK * DMODEL];
__device__ __half g_w1h[(size_t)512 * 1024];
__device__ __half g_w2h[(size_t)1024 * 512];
__device__ __half g_wqh[(size_t)512 * 512];
__device__ __half g_wkh[(size_t)512 * 512];
__device__ __half g_wvh[(size_t)512 * 512];
__device__ __half g_woh[(size_t)512 * 512];

// ---------------------------------------------------------------------------
// helpers
// ---------------------------------------------------------------------------
__device__ __forceinline__ uint32_t smem_u32(const void* p) {
    uint32_t a;
    asm("{ .reg .u64 t; cvta.to.shared.u64 t, %1; cvt.u32.u64 %0, t; }"
        : "=r"(a) : "l"(p));
    return a;
}

#define CP_ASYNC16(dst_u32, src_ptr) \
    asm volatile("cp.async.cg.shared.global [%0], [%1], 16;" \
                 :: "r"(dst_u32), "l"(src_ptr) : "memory")
#define CP_COMMIT() asm volatile("cp.async.commit_group;" ::: "memory")
#define CP_WAIT(n)  asm volatile("cp.async.wait_group %0;" :: "n"(n) : "memory")

__device__ __forceinline__ void mma_f16(
    float& d0, float& d1, float& d2, float& d3,
    unsigned a0, unsigned a1, unsigned a2, unsigned a3,
    unsigned b0, unsigned b1)
{
    asm volatile(
        "mma.sync.aligned.m16n8k16.row.col.f32.f16.f16.f32 "
        "{%0,%1,%2,%3},{%4,%5,%6,%7},{%8,%9},{%0,%1,%2,%3};\n"
        : "+f"(d0), "+f"(d1), "+f"(d2), "+f"(d3)
        : "r"(a0), "r"(a1), "r"(a2), "r"(a3), "r"(b0), "r"(b1));
}

__device__ __forceinline__ void ldm_x4(
    unsigned& r0, unsigned& r1, unsigned& r2, unsigned& r3, uint32_t addr)
{
    asm volatile("ldmatrix.sync.aligned.m8n8.x4.shared.b16 {%0,%1,%2,%3}, [%4];"
        : "=r"(r0), "=r"(r1), "=r"(r2), "=r"(r3) : "r"(addr));
}

__device__ __forceinline__ void ldm_x4_t(
    unsigned& r0, unsigned& r1, unsigned& r2, unsigned& r3, uint32_t addr)
{
    asm volatile("ldmatrix.sync.aligned.m8n8.x4.trans.shared.b16 {%0,%1,%2,%3}, [%4];"
        : "=r"(r0), "=r"(r1), "=r"(r2), "=r"(r3) : "r"(addr));
}

__device__ __forceinline__ unsigned h2u(__half2 h) {
    return *(unsigned*)&h;
}

// ---------------------------------------------------------------------------
// Fused prep: fp32 -> half for x + 6 weights in ONE launch.
// Flat float4 index space with segment lookup.
// ---------------------------------------------------------------------------
struct Prep {
    const float* src[7];
    __half* dst[7];
    unsigned cum[8];   // cumulative float4 counts
};

__global__ __launch_bounds__(256) void prep_all(Prep p)
{
    const unsigned i = blockIdx.x * 256 + threadIdx.x;   // float4 index
    if (i >= p.cum[7]) return;
    int s = 0;
#pragma unroll
    for (int j = 1; j < 7; j++) s += (i >= p.cum[j]) ? 1 : 0;
    const unsigned off = i - p.cum[s];
    float4 v = ((const float4*)p.src[s])[off];
    __half2* d = (__half2*)(p.dst[s] + (size_t)off * 4);
    d[0] = __floats2half2_rn(v.x, v.y);
    d[1] = __floats2half2_rn(v.z, v.w);
}

// ---------------------------------------------------------------------------
// FP16 GEMM: C[M,N] = act(A[M,K] @ W[K,N] + bias)
// BM=64, BN=128, BK=32; 128 threads = 4 warps (2x2), warp tile 32x64.
// ldmatrix feeds, 3-stage cp.async pipeline. OMODE: 0=float out, 1=half out.
// ---------------------------------------------------------------------------
#define AP  40
#define BPH 136

template<int RELU, int OMODE>
__global__ __launch_bounds__(128) void gemm_f16(
    const __half* __restrict__ A, const __half* __restrict__ W,
    const float* __restrict__ bias, void* __restrict__ Cv,
    int M, int N, int K)
{
    __shared__ __half As[3][64][AP];
    __shared__ __half Bs[3][32][BPH];

    const int tid  = threadIdx.x;
    const int warp = tid >> 5;
    const int lane = tid & 31;
    const int g    = lane >> 2;
    const int tg   = lane & 3;
    const int wm   = warp >> 1;
    const int wn   = warp & 1;
    const int m0   = blockIdx.y * 64;
    const int n0   = blockIdx.x * 128;

    const uint32_t aBase = smem_u32(&As[0][0][0]);
    const uint32_t bBase = smem_u32(&Bs[0][0][0]);
    const uint32_t aStride = 64 * AP * 2;
    const uint32_t bStride = 32 * BPH * 2;

    float acc[2][8][4];
#pragma unroll
    for (int mi = 0; mi < 2; mi++)
#pragma unroll
        for (int nj = 0; nj < 8; nj++)
#pragma unroll
            for (int r = 0; r < 4; r++) acc[mi][nj][r] = 0.f;

    const int nt = K >> 5;

    // issue one k-tile into pipeline slot
    auto issue = [&](int kt, int slot) {
        const int k0 = kt << 5;
        const uint32_t aOff = aBase + slot * aStride;
        const uint32_t bOff = bBase + slot * bStride;
#pragma unroll
        for (int t = 0; t < 2; t++) {
            const int ia = tid + t * 128;
            const int ra = ia >> 2, ca = ia & 3;
            CP_ASYNC16(aOff + (uint32_t)(ra * AP * 2 + ca * 16),
                       A + (size_t)(m0 + ra) * K + k0 + ca * 8);
        }
#pragma unroll
        for (int t = 0; t < 4; t++) {
            const int ib = tid + t * 128;
            const int rb = ib >> 4, cb = ib & 15;
            CP_ASYNC16(bOff + (uint32_t)(rb * BPH * 2 + cb * 16),
                       W + (size_t)(k0 + rb) * N + n0 + cb * 8);
        }
        CP_COMMIT();
    };

    issue(0, 0);
    issue(1, 1);

    int slot = 0;
    for (int kt = 0; kt < nt; kt++) {
        if (kt + 2 < nt) {
            issue(kt + 2, (kt + 2) % 3);
            CP_WAIT(2);
        } else {
            CP_WAIT(0);
        }
        __syncthreads();

        const uint32_t aB = aBase + slot * aStride;
        const uint32_t bB = bBase + slot * bStride;
        const int lrow = lane & 15;
        const int lcol = (lane >> 4) << 3;

#pragma unroll
        for (int ks = 0; ks < 2; ks++) {
            const int kb = ks * 16;
            unsigned a[2][4];
#pragma unroll
            for (int mi = 0; mi < 2; mi++) {
                const int row0 = wm * 32 + mi * 16;
                ldm_x4(a[mi][0], a[mi][1], a[mi][2], a[mi][3],
                       aB + (uint32_t)(((row0 + lrow) * AP + kb + lcol) * 2));
            }
            unsigned b[8][2];
#pragma unroll
            for (int njp = 0; njp < 4; njp++) {
                const int col0 = wn * 64 + njp * 16;
                ldm_x4_t(b[2 * njp][0], b[2 * njp][1],
                         b[2 * njp + 1][0], b[2 * njp + 1][1],
                         bB + (uint32_t)(((kb + lrow) * BPH + col0 + lcol) * 2));
            }
#pragma unroll
            for (int mi = 0; mi < 2; mi++)
#pragma unroll
                for (int nj = 0; nj < 8; nj++)
                    mma_f16(acc[mi][nj][0], acc[mi][nj][1],
                            acc[mi][nj][2], acc[mi][nj][3],
                            a[mi][0], a[mi][1], a[mi][2], a[mi][3],
                            b[nj][0], b[nj][1]);
        }
        __syncthreads();
        slot = (slot + 1) % 3;
    }

    // Epilogue
#pragma unroll
    for (int mi = 0; mi < 2; mi++) {
        const int row = m0 + wm * 32 + mi * 16 + g;
#pragma unroll
        for (int nj = 0; nj < 8; nj++) {
            const int col = n0 + wn * 64 + nj * 8 + tg * 2;
            float2 bv = *(const float2*)(bias + col);
            float c0x = acc[mi][nj][0] + bv.x;
            float c0y = acc[mi][nj][1] + bv.y;
            float c1x = acc[mi][nj][2] + bv.x;
            float c1y = acc[mi][nj][3] + bv.y;
            if (RELU) {
                c0x = fmaxf(c0x, 0.f); c0y = fmaxf(c0y, 0.f);
                c1x = fmaxf(c1x, 0.f); c1y = fmaxf(c1y, 0.f);
            }
            if (OMODE == 0) {
                float* C = (float*)Cv;
                float2 u; u.x = c0x; u.y = c0y;
                float2 w; w.x = c1x; w.y = c1y;
                *(float2*)(C + (size_t)row * N + col)       = u;
                *(float2*)(C + (size_t)(row + 8) * N + col) = w;
            } else {
                __half* C = (__half*)Cv;
                *(__half2*)(C + (size_t)row * N + col)       = __floats2half2_rn(c0x, c0y);
                *(__half2*)(C + (size_t)(row + 8) * N + col) = __floats2half2_rn(c1x, c1y);
            }
        }
    }
}

// ---------------------------------------------------------------------------
// Fused QKV GEMM (BM=64, 3-stage): N=1536, regions q/k/vt.
// ---------------------------------------------------------------------------
struct QKVp {
    const __half* w[3];
    const float*  b[3];
    __half* q; __half* k; __half* vt;
};

__global__ __launch_bounds__(128) void gemm_qkv(
    const __half* __restrict__ A, QKVp p, int M, int K)
{
    __shared__ __half As[3][64][AP];
    __shared__ __half Bs[3][32][BPH];

    const int tid  = threadIdx.x;
    const int warp = tid >> 5;
    const int lane = tid & 31;
    const int g    = lane >> 2;
    const int tg   = lane & 3;
    const int wm   = warp >> 1;
    const int wn   = warp & 1;
    const int m0   = blockIdx.y * 64;
    const int n0g  = blockIdx.x * 128;
    const int reg  = n0g >> 9;
    const int n0   = n0g & 511;
    const __half* W = p.w[reg];
    const float* bias = p.b[reg];

    const uint32_t aBase = smem_u32(&As[0][0][0]);
    const uint32_t bBase = smem_u32(&Bs[0][0][0]);
    const uint32_t aStride = 64 * AP * 2;
    const uint32_t bStride = 32 * BPH * 2;

    float acc[2][8][4];
#pragma unroll
    for (int mi = 0; mi < 2; mi++)
#pragma unroll
        for (int nj = 0; nj < 8; nj++)
#pragma unroll
            for (int r = 0; r < 4; r++) acc[mi][nj][r] = 0.f;

    const int nt = K >> 5;

    auto issue = [&](int kt, int slot) {
        const int k0 = kt << 5;
        const uint32_t aOff = aBase + slot * aStride;
        const uint32_t bOff = bBase + slot * bStride;
#pragma unroll
        for (int t = 0; t < 2; t++) {
            const int ia = tid + t * 128;
            const int ra = ia >> 2, ca = ia & 3;
            CP_ASYNC16(aOff + (uint32_t)(ra * AP * 2 + ca * 16),
                       A + (size_t)(m0 + ra) * K + k0 + ca * 8);
        }
#pragma unroll
        for (int t = 0; t < 4; t++) {
            const int ib = tid + t * 128;
            const int rb = ib >> 4, cb = ib & 15;
            CP_ASYNC16(bOff + (uint32_t)(rb * BPH * 2 + cb * 16),
                       W + (size_t)(k0 + rb) * 512 + n0 + cb * 8);
        }
        CP_COMMIT();
    };

    issue(0, 0);
    issue(1, 1);

    int slot = 0;
    for (int kt = 0; kt < nt; kt++) {
        if (kt + 2 < nt) {
            issue(kt + 2, (kt + 2) % 3);
            CP_WAIT(2);
        } else {
            CP_WAIT(0);
        }
        __syncthreads();

        const uint32_t aB = aBase + slot * aStride;
        const uint32_t bB = bBase + slot * bStride;
        const int lrow = lane & 15;
        const int lcol = (lane >> 4) << 3;

#pragma unroll
        for (int ks = 0; ks < 2; ks++) {
            const int kb = ks * 16;
            unsigned a[2][4];
#pragma unroll
            for (int mi = 0; mi < 2; mi++) {
                const int row0 = wm * 32 + mi * 16;
                ldm_x4(a[mi][0], a[mi][1], a[mi][2], a[mi][3],
                       aB + (uint32_t)(((row0 + lrow) * AP + kb + lcol) * 2));
            }
            unsigned b[8][2];
#pragma unroll
            for (int njp = 0; njp < 4; njp++) {
                const int col0 = wn * 64 + njp * 16;
                ldm_x4_t(b[2 * njp][0], b[2 * njp][1],
                         b[2 * njp + 1][0], b[2 * njp + 1][1],
                         bB + (uint32_t)(((kb + lrow) * BPH + col0 + lcol) * 2));
            }
#pragma unroll
            for (int mi = 0; mi < 2; mi++)
#pragma unroll
                for (int nj = 0; nj < 8; nj++)
                    mma_f16(acc[mi][nj][0], acc[mi][nj][1],
                            acc[mi][nj][2], acc[mi][nj][3],
                            a[mi][0], a[mi][1], a[mi][2], a[mi][3],
                            b[nj][0], b[nj][1]);
        }
        __syncthreads();
        slot = (slot + 1) % 3;
    }

#pragma unroll
    for (int mi = 0; mi < 2; mi++) {
        const int row = m0 + wm * 32 + mi * 16 + g;
#pragma unroll
        for (int nj = 0; nj < 8; nj++) {
            const int coln = n0 + wn * 64 + nj * 8 + tg * 2;
            float2 bv = *(const float2*)(bias + coln);
            const float c0x = acc[mi][nj][0] + bv.x;
            const float c0y = acc[mi][nj][1] + bv.y;
            const float c1x = acc[mi][nj][2] + bv.x;
            const float c1y = acc[mi][nj][3] + bv.y;
            if (reg == 2) {
                __half* C = p.vt;
                const int b = row >> 11, s = row & 2047;
                const int h = coln >> 6, dd = coln & 63;
                const size_t base = (((size_t)(b * 8 + h) * 64 + dd) << 11);
                C[base + s]            = __float2half_rn(c0x);
                C[base + 2048 + s]     = __float2half_rn(c0y);
                C[base + s + 8]        = __float2half_rn(c1x);
                C[base + 2048 + s + 8] = __float2half_rn(c1y);
            } else {
                __half* C = (reg == 0) ? p.q : p.k;
                *(__half2*)(C + (size_t)row * DMODEL + coln)       = __floats2half2_rn(c0x, c0y);
                *(__half2*)(C + (size_t)(row + 8) * DMODEL + coln) = __floats2half2_rn(c1x, c1y);
            }
        }
    }
}

// ---------------------------------------------------------------------------
// FP16 flash attention: QTILE=256, register-resident P, cp.async K/V pipeline.
// Q pre-scaled by 0.125*log2e -> softmax via exp2f (identical values).
// ---------------------------------------------------------------------------
#define QP_STRIDE 72
#define QTILE 256
#define KVBUF (64 * QP_STRIDE)

__global__ __launch_bounds__(256) void attn_f16(
    const __half* __restrict__ Qg, const __half* __restrict__ Kg,
    const __half* __restrict__ Vt, __half* __restrict__ Og)
{
    extern __shared__ __half smh[];
    __half (*QP)[QP_STRIDE] = (__half(*)[QP_STRIDE])smh;
    __half* KsBase = smh + QTILE * QP_STRIDE;
    __half* VsBase = KsBase + 2 * KVBUF;

    const int tid  = threadIdx.x;
    const int warp = tid >> 5;
    const int lane = tid & 31;
    const int g    = lane >> 2;
    const int tg   = lane & 3;
    const int bh   = blockIdx.y;
    const int b    = bh >> 3;
    const int h    = bh & 7;
    const int q0   = blockIdx.x * QTILE;
    const int wrow = warp * 32;

    const uint32_t qpB = smem_u32(&QP[0][0]);
    const uint32_t ksB = smem_u32(KsBase);
    const uint32_t vsB = smem_u32(VsBase);
    const int lr16 = lane & 15;
    const int lc16 = (lane >> 4) << 3;
    const int lr8  = (lane & 7) + ((lane >> 4) << 3);
    const int lc8  = ((lane >> 3) & 1) << 3;

    const __half* Qb  = Qg + (size_t)b * SQ * DMODEL + h * HDIM;
    const __half* Kb  = Kg + (size_t)b * SQ * DMODEL + h * HDIM;
    const __half* Vtb = Vt + (size_t)bh * HDIM * SQ;

    // Stage Q scaled by 0.125 * log2(e)
    const __half2 sc = __float2half2_rn(0.125f * 1.4426950408889634f);
#pragma unroll
    for (int t = 0; t < 8; t++) {
        const int idx = tid + t * 256;
        const int r = idx >> 3, c = (idx & 7) * 8;
        uint4 v = *(const uint4*)(Qb + (size_t)(q0 + r) * DMODEL + c);
        __half2* pv = (__half2*)&v;
#pragma unroll
        for (int j = 0; j < 4; j++) pv[j] = __hmul2(pv[j], sc);
        *(uint4*)&QP[r][c] = v;
    }

    // Prologue: K/V tile 0
#pragma unroll
    for (int t = 0; t < 2; t++) {
        const int idx = tid + t * 256;
        const int r = idx >> 3, c = (idx & 7) * 8;
        CP_ASYNC16(ksB + (uint32_t)((r * QP_STRIDE + c) * 2),
                   Kb + (size_t)r * DMODEL + c);
        CP_ASYNC16(vsB + (uint32_t)((r * QP_STRIDE + c) * 2),
                   Vtb + (size_t)r * SQ + c);
    }
    CP_COMMIT();
    __syncthreads();

    unsigned qf[4][2][4];
#pragma unroll
    for (int ks = 0; ks < 4; ks++) {
        const int kb = ks * 16;
#pragma unroll
        for (int mi = 0; mi < 2; mi++) {
            const int row0 = wrow + mi * 16;
            ldm_x4(qf[ks][mi][0], qf[ks][mi][1], qf[ks][mi][2], qf[ks][mi][3],
                   qpB + (uint32_t)(((row0 + lr16) * QP_STRIDE + kb + lc16) * 2));
        }
    }

    float oacc[2][8][4];
#pragma unroll
    for (int mi = 0; mi < 2; mi++)
#pragma unroll
        for (int nj = 0; nj < 8; nj++)
#pragma unroll
            for (int r = 0; r < 4; r++) oacc[mi][nj][r] = 0.f;
    float mrow[2][2], lrow[2][2];
#pragma unroll
    for (int mi = 0; mi < 2; mi++) {
        mrow[mi][0] = mrow[mi][1] = -1e30f;
        lrow[mi][0] = lrow[mi][1] = 0.f;
    }

    const int NT = SQ / 64;
    for (int kt = 0; kt < NT; kt++) {
        const int k0 = kt * 64;
        const int buf = kt & 1;

        if (kt + 1 < NT) {
            const int kn = (kt + 1) * 64;
            const uint32_t kOff = ksB + (buf ^ 1) * KVBUF * 2;
            const uint32_t vOff = vsB + (buf ^ 1) * KVBUF * 2;
#pragma unroll
            for (int t = 0; t < 2; t++) {
                const int idx = tid + t * 256;
                const int r = idx >> 3, c = (idx & 7) * 8;
                CP_ASYNC16(kOff + (uint32_t)((r * QP_STRIDE + c) * 2),
                           Kb + (size_t)(kn + r) * DMODEL + c);
                CP_ASYNC16(vOff + (uint32_t)((r * QP_STRIDE + c) * 2),
                           Vtb + (size_t)r * SQ + kn + c);
            }
            CP_COMMIT();
            CP_WAIT(1);
        } else {
            CP_WAIT(0);
        }
        __syncthreads();

        const uint32_t kB = ksB + buf * KVBUF * 2;
        const uint32_t vB = vsB + buf * KVBUF * 2;

        // S = Q @ K^T  (log2-domain scores)
        float sfrag[2][8][4];
#pragma unroll
        for (int mi = 0; mi < 2; mi++)
#pragma unroll
            for (int nj = 0; nj < 8; nj++)
#pragma unroll
                for (int r = 0; r < 4; r++) sfrag[mi][nj][r] = 0.f;

#pragma unroll
        for (int ks = 0; ks < 4; ks++) {
            const int kb = ks * 16;
            unsigned bq[8][2];
#pragma unroll
            for (int njp = 0; njp < 4; njp++) {
                ldm_x4(bq[2 * njp][0], bq[2 * njp][1],
                       bq[2 * njp + 1][0], bq[2 * njp + 1][1],
                       kB + (uint32_t)(((njp * 16 + lr8) * QP_STRIDE + kb + lc8) * 2));
            }
#pragma unroll
            for (int mi = 0; mi < 2; mi++)
#pragma unroll
                for (int nj = 0; nj < 8; nj++)
                    mma_f16(sfrag[mi][nj][0], sfrag[mi][nj][1],
                            sfrag[mi][nj][2], sfrag[mi][nj][3],
                            qf[ks][mi][0], qf[ks][mi][1],
                            qf[ks][mi][2], qf[ks][mi][3],
                            bq[nj][0], bq[nj][1]);
        }

        // Inverse-band mask
        const bool need_mask = (k0 <= q0 + QTILE - 1 + WIN) && (k0 + 63 >= q0 - WIN);
        if (need_mask) {
#pragma unroll
            for (int mi = 0; mi < 2; mi++) {
                const int qr0 = q0 + wrow + mi * 16 + g;
                const int qr1 = qr0 + 8;
#pragma unroll
                for (int nj = 0; nj < 8; nj++) {
                    const int kc0 = k0 + nj * 8 + tg * 2;
                    if ((unsigned)(qr0 - kc0     + WIN) <= 2 * WIN) sfrag[mi][nj][0] = -1e9f;
                    if ((unsigned)(qr0 - kc0 - 1 + WIN) <= 2 * WIN) sfrag[mi][nj][1] = -1e9f;
                    if ((unsigned)(qr1 - kc0     + WIN) <= 2 * WIN) sfrag[mi][nj][2] = -1e9f;
                    if ((unsigned)(qr1 - kc0 - 1 + WIN) <= 2 * WIN) sfrag[mi][nj][3] = -1e9f;
                }
            }
        }

        // Online softmax (exp2 domain); P packed into register A-fragments
        unsigned pf[2][8][2];
#pragma unroll
        for (int mi = 0; mi < 2; mi++) {
            float tmax0 = -1e30f, tmax1 = -1e30f;
#pragma unroll
            for (int nj = 0; nj < 8; nj++) {
                tmax0 = fmaxf(tmax0, fmaxf(sfrag[mi][nj][0], sfrag[mi][nj][1]));
                tmax1 = fmaxf(tmax1, fmaxf(sfrag[mi][nj][2], sfrag[mi][nj][3]));
            }
#pragma unroll
            for (int off = 1; off <= 2; off <<= 1) {
                tmax0 = fmaxf(tmax0, __shfl_xor_sync(0xffffffffu, tmax0, off));
                tmax1 = fmaxf(tmax1, __shfl_xor_sync(0xffffffffu, tmax1, off));
            }
            const float mnew0 = fmaxf(mrow[mi][0], tmax0);
            const float mnew1 = fmaxf(mrow[mi][1], tmax1);
            const float alpha0 = exp2f(mrow[mi][0] - mnew0);
            const float alpha1 = exp2f(mrow[mi][1] - mnew1);

            float rs0 = 0.f, rs1 = 0.f;
#pragma unroll
            for (int nj = 0; nj < 8; nj++) {
                const float p0 = exp2f(sfrag[mi][nj][0] - mnew0);
                const float p1 = exp2f(sfrag[mi][nj][1] - mnew0);
                const float p2 = exp2f(sfrag[mi][nj][2] - mnew1);
                const float p3 = exp2f(sfrag[mi][nj][3] - mnew1);
                rs0 += p0 + p1;
                rs1 += p2 + p3;
                pf[mi][nj][0] = h2u(__floats2half2_rn(p0, p1));
                pf[mi][nj][1] = h2u(__floats2half2_rn(p2, p3));
            }
#pragma unroll
            for (int off = 1; off <= 2; off <<= 1) {
                rs0 += __shfl_xor_sync(0xffffffffu, rs0, off);
                rs1 += __shfl_xor_sync(0xffffffffu, rs1, off);
            }
            lrow[mi][0] = lrow[mi][0] * alpha0 + rs0;
            lrow[mi][1] = lrow[mi][1] * alpha1 + rs1;
            mrow[mi][0] = mnew0;
            mrow[mi][1] = mnew1;
#pragma unroll
            for (int nj = 0; nj < 8; nj++) {
                oacc[mi][nj][0] *= alpha0; oacc[mi][nj][1] *= alpha0;
                oacc[mi][nj][2] *= alpha1; oacc[mi][nj][3] *= alpha1;
            }
        }

        // O += P @ V
#pragma unroll
        for (int ks = 0; ks < 4; ks++) {
            const int kb = ks * 16;
            unsigned bv[8][2];
#pragma unroll
            for (int njp = 0; njp < 4; njp++) {
                ldm_x4(bv[2 * njp][0], bv[2 * njp][1],
                       bv[2 * njp + 1][0], bv[2 * njp + 1][1],
                       vB + (uint32_t)(((njp * 16 + lr8) * QP_STRIDE + kb + lc8) * 2));
            }
#pragma unroll
            for (int mi = 0; mi < 2; mi++) {
                const unsigned a0 = pf[mi][2 * ks][0];
                const unsigned a1 = pf[mi][2 * ks][1];
                const unsigned a2 = pf[mi][2 * ks + 1][0];
                const unsigned a3 = pf[mi][2 * ks + 1][1];
#pragma unroll
                for (int nj = 0; nj < 8; nj++)
                    mma_f16(oacc[mi][nj][0], oacc[mi][nj][1],
                            oacc[mi][nj][2], oacc[mi][nj][3],
                            a0, a1, a2, a3, bv[nj][0], bv[nj][1]);
            }
        }
        __syncthreads();
    }

    // Finalize
    __half* Ob = Og + (size_t)b * SQ * DMODEL + h * HDIM;
#pragma unroll
    for (int mi = 0; mi < 2; mi++) {
        const float inv0 = 1.0f / lrow[mi][0];
        const float inv1 = 1.0f / lrow[mi][1];
        const int row0 = q0 + wrow + mi * 16 + g;
#pragma unroll
        for (int nj = 0; nj < 8; nj++) {
            const int col = nj * 8 + tg * 2;
            *(__half2*)(Ob + (size_t)row0 * DMODEL + col) =
                __floats2half2_rn(oacc[mi][nj][0] * inv0, oacc[mi][nj][1] * inv0);
            *(__half2*)(Ob + (size_t)(row0 + 8) * DMODEL + col) =
                __floats2half2_rn(oacc[mi][nj][2] * inv1, oacc[mi][nj][3] * inv1);
        }
    }
}

// ---------------------------------------------------------------------------
// Launch
// ---------------------------------------------------------------------------
extern "C" void kernel_launch(void* const* d_in, const int* in_sizes, int n_in,
                              void* d_out, int out_size)
{
    (void)in_sizes; (void)n_in; (void)out_size;

    const float* x  = (const float*)d_in[0];
    const float* W1 = (const float*)d_in[1];
    const float* b1 = (const float*)d_in[2];
    const float* W2 = (const float*)d_in[3];
    const float* b2 = (const float*)d_in[4];
    const float* Wq = (const float*)d_in[5];
    const float* bq = (const float*)d_in[6];
    const float* Wk = (const float*)d_in[7];
    const float* bk = (const float*)d_in[8];
    const float* Wv = (const float*)d_in[9];
    const float* bv = (const float*)d_in[10];
    const float* Wo = (const float*)d_in[11];
    const float* bo = (const float*)d_in[12];
    float* out = (float*)d_out;

    __half *xh, *h1, *xm, *q, *k, *vt, *o;
    __half *w1h, *w2h, *wqh, *wkh, *wvh, *woh;
    cudaGetSymbolAddress((void**)&xh, g_xh);
    cudaGetSymbolAddress((void**)&h1, g_h1);
    cudaGetSymbolAddress((void**)&xm, g_xm);
    cudaGetSymbolAddress((void**)&q,  g_q);
    cudaGetSymbolAddress((void**)&k,  g_k);
    cudaGetSymbolAddress((void**)&vt, g_vt);
    cudaGetSymbolAddress((void**)&o,  g_o);
    cudaGetSymbolAddress((void**)&w1h, g_w1h);
    cudaGetSymbolAddress((void**)&w2h, g_w2h);
    cudaGetSymbolAddress((void**)&wqh, g_wqh);
    cudaGetSymbolAddress((void**)&wkh, g_wkh);
    cudaGetSymbolAddress((void**)&wvh, g_wvh);
    cudaGetSymbolAddress((void**)&woh, g_woh);

    const int attn_smem = (QTILE * QP_STRIDE + 4 * KVBUF) * (int)sizeof(__half);
    cudaFuncSetAttribute(attn_f16, cudaFuncAttributeMaxDynamicSharedMemorySize,
                         attn_smem);

    // Fused prep: x + 6 weights, one launch. Counts in float4 units.
    Prep pr;
    pr.src[0] = x;  pr.dst[0] = xh;
    pr.src[1] = W1; pr.dst[1] = w1h;
    pr.src[2] = W2; pr.dst[2] = w2h;
    pr.src[3] = Wq; pr.dst[3] = wqh;
    pr.src[4] = Wk; pr.dst[4] = wkh;
    pr.src[5] = Wv; pr.dst[5] = wvh;
    pr.src[6] = Wo; pr.dst[6] = woh;
    const unsigned cnt[7] = {
        (TOK * DMODEL) / 4, (512 * 1024) / 4, (1024 * 512) / 4,
        (512 * 512) / 4, (512 * 512) / 4, (512 * 512) / 4, (512 * 512) / 4 };
    unsigned acc = 0;
    for (int i = 0; i < 7; i++) { pr.cum[i] = acc; acc += cnt[i]; }
    pr.cum[7] = acc;
    prep_all<<<(acc + 255) / 256, 256>>>(pr);

    QKVp qp;
    qp.w[0] = wqh; qp.w[1] = wkh; qp.w[2] = wvh;
    qp.b[0] = bq;  qp.b[1] = bk;  qp.b[2] = bv;
    qp.q = q; qp.k = k; qp.vt = vt;

    dim3 blk(128);
    gemm_f16<1, 1><<<dim3(1024 / 128, TOK / 64), blk>>>(xh, w1h, b1, h1, TOK, 1024, DMODEL);
    gemm_f16<0, 1><<<dim3(DMODEL / 128, TOK / 64), blk>>>(h1, w2h, b2, xm, TOK, DMODEL, 1024);
    gemm_qkv<<<dim3(1536 / 128, TOK / 64), blk>>>(xm, qp, TOK, DMODEL);
    attn_f16<<<dim3(SQ / QTILE, 4 * NHEADS), dim3(256), attn_smem>>>(q, k, vt, o);
    gemm_f16<0, 0><<<dim3(DMODEL / 128, TOK / 64), blk>>>(o, woh, bo, out, TOK, DMODEL, DMODEL);
}

// round 12
// speedup vs baseline: 2.2894x; 1.0314x over previous
#include <cuda_runtime.h>
#include <cuda_fp16.h>
#include <cstdint>

#define TOK    8192
#define DMODEL 512
#define SQ     2048
#define NHEADS 8
#define HDIM   64
#define WIN    5

// ---------------------------------------------------------------------------
// Device scratch (half). Weights in [K][N] layout.
// ---------------------------------------------------------------------------
__device__ __half g_xh[(size_t)TOK * DMODEL];
__device__ __half g_h1[(size_t)TOK * 1024];
__device__ __half g_xm[(size_t)TOK * DMODEL];
__device__ __half g_q [(size_t)TOK * DMODEL];
__device__ __half g_k [(size_t)TOK * DMODEL];
__device__ __half g_vt[(size_t)4 * NHEADS * HDIM * SQ];  // [b*8+h][d][s]
__device__ __half g_o [(size_t)TOK * DMODEL];
__device__ __half g_w1h[(size_t)512 * 1024];
__device__ __half g_w2h[(size_t)1024 * 512];
__device__ __half g_wqh[(size_t)512 * 512];
__device__ __half g_wkh[(size_t)512 * 512];
__device__ __half g_wvh[(size_t)512 * 512];
__device__ __half g_woh[(size_t)512 * 512];

// ---------------------------------------------------------------------------
// helpers
// ---------------------------------------------------------------------------
__device__ __forceinline__ uint32_t smem_u32(const void* p) {
    uint32_t a;
    asm("{ .reg .u64 t; cvta.to.shared.u64 t, %1; cvt.u32.u64 %0, t; }"
        : "=r"(a) : "l"(p));
    return a;
}

#define CP_ASYNC16(dst_u32, src_ptr) \
    asm volatile("cp.async.cg.shared.global [%0], [%1], 16;" \
                 :: "r"(dst_u32), "l"(src_ptr) : "memory")
#define CP_COMMIT() asm volatile("cp.async.commit_group;" ::: "memory")
#define CP_WAIT(n)  asm volatile("cp.async.wait_group %0;" :: "n"(n) : "memory")

__device__ __forceinline__ void mma_f16(
    float& d0, float& d1, float& d2, float& d3,
    unsigned a0, unsigned a1, unsigned a2, unsigned a3,
    unsigned b0, unsigned b1)
{
    asm volatile(
        "mma.sync.aligned.m16n8k16.row.col.f32.f16.f16.f32 "
        "{%0,%1,%2,%3},{%4,%5,%6,%7},{%8,%9},{%0,%1,%2,%3};\n"
        : "+f"(d0), "+f"(d1), "+f"(d2), "+f"(d3)
        : "r"(a0), "r"(a1), "r"(a2), "r"(a3), "r"(b0), "r"(b1));
}

__device__ __forceinline__ void ldm_x4(
    unsigned& r0, unsigned& r1, unsigned& r2, unsigned& r3, uint32_t addr)
{
    asm volatile("ldmatrix.sync.aligned.m8n8.x4.shared.b16 {%0,%1,%2,%3}, [%4];"
        : "=r"(r0), "=r"(r1), "=r"(r2), "=r"(r3) : "r"(addr));
}

__device__ __forceinline__ void ldm_x4_t(
    unsigned& r0, unsigned& r1, unsigned& r2, unsigned& r3, uint32_t addr)
{
    asm volatile("ldmatrix.sync.aligned.m8n8.x4.trans.shared.b16 {%0,%1,%2,%3}, [%4];"
        : "=r"(r0), "=r"(r1), "=r"(r2), "=r"(r3) : "r"(addr));
}

__device__ __forceinline__ unsigned h2u(__half2 h) {
    return *(unsigned*)&h;
}

// ---------------------------------------------------------------------------
// Fused prep: fp32 -> half for x + 6 weights in ONE launch.
// ---------------------------------------------------------------------------
struct Prep {
    const float* src[7];
    __half* dst[7];
    unsigned cum[8];
};

__global__ __launch_bounds__(256) void prep_all(Prep p)
{
    const unsigned i = blockIdx.x * 256 + threadIdx.x;
    if (i >= p.cum[7]) return;
    int s = 0;
#pragma unroll
    for (int j = 1; j < 7; j++) s += (i >= p.cum[j]) ? 1 : 0;
    const unsigned off = i - p.cum[s];
    float4 v = ((const float4*)p.src[s])[off];
    __half2* d = (__half2*)(p.dst[s] + (size_t)off * 4);
    d[0] = __floats2half2_rn(v.x, v.y);
    d[1] = __floats2half2_rn(v.z, v.w);
}

// ---------------------------------------------------------------------------
// FP16 GEMM: C[M,N] = act(A[M,K] @ W[K,N] + bias)
// BM=64, BN=128, BK=64; 128 threads = 4 warps (2x2), warp tile 32x64.
// 2-stage cp.async, ONE barrier per k-iteration (wait->sync->issue->compute).
// Dynamic smem: As[2][64][72] + Bs[2][64][136].
// ---------------------------------------------------------------------------
#define AP2 72     // A row stride in halves (64+8)
#define BPH 136    // B row stride in halves (128+8)
#define A_ST (64 * AP2 * 2)          // bytes per A stage = 9216
#define B_ST (64 * BPH * 2)          // bytes per B stage = 17408
#define GSMEM (2 * (A_ST + B_ST))    // 53248

template<int RELU, int OMODE>
__global__ void __launch_bounds__(128, 4) gemm_f16(
    const __half* __restrict__ A, const __half* __restrict__ W,
    const float* __restrict__ bias, void* __restrict__ Cv,
    int M, int N, int K)
{
    extern __shared__ __half smg[];
    const uint32_t aBase = smem_u32(smg);
    const uint32_t bBase = aBase + 2 * A_ST;

    const int tid  = threadIdx.x;
    const int warp = tid >> 5;
    const int lane = tid & 31;
    const int g    = lane >> 2;
    const int tg   = lane & 3;
    const int wm   = warp >> 1;
    const int wn   = warp & 1;
    const int m0   = blockIdx.y * 64;
    const int n0   = blockIdx.x * 128;

    float acc[2][8][4];
#pragma unroll
    for (int mi = 0; mi < 2; mi++)
#pragma unroll
        for (int nj = 0; nj < 8; nj++)
#pragma unroll
            for (int r = 0; r < 4; r++) acc[mi][nj][r] = 0.f;

    const int nt = K >> 6;

    auto issue = [&](int kt, int slot) {
        const int k0 = kt << 6;
        const uint32_t aOff = aBase + slot * A_ST;
        const uint32_t bOff = bBase + slot * B_ST;
#pragma unroll
        for (int t = 0; t < 4; t++) {          // A: 64 rows x 8 chunks
            const int ia = tid + t * 128;
            const int ra = ia >> 3, ca = ia & 7;
            CP_ASYNC16(aOff + (uint32_t)(ra * AP2 * 2 + ca * 16),
                       A + (size_t)(m0 + ra) * K + k0 + ca * 8);
        }
#pragma unroll
        for (int t = 0; t < 8; t++) {          // B: 64 rows x 16 chunks
            const int ib = tid + t * 128;
            const int rb = ib >> 4, cb = ib & 15;
            CP_ASYNC16(bOff + (uint32_t)(rb * BPH * 2 + cb * 16),
                       W + (size_t)(k0 + rb) * N + n0 + cb * 8);
        }
        CP_COMMIT();
    };

    issue(0, 0);

    for (int kt = 0; kt < nt; kt++) {
        const int slot = kt & 1;
        CP_WAIT(0);
        __syncthreads();
        if (kt + 1 < nt) issue(kt + 1, slot ^ 1);

        const uint32_t aB = aBase + slot * A_ST;
        const uint32_t bB = bBase + slot * B_ST;
        const int lrow = lane & 15;
        const int lcol = (lane >> 4) << 3;

#pragma unroll
        for (int ks = 0; ks < 4; ks++) {
            const int kb = ks * 16;
            unsigned a[2][4];
#pragma unroll
            for (int mi = 0; mi < 2; mi++) {
                const int row0 = wm * 32 + mi * 16;
                ldm_x4(a[mi][0], a[mi][1], a[mi][2], a[mi][3],
                       aB + (uint32_t)(((row0 + lrow) * AP2 + kb + lcol) * 2));
            }
            unsigned b[8][2];
#pragma unroll
            for (int njp = 0; njp < 4; njp++) {
                const int col0 = wn * 64 + njp * 16;
                ldm_x4_t(b[2 * njp][0], b[2 * njp][1],
                         b[2 * njp + 1][0], b[2 * njp + 1][1],
                         bB + (uint32_t)(((kb + lrow) * BPH + col0 + lcol) * 2));
            }
#pragma unroll
            for (int mi = 0; mi < 2; mi++)
#pragma unroll
                for (int nj = 0; nj < 8; nj++)
                    mma_f16(acc[mi][nj][0], acc[mi][nj][1],
                            acc[mi][nj][2], acc[mi][nj][3],
                            a[mi][0], a[mi][1], a[mi][2], a[mi][3],
                            b[nj][0], b[nj][1]);
        }
    }

    // Epilogue
#pragma unroll
    for (int mi = 0; mi < 2; mi++) {
        const int row = m0 + wm * 32 + mi * 16 + g;
#pragma unroll
        for (int nj = 0; nj < 8; nj++) {
            const int col = n0 + wn * 64 + nj * 8 + tg * 2;
            float2 bv = *(const float2*)(bias + col);
            float c0x = acc[mi][nj][0] + bv.x;
            float c0y = acc[mi][nj][1] + bv.y;
            float c1x = acc[mi][nj][2] + bv.x;
            float c1y = acc[mi][nj][3] + bv.y;
            if (RELU) {
                c0x = fmaxf(c0x, 0.f); c0y = fmaxf(c0y, 0.f);
                c1x = fmaxf(c1x, 0.f); c1y = fmaxf(c1y, 0.f);
            }
            if (OMODE == 0) {
                float* C = (float*)Cv;
                float2 u; u.x = c0x; u.y = c0y;
                float2 w; w.x = c1x; w.y = c1y;
                *(float2*)(C + (size_t)row * N + col)       = u;
                *(float2*)(C + (size_t)(row + 8) * N + col) = w;
            } else {
                __half* C = (__half*)Cv;
                *(__half2*)(C + (size_t)row * N + col)       = __floats2half2_rn(c0x, c0y);
                *(__half2*)(C + (size_t)(row + 8) * N + col) = __floats2half2_rn(c1x, c1y);
            }
        }
    }
}

// ---------------------------------------------------------------------------
// Fused QKV GEMM (BM=64, BK=64, 2-stage single-barrier): N=1536 regions.
// ---------------------------------------------------------------------------
struct QKVp {
    const __half* w[3];
    const float*  b[3];
    __half* q; __half* k; __half* vt;
};

__global__ void __launch_bounds__(128, 4) gemm_qkv(
    const __half* __restrict__ A, QKVp p, int M, int K)
{
    extern __shared__ __half smg[];
    const uint32_t aBase = smem_u32(smg);
    const uint32_t bBase = aBase + 2 * A_ST;

    const int tid  = threadIdx.x;
    const int warp = tid >> 5;
    const int lane = tid & 31;
    const int g    = lane >> 2;
    const int tg   = lane & 3;
    const int wm   = warp >> 1;
    const int wn   = warp & 1;
    const int m0   = blockIdx.y * 64;
    const int n0g  = blockIdx.x * 128;
    const int reg  = n0g >> 9;
    const int n0   = n0g & 511;
    const __half* W = p.w[reg];
    const float* bias = p.b[reg];

    float acc[2][8][4];
#pragma unroll
    for (int mi = 0; mi < 2; mi++)
#pragma unroll
        for (int nj = 0; nj < 8; nj++)
#pragma unroll
            for (int r = 0; r < 4; r++) acc[mi][nj][r] = 0.f;

    const int nt = K >> 6;

    auto issue = [&](int kt, int slot) {
        const int k0 = kt << 6;
        const uint32_t aOff = aBase + slot * A_ST;
        const uint32_t bOff = bBase + slot * B_ST;
#pragma unroll
        for (int t = 0; t < 4; t++) {
            const int ia = tid + t * 128;
            const int ra = ia >> 3, ca = ia & 7;
            CP_ASYNC16(aOff + (uint32_t)(ra * AP2 * 2 + ca * 16),
                       A + (size_t)(m0 + ra) * K + k0 + ca * 8);
        }
#pragma unroll
        for (int t = 0; t < 8; t++) {
            const int ib = tid + t * 128;
            const int rb = ib >> 4, cb = ib & 15;
            CP_ASYNC16(bOff + (uint32_t)(rb * BPH * 2 + cb * 16),
                       W + (size_t)(k0 + rb) * 512 + n0 + cb * 8);
        }
        CP_COMMIT();
    };

    issue(0, 0);

    for (int kt = 0; kt < nt; kt++) {
        const int slot = kt & 1;
        CP_WAIT(0);
        __syncthreads();
        if (kt + 1 < nt) issue(kt + 1, slot ^ 1);

        const uint32_t aB = aBase + slot * A_ST;
        const uint32_t bB = bBase + slot * B_ST;
        const int lrow = lane & 15;
        const int lcol = (lane >> 4) << 3;

#pragma unroll
        for (int ks = 0; ks < 4; ks++) {
            const int kb = ks * 16;
            unsigned a[2][4];
#pragma unroll
            for (int mi = 0; mi < 2; mi++) {
                const int row0 = wm * 32 + mi * 16;
                ldm_x4(a[mi][0], a[mi][1], a[mi][2], a[mi][3],
                       aB + (uint32_t)(((row0 + lrow) * AP2 + kb + lcol) * 2));
            }
            unsigned b[8][2];
#pragma unroll
            for (int njp = 0; njp < 4; njp++) {
                const int col0 = wn * 64 + njp * 16;
                ldm_x4_t(b[2 * njp][0], b[2 * njp][1],
                         b[2 * njp + 1][0], b[2 * njp + 1][1],
                         bB + (uint32_t)(((kb + lrow) * BPH + col0 + lcol) * 2));
            }
#pragma unroll
            for (int mi = 0; mi < 2; mi++)
#pragma unroll
                for (int nj = 0; nj < 8; nj++)
                    mma_f16(acc[mi][nj][0], acc[mi][nj][1],
                            acc[mi][nj][2], acc[mi][nj][3],
                            a[mi][0], a[mi][1], a[mi][2], a[mi][3],
                            b[nj][0], b[nj][1]);
        }
    }

#pragma unroll
    for (int mi = 0; mi < 2; mi++) {
        const int row = m0 + wm * 32 + mi * 16 + g;
#pragma unroll
        for (int nj = 0; nj < 8; nj++) {
            const int coln = n0 + wn * 64 + nj * 8 + tg * 2;
            float2 bv = *(const float2*)(bias + coln);
            const float c0x = acc[mi][nj][0] + bv.x;
            const float c0y = acc[mi][nj][1] + bv.y;
            const float c1x = acc[mi][nj][2] + bv.x;
            const float c1y = acc[mi][nj][3] + bv.y;
            if (reg == 2) {
                __half* C = p.vt;
                const int b = row >> 11, s = row & 2047;
                const int h = coln >> 6, dd = coln & 63;
                const size_t base = (((size_t)(b * 8 + h) * 64 + dd) << 11);
                C[base + s]            = __float2half_rn(c0x);
                C[base + 2048 + s]     = __float2half_rn(c0y);
                C[base + s + 8]        = __float2half_rn(c1x);
                C[base + 2048 + s + 8] = __float2half_rn(c1y);
            } else {
                __half* C = (reg == 0) ? p.q : p.k;
                *(__half2*)(C + (size_t)row * DMODEL + coln)       = __floats2half2_rn(c0x, c0y);
                *(__half2*)(C + (size_t)(row + 8) * DMODEL + coln) = __floats2half2_rn(c1x, c1y);
            }
        }
    }
}

// ---------------------------------------------------------------------------
// FP16 flash attention: QTILE=256, register-resident P, cp.async pipeline,
// single barrier per kt (wait->sync->issue->compute). exp2 softmax.
// ---------------------------------------------------------------------------
#define QP_STRIDE 72
#define QTILE 256
#define KVBUF (64 * QP_STRIDE)

__global__ __launch_bounds__(256) void attn_f16(
    const __half* __restrict__ Qg, const __half* __restrict__ Kg,
    const __half* __restrict__ Vt, __half* __restrict__ Og)
{
    extern __shared__ __half smh[];
    __half (*QP)[QP_STRIDE] = (__half(*)[QP_STRIDE])smh;
    __half* KsBase = smh + QTILE * QP_STRIDE;
    __half* VsBase = KsBase + 2 * KVBUF;

    const int tid  = threadIdx.x;
    const int warp = tid >> 5;
    const int lane = tid & 31;
    const int g    = lane >> 2;
    const int tg   = lane & 3;
    const int bh   = blockIdx.y;
    const int b    = bh >> 3;
    const int h    = bh & 7;
    const int q0   = blockIdx.x * QTILE;
    const int wrow = warp * 32;

    const uint32_t qpB = smem_u32(&QP[0][0]);
    const uint32_t ksB = smem_u32(KsBase);
    const uint32_t vsB = smem_u32(VsBase);
    const int lr16 = lane & 15;
    const int lc16 = (lane >> 4) << 3;
    const int lr8  = (lane & 7) + ((lane >> 4) << 3);
    const int lc8  = ((lane >> 3) & 1) << 3;

    const __half* Qb  = Qg + (size_t)b * SQ * DMODEL + h * HDIM;
    const __half* Kb  = Kg + (size_t)b * SQ * DMODEL + h * HDIM;
    const __half* Vtb = Vt + (size_t)bh * HDIM * SQ;

    // Stage Q scaled by 0.125 * log2(e)
    const __half2 sc = __float2half2_rn(0.125f * 1.4426950408889634f);
#pragma unroll
    for (int t = 0; t < 8; t++) {
        const int idx = tid + t * 256;
        const int r = idx >> 3, c = (idx & 7) * 8;
        uint4 v = *(const uint4*)(Qb + (size_t)(q0 + r) * DMODEL + c);
        __half2* pv = (__half2*)&v;
#pragma unroll
        for (int j = 0; j < 4; j++) pv[j] = __hmul2(pv[j], sc);
        *(uint4*)&QP[r][c] = v;
    }

    // Prologue: issue K/V tile 0
#pragma unroll
    for (int t = 0; t < 2; t++) {
        const int idx = tid + t * 256;
        const int r = idx >> 3, c = (idx & 7) * 8;
        CP_ASYNC16(ksB + (uint32_t)((r * QP_STRIDE + c) * 2),
                   Kb + (size_t)r * DMODEL + c);
        CP_ASYNC16(vsB + (uint32_t)((r * QP_STRIDE + c) * 2),
                   Vtb + (size_t)r * SQ + c);
    }
    CP_COMMIT();
    __syncthreads();   // publish QP

    unsigned qf[4][2][4];
#pragma unroll
    for (int ks = 0; ks < 4; ks++) {
        const int kb = ks * 16;
#pragma unroll
        for (int mi = 0; mi < 2; mi++) {
            const int row0 = wrow + mi * 16;
            ldm_x4(qf[ks][mi][0], qf[ks][mi][1], qf[ks][mi][2], qf[ks][mi][3],
                   qpB + (uint32_t)(((row0 + lr16) * QP_STRIDE + kb + lc16) * 2));
        }
    }

    float oacc[2][8][4];
#pragma unroll
    for (int mi = 0; mi < 2; mi++)
#pragma unroll
        for (int nj = 0; nj < 8; nj++)
#pragma unroll
            for (int r = 0; r < 4; r++) oacc[mi][nj][r] = 0.f;
    float mrow[2][2], lrow[2][2];
#pragma unroll
    for (int mi = 0; mi < 2; mi++) {
        mrow[mi][0] = mrow[mi][1] = -1e30f;
        lrow[mi][0] = lrow[mi][1] = 0.f;
    }

    const int NT = SQ / 64;
    for (int kt = 0; kt < NT; kt++) {
        const int k0 = kt * 64;
        const int buf = kt & 1;

        CP_WAIT(0);
        __syncthreads();

        if (kt + 1 < NT) {
            const int kn = (kt + 1) * 64;
            const uint32_t kOff = ksB + (buf ^ 1) * KVBUF * 2;
            const uint32_t vOff = vsB + (buf ^ 1) * KVBUF * 2;
#pragma unroll
            for (int t = 0; t < 2; t++) {
                const int idx = tid + t * 256;
                const int r = idx >> 3, c = (idx & 7) * 8;
                CP_ASYNC16(kOff + (uint32_t)((r * QP_STRIDE + c) * 2),
                           Kb + (size_t)(kn + r) * DMODEL + c);
                CP_ASYNC16(vOff + (uint32_t)((r * QP_STRIDE + c) * 2),
                           Vtb + (size_t)r * SQ + kn + c);
            }
            CP_COMMIT();
        }

        const uint32_t kB = ksB + buf * KVBUF * 2;
        const uint32_t vB = vsB + buf * KVBUF * 2;

        // S = Q @ K^T  (log2-domain)
        float sfrag[2][8][4];
#pragma unroll
        for (int mi = 0; mi < 2; mi++)
#pragma unroll
            for (int nj = 0; nj < 8; nj++)
#pragma unroll
                for (int r = 0; r < 4; r++) sfrag[mi][nj][r] = 0.f;

#pragma unroll
        for (int ks = 0; ks < 4; ks++) {
            const int kb = ks * 16;
            unsigned bq[8][2];
#pragma unroll
            for (int njp = 0; njp < 4; njp++) {
                ldm_x4(bq[2 * njp][0], bq[2 * njp][1],
                       bq[2 * njp + 1][0], bq[2 * njp + 1][1],
                       kB + (uint32_t)(((njp * 16 + lr8) * QP_STRIDE + kb + lc8) * 2));
            }
#pragma unroll
            for (int mi = 0; mi < 2; mi++)
#pragma unroll
                for (int nj = 0; nj < 8; nj++)
                    mma_f16(sfrag[mi][nj][0], sfrag[mi][nj][1],
                            sfrag[mi][nj][2], sfrag[mi][nj][3],
                            qf[ks][mi][0], qf[ks][mi][1],
                            qf[ks][mi][2], qf[ks][mi][3],
                            bq[nj][0], bq[nj][1]);
        }

        // Inverse-band mask
        const bool need_mask = (k0 <= q0 + QTILE - 1 + WIN) && (k0 + 63 >= q0 - WIN);
        if (need_mask) {
#pragma unroll
            for (int mi = 0; mi < 2; mi++) {
                const int qr0 = q0 + wrow + mi * 16 + g;
                const int qr1 = qr0 + 8;
#pragma unroll
                for (int nj = 0; nj < 8; nj++) {
                    const int kc0 = k0 + nj * 8 + tg * 2;
                    if ((unsigned)(qr0 - kc0     + WIN) <= 2 * WIN) sfrag[mi][nj][0] = -1e9f;
                    if ((unsigned)(qr0 - kc0 - 1 + WIN) <= 2 * WIN) sfrag[mi][nj][1] = -1e9f;
                    if ((unsigned)(qr1 - kc0     + WIN) <= 2 * WIN) sfrag[mi][nj][2] = -1e9f;
                    if ((unsigned)(qr1 - kc0 - 1 + WIN) <= 2 * WIN) sfrag[mi][nj][3] = -1e9f;
                }
            }
        }

        // Online softmax (exp2 domain); P into register A-fragments
        unsigned pf[2][8][2];
#pragma unroll
        for (int mi = 0; mi < 2; mi++) {
            float tmax0 = -1e30f, tmax1 = -1e30f;
#pragma unroll
            for (int nj = 0; nj < 8; nj++) {
                tmax0 = fmaxf(tmax0, fmaxf(sfrag[mi][nj][0], sfrag[mi][nj][1]));
                tmax1 = fmaxf(tmax1, fmaxf(sfrag[mi][nj][2], sfrag[mi][nj][3]));
            }
#pragma unroll
            for (int off = 1; off <= 2; off <<= 1) {
                tmax0 = fmaxf(tmax0, __shfl_xor_sync(0xffffffffu, tmax0, off));
                tmax1 = fmaxf(tmax1, __shfl_xor_sync(0xffffffffu, tmax1, off));
            }
            const float mnew0 = fmaxf(mrow[mi][0], tmax0);
            const float mnew1 = fmaxf(mrow[mi][1], tmax1);
            const float alpha0 = exp2f(mrow[mi][0] - mnew0);
            const float alpha1 = exp2f(mrow[mi][1] - mnew1);

            float rs0 = 0.f, rs1 = 0.f;
#pragma unroll
            for (int nj = 0; nj < 8; nj++) {
                const float p0 = exp2f(sfrag[mi][nj][0] - mnew0);
                const float p1 = exp2f(sfrag[mi][nj][1] - mnew0);
                const float p2 = exp2f(sfrag[mi][nj][2] - mnew1);
                const float p3 = exp2f(sfrag[mi][nj][3] - mnew1);
                rs0 += p0 + p1;
                rs1 += p2 + p3;
                pf[mi][nj][0] = h2u(__floats2half2_rn(p0, p1));
                pf[mi][nj][1] = h2u(__floats2half2_rn(p2, p3));
            }
#pragma unroll
            for (int off = 1; off <= 2; off <<= 1) {
                rs0 += __shfl_xor_sync(0xffffffffu, rs0, off);
                rs1 += __shfl_xor_sync(0xffffffffu, rs1, off);
            }
            lrow[mi][0] = lrow[mi][0] * alpha0 + rs0;
            lrow[mi][1] = lrow[mi][1] * alpha1 + rs1;
            mrow[mi][0] = mnew0;
            mrow[mi][1] = mnew1;
#pragma unroll
            for (int nj = 0; nj < 8; nj++) {
                oacc[mi][nj][0] *= alpha0; oacc[mi][nj][1] *= alpha0;
                oacc[mi][nj][2] *= alpha1; oacc[mi][nj][3] *= alpha1;
            }
        }

        // O += P @ V
#pragma unroll
        for (int ks = 0; ks < 4; ks++) {
            const int kb = ks * 16;
            unsigned bv[8][2];
#pragma unroll
            for (int njp = 0; njp < 4; njp++) {
                ldm_x4(bv[2 * njp][0], bv[2 * njp][1],
                       bv[2 * njp + 1][0], bv[2 * njp + 1][1],
                       vB + (uint32_t)(((njp * 16 + lr8) * QP_STRIDE + kb + lc8) * 2));
            }
#pragma unroll
            for (int mi = 0; mi < 2; mi++) {
                const unsigned a0 = pf[mi][2 * ks][0];
                const unsigned a1 = pf[mi][2 * ks][1];
                const unsigned a2 = pf[mi][2 * ks + 1][0];
                const unsigned a3 = pf[mi][2 * ks + 1][1];
#pragma unroll
                for (int nj = 0; nj < 8; nj++)
                    mma_f16(oacc[mi][nj][0], oacc[mi][nj][1],
                            oacc[mi][nj][2], oacc[mi][nj][3],
                            a0, a1, a2, a3, bv[nj][0], bv[nj][1]);
            }
        }
    }

    // Finalize
    __half* Ob = Og + (size_t)b * SQ * DMODEL + h * HDIM;
#pragma unroll
    for (int mi = 0; mi < 2; mi++) {
        const float inv0 = 1.0f / lrow[mi][0];
        const float inv1 = 1.0f / lrow[mi][1];
        const int row0 = q0 + wrow + mi * 16 + g;
#pragma unroll
        for (int nj = 0; nj < 8; nj++) {
            const int col = nj * 8 + tg * 2;
            *(__half2*)(Ob + (size_t)row0 * DMODEL + col) =
                __floats2half2_rn(oacc[mi][nj][0] * inv0, oacc[mi][nj][1] * inv0);
            *(__half2*)(Ob + (size_t)(row0 + 8) * DMODEL + col) =
                __floats2half2_rn(oacc[mi][nj][2] * inv1, oacc[mi][nj][3] * inv1);
        }
    }
}

// ---------------------------------------------------------------------------
// Launch
// ---------------------------------------------------------------------------
extern "C" void kernel_launch(void* const* d_in, const int* in_sizes, int n_in,
                              void* d_out, int out_size)
{
    (void)in_sizes; (void)n_in; (void)out_size;

    const float* x  = (const float*)d_in[0];
    const float* W1 = (const float*)d_in[1];
    const float* b1 = (const float*)d_in[2];
    const float* W2 = (const float*)d_in[3];
    const float* b2 = (const float*)d_in[4];
    const float* Wq = (const float*)d_in[5];
    const float* bq = (const float*)d_in[6];
    const float* Wk = (const float*)d_in[7];
    const float* bk = (const float*)d_in[8];
    const float* Wv = (const float*)d_in[9];
    const float* bv = (const float*)d_in[10];
    const float* Wo = (const float*)d_in[11];
    const float* bo = (const float*)d_in[12];
    float* out = (float*)d_out;

    __half *xh, *h1, *xm, *q, *k, *vt, *o;
    __half *w1h, *w2h, *wqh, *wkh, *wvh, *woh;
    cudaGetSymbolAddress((void**)&xh, g_xh);
    cudaGetSymbolAddress((void**)&h1, g_h1);
    cudaGetSymbolAddress((void**)&xm, g_xm);
    cudaGetSymbolAddress((void**)&q,  g_q);
    cudaGetSymbolAddress((void**)&k,  g_k);
    cudaGetSymbolAddress((void**)&vt, g_vt);
    cudaGetSymbolAddress((void**)&o,  g_o);
    cudaGetSymbolAddress((void**)&w1h, g_w1h);
    cudaGetSymbolAddress((void**)&w2h, g_w2h);
    cudaGetSymbolAddress((void**)&wqh, g_wqh);
    cudaGetSymbolAddress((void**)&wkh, g_wkh);
    cudaGetSymbolAddress((void**)&wvh, g_wvh);
    cudaGetSymbolAddress((void**)&woh, g_woh);

    cudaFuncSetAttribute(gemm_f16<1, 1>, cudaFuncAttributeMaxDynamicSharedMemorySize, GSMEM);
    cudaFuncSetAttribute(gemm_f16<0, 1>, cudaFuncAttributeMaxDynamicSharedMemorySize, GSMEM);
    cudaFuncSetAttribute(gemm_f16<0, 0>, cudaFuncAttributeMaxDynamicSharedMemorySize, GSMEM);
    cudaFuncSetAttribute(gemm_qkv, cudaFuncAttributeMaxDynamicSharedMemorySize, GSMEM);
    const int attn_smem = (QTILE * QP_STRIDE + 4 * KVBUF) * (int)sizeof(__half);
    cudaFuncSetAttribute(attn_f16, cudaFuncAttributeMaxDynamicSharedMemorySize,
                         attn_smem);

    // Fused prep
    Prep pr;
    pr.src[0] = x;  pr.dst[0] = xh;
    pr.src[1] = W1; pr.dst[1] = w1h;
    pr.src[2] = W2; pr.dst[2] = w2h;
    pr.src[3] = Wq; pr.dst[3] = wqh;
    pr.src[4] = Wk; pr.dst[4] = wkh;
    pr.src[5] = Wv; pr.dst[5] = wvh;
    pr.src[6] = Wo; pr.dst[6] = woh;
    const unsigned cnt[7] = {
        (TOK * DMODEL) / 4, (512 * 1024) / 4, (1024 * 512) / 4,
        (512 * 512) / 4, (512 * 512) / 4, (512 * 512) / 4, (512 * 512) / 4 };
    unsigned acc = 0;
    for (int i = 0; i < 7; i++) { pr.cum[i] = acc; acc += cnt[i]; }
    pr.cum[7] = acc;
    prep_all<<<(acc + 255) / 256, 256>>>(pr);

    QKVp qp;
    qp.w[0] = wqh; qp.w[1] = wkh; qp.w[2] = wvh;
    qp.b[0] = bq;  qp.b[1] = bk;  qp.b[2] = bv;
    qp.q = q; qp.k = k; qp.vt = vt;

    dim3 blk(128);
    gemm_f16<1, 1><<<dim3(1024 / 128, TOK / 64), blk, GSMEM>>>(xh, w1h, b1, h1, TOK, 1024, DMODEL);
    gemm_f16<0, 1><<<dim3(DMODEL / 128, TOK / 64), blk, GSMEM>>>(h1, w2h, b2, xm, TOK, DMODEL, 1024);
    gemm_qkv<<<dim3(1536 / 128, TOK / 64), blk, GSMEM>>>(xm, qp, TOK, DMODEL);
    attn_f16<<<dim3(SQ / QTILE, 4 * NHEADS), dim3(256), attn_smem>>>(q, k, vt, o);
    gemm_f16<0, 0><<<dim3(DMODEL / 128, TOK / 64), blk, GSMEM>>>(o, woh, bo, out, TOK, DMODEL, DMODEL);
}